// round 1
// baseline (speedup 1.0000x reference)
#include <cuda_runtime.h>

#define BB  8
#define SQL 512
#define SKL 512
#define HH  768
#define NHD 12
#define DHD 64

// Scratch (device globals: allocation-free per harness rules)
__device__ float g_q[BB * SQL * HH];
__device__ float g_k[BB * SKL * HH];
__device__ float g_v[BB * SKL * HH];
__device__ float g_P[SQL * SKL];

// ---------------------------------------------------------------------------
// SGEMM (NT): out[m,n] = sum_k A[m,k] * W[n,k] (+ bias[n]) (+ pos[(m%512)*64 + n%64])
// BM=BN=128, BK=16, 256 threads, 8x8 micro-tile per thread.
// ---------------------------------------------------------------------------
__global__ __launch_bounds__(256) void sgemm_nt(
    const float* __restrict__ A, const float* __restrict__ W,
    const float* __restrict__ bias, const float* __restrict__ pos,
    float* __restrict__ out, int M, int N, int K, int addPos)
{
    const int BM = 128, BN = 128, BK = 16;
    __shared__ float As[BK][BM + 4];
    __shared__ float Bs[BK][BN + 4];

    const int t  = threadIdx.x;
    const int m0 = blockIdx.y * BM;
    const int n0 = blockIdx.x * BN;
    const int tm = (t >> 4) << 3;   // 0..120 step 8
    const int tn = (t & 15) << 3;   // 0..120 step 8

    float acc[8][8];
#pragma unroll
    for (int i = 0; i < 8; i++)
#pragma unroll
        for (int j = 0; j < 8; j++) acc[i][j] = 0.0f;

    for (int k0 = 0; k0 < K; k0 += BK) {
        // Load A tile (128x16) and W tile (128x16), store transposed [k][row].
        for (int i = t; i < 512; i += 256) {
            int row = i >> 2;
            int c4  = (i & 3) << 2;
            float4 va = *(const float4*)(A + (size_t)(m0 + row) * K + k0 + c4);
            As[c4 + 0][row] = va.x; As[c4 + 1][row] = va.y;
            As[c4 + 2][row] = va.z; As[c4 + 3][row] = va.w;
            float4 vb = *(const float4*)(W + (size_t)(n0 + row) * K + k0 + c4);
            Bs[c4 + 0][row] = vb.x; Bs[c4 + 1][row] = vb.y;
            Bs[c4 + 2][row] = vb.z; Bs[c4 + 3][row] = vb.w;
        }
        __syncthreads();

#pragma unroll
        for (int kk = 0; kk < BK; kk++) {
            float a[8], b[8];
            *(float4*)(a + 0) = *(const float4*)&As[kk][tm];
            *(float4*)(a + 4) = *(const float4*)&As[kk][tm + 4];
            *(float4*)(b + 0) = *(const float4*)&Bs[kk][tn];
            *(float4*)(b + 4) = *(const float4*)&Bs[kk][tn + 4];
#pragma unroll
            for (int i = 0; i < 8; i++)
#pragma unroll
                for (int j = 0; j < 8; j++)
                    acc[i][j] += a[i] * b[j];
        }
        __syncthreads();
    }

#pragma unroll
    for (int i = 0; i < 8; i++) {
        int m = m0 + tm + i;
        if (m >= M) continue;
#pragma unroll
        for (int j = 0; j < 8; j++) {
            int n = n0 + tn + j;
            if (n >= N) continue;
            float v = acc[i][j];
            if (bias) v += bias[n];
            if (addPos) v += pos[(m & (SKL - 1)) * DHD + (n & (DHD - 1))];
            out[(size_t)m * N + n] = v;
        }
    }
}

// ---------------------------------------------------------------------------
// Flash attention: one block per (b, h, 64-row q tile). 128 threads.
// S = Q K'^T ; add P[i,j] (precomputed pos_q·pos_k) ; scale 1/8 ; mask ;
// online softmax ; O += P_tile @ V.
// Thread layout: rg = t/8 owns 4 q-rows, cg = t%8 owns 8 cols.
// ---------------------------------------------------------------------------
__global__ __launch_bounds__(128) void flash_attn(
    const float* __restrict__ q, const float* __restrict__ k,
    const float* __restrict__ v, const float* __restrict__ Pg,
    const int* __restrict__ mask, float* __restrict__ out)
{
    extern __shared__ float sm[];
    float* Qs = sm;                 // [64][68] stored [d][m]
    float* Ks = Qs + 64 * 68;       // [64][68] stored [d][n]
    float* Vs = Ks + 64 * 68;       // [64][68] stored [j][d]
    float* Ps = Vs + 64 * 68;       // [64][68] stored [j][m]
    float* mb = Ps + 64 * 68;       // [64]

    const int t  = threadIdx.x;
    const int b  = blockIdx.z;
    const int h  = blockIdx.y;
    const int q0 = blockIdx.x << 6;
    const int rg = t >> 3, cg = t & 7;
    const int m0 = rg << 2, n0 = cg << 3;

    const float* qbase = q + ((size_t)(b * SQL) + q0) * HH + h * DHD;
    const float* kbase = k + (size_t)(b * SKL) * HH + h * DHD;
    const float* vbase = v + (size_t)(b * SKL) * HH + h * DHD;

    for (int i = t; i < 4096; i += 128) {
        int m = i >> 6, d = i & 63;
        Qs[d * 68 + m] = qbase[(size_t)m * HH + d];
    }

    float o[4][8], mi[4], li[4];
#pragma unroll
    for (int r = 0; r < 4; r++) {
        mi[r] = -1e30f; li[r] = 0.0f;
#pragma unroll
        for (int c = 0; c < 8; c++) o[r][c] = 0.0f;
    }

    for (int kt = 0; kt < SKL; kt += 64) {
        __syncthreads();  // protect Ks/Vs (prev iter PV) and Qs (first iter)
        for (int i = t; i < 4096; i += 128) {
            int n = i >> 6, d = i & 63;
            float kv = kbase[(size_t)(kt + n) * HH + d];
            Ks[d * 68 + n] = kv;
            Vs[n * 68 + d] = vbase[(size_t)(kt + n) * HH + d];
        }
        if (t < 64) mb[t] = (mask[b * SKL + kt + t] == 0) ? -1e30f : 0.0f;
        __syncthreads();

        // S = Q K^T (per-thread 4x8 tile)
        float s[4][8];
#pragma unroll
        for (int r = 0; r < 4; r++)
#pragma unroll
            for (int c = 0; c < 8; c++) s[r][c] = 0.0f;

#pragma unroll 8
        for (int d = 0; d < 64; d++) {
            float4 qa  = *(const float4*)&Qs[d * 68 + m0];
            float4 kb0 = *(const float4*)&Ks[d * 68 + n0];
            float4 kb1 = *(const float4*)&Ks[d * 68 + n0 + 4];
            float a[4] = {qa.x, qa.y, qa.z, qa.w};
            float bb[8] = {kb0.x, kb0.y, kb0.z, kb0.w, kb1.x, kb1.y, kb1.z, kb1.w};
#pragma unroll
            for (int r = 0; r < 4; r++)
#pragma unroll
                for (int c = 0; c < 8; c++)
                    s[r][c] += a[r] * bb[c];
        }

        // epilogue: + positional bias, scale, mask
#pragma unroll
        for (int r = 0; r < 4; r++) {
            const float* Prow = Pg + (size_t)(q0 + m0 + r) * SKL + kt + n0;
#pragma unroll
            for (int c = 0; c < 8; c++)
                s[r][c] = (s[r][c] + Prow[c]) * 0.125f + mb[n0 + c];
        }

        // online softmax per row (reduce across the 8 lanes sharing a row)
#pragma unroll
        for (int r = 0; r < 4; r++) {
            float mx = s[r][0];
#pragma unroll
            for (int c = 1; c < 8; c++) mx = fmaxf(mx, s[r][c]);
            mx = fmaxf(mx, __shfl_xor_sync(0xffffffffu, mx, 1));
            mx = fmaxf(mx, __shfl_xor_sync(0xffffffffu, mx, 2));
            mx = fmaxf(mx, __shfl_xor_sync(0xffffffffu, mx, 4));
            float mnew = fmaxf(mi[r], mx);
            float corr = __expf(mi[r] - mnew);
            float ps = 0.0f;
#pragma unroll
            for (int c = 0; c < 8; c++) {
                float p = __expf(s[r][c] - mnew);
                s[r][c] = p;
                ps += p;
            }
            ps += __shfl_xor_sync(0xffffffffu, ps, 1);
            ps += __shfl_xor_sync(0xffffffffu, ps, 2);
            ps += __shfl_xor_sync(0xffffffffu, ps, 4);
            li[r] = li[r] * corr + ps;
            mi[r] = mnew;
#pragma unroll
            for (int c = 0; c < 8; c++) o[r][c] *= corr;
        }

        // write P tile transposed [j][m]
#pragma unroll
        for (int r = 0; r < 4; r++)
#pragma unroll
            for (int c = 0; c < 8; c++)
                Ps[(n0 + c) * 68 + m0 + r] = s[r][c];
        __syncthreads();

        // O += P @ V
#pragma unroll 8
        for (int j = 0; j < 64; j++) {
            float4 p4 = *(const float4*)&Ps[j * 68 + m0];
            float4 va = *(const float4*)&Vs[j * 68 + n0];
            float4 vb = *(const float4*)&Vs[j * 68 + n0 + 4];
            float pr[4] = {p4.x, p4.y, p4.z, p4.w};
            float vv[8] = {va.x, va.y, va.z, va.w, vb.x, vb.y, vb.z, vb.w};
#pragma unroll
            for (int r = 0; r < 4; r++)
#pragma unroll
                for (int c = 0; c < 8; c++)
                    o[r][c] += pr[r] * vv[c];
        }
    }

    float* obase = out + ((size_t)(b * SQL) + q0) * HH + h * DHD;
#pragma unroll
    for (int r = 0; r < 4; r++) {
        float inv = 1.0f / li[r];
#pragma unroll
        for (int c = 0; c < 8; c++)
            obase[(size_t)(m0 + r) * HH + n0 + c] = o[r][c] * inv;
    }
}

// ---------------------------------------------------------------------------
extern "C" void kernel_launch(void* const* d_in, const int* in_sizes, int n_in,
                              void* d_out, int out_size)
{
    const float* hidden  = (const float*)d_in[0];
    const float* context = (const float*)d_in[1];
    const int*   mask    = (const int*)d_in[2];
    const float* Wq      = (const float*)d_in[3];
    const float* bq      = (const float*)d_in[4];
    const float* Wk      = (const float*)d_in[5];
    const float* bk      = (const float*)d_in[6];
    const float* Wv      = (const float*)d_in[7];
    const float* bv      = (const float*)d_in[8];
    const float* pos     = (const float*)d_in[9];
    float* out = (float*)d_out;

    float *q, *k, *v, *P;
    cudaGetSymbolAddress((void**)&q, g_q);
    cudaGetSymbolAddress((void**)&k, g_k);
    cudaGetSymbolAddress((void**)&v, g_v);
    cudaGetSymbolAddress((void**)&P, g_P);

    const int smem_flash = (4 * 64 * 68 + 64) * (int)sizeof(float);  // ~70KB
    cudaFuncSetAttribute(flash_attn, cudaFuncAttributeMaxDynamicSharedMemorySize,
                         smem_flash);

    dim3 gproj(HH / 128, (BB * SQL) / 128);   // (6, 32)
    sgemm_nt<<<gproj, 256>>>(hidden,  Wq, bq, pos, q, BB * SQL, HH, HH, 0);
    sgemm_nt<<<gproj, 256>>>(context, Wk, bk, pos, k, BB * SKL, HH, HH, 1); // k' = k + pos_k
    sgemm_nt<<<gproj, 256>>>(context, Wv, bv, pos, v, BB * SKL, HH, HH, 0);

    dim3 gpos(SKL / 128, SQL / 128);          // (4, 4)
    sgemm_nt<<<gpos, 256>>>(pos, pos, nullptr, nullptr, P, SQL, SKL, DHD, 0);

    dim3 gattn(SQL / 64, NHD, BB);            // (8, 12, 8)
    flash_attn<<<gattn, 128, smem_flash>>>(q, k, v, P, mask, out);
}

// round 3
// speedup vs baseline: 1.7109x; 1.7109x over previous
#include <cuda_runtime.h>
#include <cuda_bf16.h>
#include <cstdint>

#define BB  8
#define SQL 512
#define SKL 512
#define HH  768
#define NHD 12
#define DHD 64
#define MROWS (BB * SQL)   // 4096

// ---------------- scratch (device globals; allocation-free) ----------------
__device__ float g_q[MROWS * HH];
__device__ float g_k[MROWS * HH];
__device__ float g_v[MROWS * HH];
__device__ float g_P[SQL * SKL];
__device__ __nv_bfloat16 g_hid_hi[MROWS * HH];
__device__ __nv_bfloat16 g_hid_lo[MROWS * HH];
__device__ __nv_bfloat16 g_ctx_hi[MROWS * HH];
__device__ __nv_bfloat16 g_ctx_lo[MROWS * HH];
__device__ __nv_bfloat16 g_w_hi[3 * HH * HH];
__device__ __nv_bfloat16 g_w_lo[3 * HH * HH];

// ---------------------------------------------------------------------------
// fp32 -> bf16 hi/lo split (vectorized x4)
// ---------------------------------------------------------------------------
__global__ void cvt_split(const float* __restrict__ x, __nv_bfloat16* __restrict__ hi,
                          __nv_bfloat16* __restrict__ lo, int n4)
{
    int i = blockIdx.x * blockDim.x + threadIdx.x;
    if (i >= n4) return;
    float4 v = ((const float4*)x)[i];
    __nv_bfloat16 h0 = __float2bfloat16_rn(v.x);
    __nv_bfloat16 h1 = __float2bfloat16_rn(v.y);
    __nv_bfloat16 h2 = __float2bfloat16_rn(v.z);
    __nv_bfloat16 h3 = __float2bfloat16_rn(v.w);
    __nv_bfloat16 l0 = __float2bfloat16_rn(v.x - __bfloat162float(h0));
    __nv_bfloat16 l1 = __float2bfloat16_rn(v.y - __bfloat162float(h1));
    __nv_bfloat16 l2 = __float2bfloat16_rn(v.z - __bfloat162float(h2));
    __nv_bfloat16 l3 = __float2bfloat16_rn(v.w - __bfloat162float(h3));
    __nv_bfloat162 a, b;
    a.x = h0; a.y = h1; b.x = h2; b.y = h3;
    ((__nv_bfloat162*)hi)[2 * i] = a; ((__nv_bfloat162*)hi)[2 * i + 1] = b;
    a.x = l0; a.y = l1; b.x = l2; b.y = l3;
    ((__nv_bfloat162*)lo)[2 * i] = a; ((__nv_bfloat162*)lo)[2 * i + 1] = b;
}

// ---------------------------------------------------------------------------
// HMMA helper: D += A*B  (m16n8k16, bf16 in, fp32 accum)
// ---------------------------------------------------------------------------
__device__ __forceinline__ void mma16816(float* d, const uint32_t* a, const uint32_t* b)
{
    asm volatile(
        "mma.sync.aligned.m16n8k16.row.col.f32.bf16.bf16.f32 "
        "{%0,%1,%2,%3}, {%4,%5,%6,%7}, {%8,%9}, {%0,%1,%2,%3};"
        : "+f"(d[0]), "+f"(d[1]), "+f"(d[2]), "+f"(d[3])
        : "r"(a[0]), "r"(a[1]), "r"(a[2]), "r"(a[3]), "r"(b[0]), "r"(b[1]));
}

// ---------------------------------------------------------------------------
// QKV projection via HMMA: out = A @ W^T (+bias) (+pos for K), 3-term bf16 split.
// CTA tile 128x128, BK=32, 256 threads (8 warps: warp_m=wid%4 -> 32 rows,
// warp_n=wid/4 -> 64 cols). blockIdx.z: 0=Q 1=K 2=V.
// smem tiles row-major [128][32] bf16 padded to 40 bf16 (80B) per row.
// ---------------------------------------------------------------------------
#define TPAD 40

__global__ __launch_bounds__(256, 2) void qkv_hmma(
    const __nv_bfloat16* __restrict__ hid_hi, const __nv_bfloat16* __restrict__ hid_lo,
    const __nv_bfloat16* __restrict__ ctx_hi, const __nv_bfloat16* __restrict__ ctx_lo,
    const __nv_bfloat16* __restrict__ w_hi,   const __nv_bfloat16* __restrict__ w_lo,
    const float* __restrict__ bq, const float* __restrict__ bk, const float* __restrict__ bv,
    const float* __restrict__ pos,
    float* __restrict__ qo, float* __restrict__ ko, float* __restrict__ vo)
{
    __shared__ __nv_bfloat16 sAhi[128 * TPAD];
    __shared__ __nv_bfloat16 sAlo[128 * TPAD];
    __shared__ __nv_bfloat16 sBhi[128 * TPAD];
    __shared__ __nv_bfloat16 sBlo[128 * TPAD];

    const int z = blockIdx.z;
    const __nv_bfloat16* Ahi = (z == 0) ? hid_hi : ctx_hi;
    const __nv_bfloat16* Alo = (z == 0) ? hid_lo : ctx_lo;
    const __nv_bfloat16* Bhi = w_hi + (size_t)z * HH * HH;
    const __nv_bfloat16* Blo = w_lo + (size_t)z * HH * HH;
    const float* bias = (z == 0) ? bq : ((z == 1) ? bk : bv);
    float* out = (z == 0) ? qo : ((z == 1) ? ko : vo);

    const int t    = threadIdx.x;
    const int lane = t & 31;
    const int wid  = t >> 5;
    const int wm   = wid & 3;          // 0..3 -> 32-row strips
    const int wn   = wid >> 2;         // 0..1 -> 64-col strips
    const int g    = lane >> 2;        // group id 0..7
    const int tig  = lane & 3;         // thread in group

    const int m0 = blockIdx.y << 7;
    const int n0 = blockIdx.x << 7;

    float acc[2][8][4];
#pragma unroll
    for (int i = 0; i < 2; i++)
#pragma unroll
        for (int j = 0; j < 8; j++)
#pragma unroll
            for (int c = 0; c < 4; c++) acc[i][j][c] = 0.0f;

    for (int k0 = 0; k0 < HH; k0 += 32) {
        // ---- load tiles: each tile = 128 rows x 32 bf16; 512 uint4 chunks ----
#pragma unroll
        for (int it = 0; it < 2; it++) {
            int c   = t + it * 256;       // 0..511
            int row = c >> 2;
            int cc  = (c & 3) << 3;       // bf16 col offset 0,8,16,24
            size_t ga = (size_t)(m0 + row) * HH + k0 + cc;
            size_t gb = (size_t)(n0 + row) * HH + k0 + cc;
            int so = row * TPAD + cc;
            *(uint4*)(sAhi + so) = *(const uint4*)(Ahi + ga);
            *(uint4*)(sAlo + so) = *(const uint4*)(Alo + ga);
            *(uint4*)(sBhi + so) = *(const uint4*)(Bhi + gb);
            *(uint4*)(sBlo + so) = *(const uint4*)(Blo + gb);
        }
        __syncthreads();

#pragma unroll
        for (int kk = 0; kk < 32; kk += 16) {
            const int acol = kk + 2 * tig;   // even
            uint32_t af[2][4], bf[8][2];

            // pass 1+2 share bhi: ahi*bhi then alo*bhi
#pragma unroll
            for (int nt = 0; nt < 8; nt++) {
                int r = (wn * 64 + nt * 8 + g) * TPAD + acol;
                bf[nt][0] = *(const uint32_t*)(sBhi + r);
                bf[nt][1] = *(const uint32_t*)(sBhi + r + 8);
            }
#pragma unroll
            for (int mt = 0; mt < 2; mt++) {
                int r = (wm * 32 + mt * 16 + g) * TPAD + acol;
                af[mt][0] = *(const uint32_t*)(sAhi + r);
                af[mt][1] = *(const uint32_t*)(sAhi + r + 8 * TPAD);
                af[mt][2] = *(const uint32_t*)(sAhi + r + 8);
                af[mt][3] = *(const uint32_t*)(sAhi + r + 8 * TPAD + 8);
            }
#pragma unroll
            for (int mt = 0; mt < 2; mt++)
#pragma unroll
                for (int nt = 0; nt < 8; nt++)
                    mma16816(acc[mt][nt], af[mt], bf[nt]);

#pragma unroll
            for (int mt = 0; mt < 2; mt++) {
                int r = (wm * 32 + mt * 16 + g) * TPAD + acol;
                af[mt][0] = *(const uint32_t*)(sAlo + r);
                af[mt][1] = *(const uint32_t*)(sAlo + r + 8 * TPAD);
                af[mt][2] = *(const uint32_t*)(sAlo + r + 8);
                af[mt][3] = *(const uint32_t*)(sAlo + r + 8 * TPAD + 8);
            }
#pragma unroll
            for (int mt = 0; mt < 2; mt++)
#pragma unroll
                for (int nt = 0; nt < 8; nt++)
                    mma16816(acc[mt][nt], af[mt], bf[nt]);

            // pass 3: ahi*blo
#pragma unroll
            for (int nt = 0; nt < 8; nt++) {
                int r = (wn * 64 + nt * 8 + g) * TPAD + acol;
                bf[nt][0] = *(const uint32_t*)(sBlo + r);
                bf[nt][1] = *(const uint32_t*)(sBlo + r + 8);
            }
#pragma unroll
            for (int mt = 0; mt < 2; mt++) {
                int r = (wm * 32 + mt * 16 + g) * TPAD + acol;
                af[mt][0] = *(const uint32_t*)(sAhi + r);
                af[mt][1] = *(const uint32_t*)(sAhi + r + 8 * TPAD);
                af[mt][2] = *(const uint32_t*)(sAhi + r + 8);
                af[mt][3] = *(const uint32_t*)(sAhi + r + 8 * TPAD + 8);
            }
#pragma unroll
            for (int mt = 0; mt < 2; mt++)
#pragma unroll
                for (int nt = 0; nt < 8; nt++)
                    mma16816(acc[mt][nt], af[mt], bf[nt]);
        }
        __syncthreads();
    }

    // ---- epilogue: c-frag (row=g(+8), col=2*tig(+1)) -> global with bias/pos ----
#pragma unroll
    for (int mt = 0; mt < 2; mt++) {
#pragma unroll
        for (int nt = 0; nt < 8; nt++) {
            int m = m0 + wm * 32 + mt * 16 + g;
            int n = n0 + wn * 64 + nt * 8 + 2 * tig;
            float b0 = bias[n], b1 = bias[n + 1];
            float p0 = 0.f, p1 = 0.f;
            if (z == 1) {
                p0 = pos[(m & (SKL - 1)) * DHD + (n & (DHD - 1))];
                p1 = pos[(m & (SKL - 1)) * DHD + ((n + 1) & (DHD - 1))];
            }
            float2 v0, v1;
            v0.x = acc[mt][nt][0] + b0 + p0;
            v0.y = acc[mt][nt][1] + b1 + p1;
            *(float2*)(out + (size_t)m * HH + n) = v0;
            int m2 = m + 8;
            float q0 = 0.f, q1 = 0.f;
            if (z == 1) {
                q0 = pos[(m2 & (SKL - 1)) * DHD + (n & (DHD - 1))];
                q1 = pos[(m2 & (SKL - 1)) * DHD + ((n + 1) & (DHD - 1))];
            }
            v1.x = acc[mt][nt][2] + b0 + q0;
            v1.y = acc[mt][nt][3] + b1 + q1;
            *(float2*)(out + (size_t)m2 * HH + n) = v1;
        }
    }
}

// ---------------------------------------------------------------------------
// Small fp32 GEMM for P = pos @ pos^T  (512x512x64)
// ---------------------------------------------------------------------------
__global__ __launch_bounds__(256) void sgemm_nt(
    const float* __restrict__ A, const float* __restrict__ W,
    float* __restrict__ out, int M, int N, int K)
{
    const int BM = 128, BN = 128, BK = 16;
    __shared__ float As[BK][BM + 4];
    __shared__ float Bs[BK][BN + 4];

    const int t  = threadIdx.x;
    const int m0 = blockIdx.y * BM;
    const int n0 = blockIdx.x * BN;
    const int tm = (t >> 4) << 3;
    const int tn = (t & 15) << 3;

    float acc[8][8];
#pragma unroll
    for (int i = 0; i < 8; i++)
#pragma unroll
        for (int j = 0; j < 8; j++) acc[i][j] = 0.0f;

    for (int k0 = 0; k0 < K; k0 += BK) {
        for (int i = t; i < 512; i += 256) {
            int row = i >> 2;
            int c4  = (i & 3) << 2;
            float4 va = *(const float4*)(A + (size_t)(m0 + row) * K + k0 + c4);
            As[c4 + 0][row] = va.x; As[c4 + 1][row] = va.y;
            As[c4 + 2][row] = va.z; As[c4 + 3][row] = va.w;
            float4 vb = *(const float4*)(W + (size_t)(n0 + row) * K + k0 + c4);
            Bs[c4 + 0][row] = vb.x; Bs[c4 + 1][row] = vb.y;
            Bs[c4 + 2][row] = vb.z; Bs[c4 + 3][row] = vb.w;
        }
        __syncthreads();
#pragma unroll
        for (int kk = 0; kk < BK; kk++) {
            float a[8], b[8];
            *(float4*)(a + 0) = *(const float4*)&As[kk][tm];
            *(float4*)(a + 4) = *(const float4*)&As[kk][tm + 4];
            *(float4*)(b + 0) = *(const float4*)&Bs[kk][tn];
            *(float4*)(b + 4) = *(const float4*)&Bs[kk][tn + 4];
#pragma unroll
            for (int i = 0; i < 8; i++)
#pragma unroll
                for (int j = 0; j < 8; j++)
                    acc[i][j] += a[i] * b[j];
        }
        __syncthreads();
    }
#pragma unroll
    for (int i = 0; i < 8; i++)
#pragma unroll
        for (int j = 0; j < 8; j++)
            out[(size_t)(m0 + tm + i) * N + n0 + tn + j] = acc[i][j];
}

// ---------------------------------------------------------------------------
// Flash attention (fp32 FFMA) — unchanged from round 1 (known correct)
// ---------------------------------------------------------------------------
__global__ __launch_bounds__(128) void flash_attn(
    const float* __restrict__ q, const float* __restrict__ k,
    const float* __restrict__ v, const float* __restrict__ Pg,
    const int* __restrict__ mask, float* __restrict__ out)
{
    extern __shared__ float sm[];
    float* Qs = sm;
    float* Ks = Qs + 64 * 68;
    float* Vs = Ks + 64 * 68;
    float* Ps = Vs + 64 * 68;
    float* mb = Ps + 64 * 68;

    const int t  = threadIdx.x;
    const int b  = blockIdx.z;
    const int h  = blockIdx.y;
    const int q0 = blockIdx.x << 6;
    const int rg = t >> 3, cg = t & 7;
    const int m0 = rg << 2, n0 = cg << 3;

    const float* qbase = q + ((size_t)(b * SQL) + q0) * HH + h * DHD;
    const float* kbase = k + (size_t)(b * SKL) * HH + h * DHD;
    const float* vbase = v + (size_t)(b * SKL) * HH + h * DHD;

    for (int i = t; i < 4096; i += 128) {
        int m = i >> 6, d = i & 63;
        Qs[d * 68 + m] = qbase[(size_t)m * HH + d];
    }

    float o[4][8], mi[4], li[4];
#pragma unroll
    for (int r = 0; r < 4; r++) {
        mi[r] = -1e30f; li[r] = 0.0f;
#pragma unroll
        for (int c = 0; c < 8; c++) o[r][c] = 0.0f;
    }

    for (int kt = 0; kt < SKL; kt += 64) {
        __syncthreads();
        for (int i = t; i < 4096; i += 128) {
            int n = i >> 6, d = i & 63;
            Ks[d * 68 + n] = kbase[(size_t)(kt + n) * HH + d];
            Vs[n * 68 + d] = vbase[(size_t)(kt + n) * HH + d];
        }
        if (t < 64) mb[t] = (mask[b * SKL + kt + t] == 0) ? -1e30f : 0.0f;
        __syncthreads();

        float s[4][8];
#pragma unroll
        for (int r = 0; r < 4; r++)
#pragma unroll
            for (int c = 0; c < 8; c++) s[r][c] = 0.0f;

#pragma unroll 8
        for (int d = 0; d < 64; d++) {
            float4 qa  = *(const float4*)&Qs[d * 68 + m0];
            float4 kb0 = *(const float4*)&Ks[d * 68 + n0];
            float4 kb1 = *(const float4*)&Ks[d * 68 + n0 + 4];
            float a[4] = {qa.x, qa.y, qa.z, qa.w};
            float bb[8] = {kb0.x, kb0.y, kb0.z, kb0.w, kb1.x, kb1.y, kb1.z, kb1.w};
#pragma unroll
            for (int r = 0; r < 4; r++)
#pragma unroll
                for (int c = 0; c < 8; c++)
                    s[r][c] += a[r] * bb[c];
        }

#pragma unroll
        for (int r = 0; r < 4; r++) {
            const float* Prow = Pg + (size_t)(q0 + m0 + r) * SKL + kt + n0;
#pragma unroll
            for (int c = 0; c < 8; c++)
                s[r][c] = (s[r][c] + Prow[c]) * 0.125f + mb[n0 + c];
        }

#pragma unroll
        for (int r = 0; r < 4; r++) {
            float mx = s[r][0];
#pragma unroll
            for (int c = 1; c < 8; c++) mx = fmaxf(mx, s[r][c]);
            mx = fmaxf(mx, __shfl_xor_sync(0xffffffffu, mx, 1));
            mx = fmaxf(mx, __shfl_xor_sync(0xffffffffu, mx, 2));
            mx = fmaxf(mx, __shfl_xor_sync(0xffffffffu, mx, 4));
            float mnew = fmaxf(mi[r], mx);
            float corr = __expf(mi[r] - mnew);
            float ps = 0.0f;
#pragma unroll
            for (int c = 0; c < 8; c++) {
                float p = __expf(s[r][c] - mnew);
                s[r][c] = p;
                ps += p;
            }
            ps += __shfl_xor_sync(0xffffffffu, ps, 1);
            ps += __shfl_xor_sync(0xffffffffu, ps, 2);
            ps += __shfl_xor_sync(0xffffffffu, ps, 4);
            li[r] = li[r] * corr + ps;
            mi[r] = mnew;
#pragma unroll
            for (int c = 0; c < 8; c++) o[r][c] *= corr;
        }

#pragma unroll
        for (int r = 0; r < 4; r++)
#pragma unroll
            for (int c = 0; c < 8; c++)
                Ps[(n0 + c) * 68 + m0 + r] = s[r][c];
        __syncthreads();

#pragma unroll 8
        for (int j = 0; j < 64; j++) {
            float4 p4 = *(const float4*)&Ps[j * 68 + m0];
            float4 va = *(const float4*)&Vs[j * 68 + n0];
            float4 vb = *(const float4*)&Vs[j * 68 + n0 + 4];
            float pr[4] = {p4.x, p4.y, p4.z, p4.w};
            float vv[8] = {va.x, va.y, va.z, va.w, vb.x, vb.y, vb.z, vb.w};
#pragma unroll
            for (int r = 0; r < 4; r++)
#pragma unroll
                for (int c = 0; c < 8; c++)
                    o[r][c] += pr[r] * vv[c];
        }
    }

    float* obase = out + ((size_t)(b * SQL) + q0) * HH + h * DHD;
#pragma unroll
    for (int r = 0; r < 4; r++) {
        float inv = 1.0f / li[r];
#pragma unroll
        for (int c = 0; c < 8; c++)
            obase[(size_t)(m0 + r) * HH + n0 + c] = o[r][c] * inv;
    }
}

// ---------------------------------------------------------------------------
extern "C" void kernel_launch(void* const* d_in, const int* in_sizes, int n_in,
                              void* d_out, int out_size)
{
    const float* hidden  = (const float*)d_in[0];
    const float* context = (const float*)d_in[1];
    const int*   mask    = (const int*)d_in[2];
    const float* Wq      = (const float*)d_in[3];
    const float* bq      = (const float*)d_in[4];
    const float* Wk      = (const float*)d_in[5];
    const float* bk      = (const float*)d_in[6];
    const float* Wv      = (const float*)d_in[7];
    const float* bv      = (const float*)d_in[8];
    const float* pos     = (const float*)d_in[9];
    float* out = (float*)d_out;

    float *q, *k, *v, *P;
    cudaGetSymbolAddress((void**)&q, g_q);
    cudaGetSymbolAddress((void**)&k, g_k);
    cudaGetSymbolAddress((void**)&v, g_v);
    cudaGetSymbolAddress((void**)&P, g_P);
    __nv_bfloat16 *hh, *hl, *ch, *cl, *wh, *wl;
    cudaGetSymbolAddress((void**)&hh, g_hid_hi);
    cudaGetSymbolAddress((void**)&hl, g_hid_lo);
    cudaGetSymbolAddress((void**)&ch, g_ctx_hi);
    cudaGetSymbolAddress((void**)&cl, g_ctx_lo);
    cudaGetSymbolAddress((void**)&wh, g_w_hi);
    cudaGetSymbolAddress((void**)&wl, g_w_lo);

    // fp32 -> bf16 hi/lo splits
    const int nA4 = MROWS * HH / 4, nW4 = HH * HH / 4;
    cvt_split<<<(nA4 + 255) / 256, 256>>>(hidden,  hh, hl, nA4);
    cvt_split<<<(nA4 + 255) / 256, 256>>>(context, ch, cl, nA4);
    cvt_split<<<(nW4 + 255) / 256, 256>>>(Wq, wh,               wl,               nW4);
    cvt_split<<<(nW4 + 255) / 256, 256>>>(Wk, wh + HH * HH,     wl + HH * HH,     nW4);
    cvt_split<<<(nW4 + 255) / 256, 256>>>(Wv, wh + 2 * HH * HH, wl + 2 * HH * HH, nW4);

    // HMMA projections (Q, K+pos, V fused in z)
    dim3 gproj(HH / 128, MROWS / 128, 3);   // (6, 32, 3)
    qkv_hmma<<<gproj, 256>>>(hh, hl, ch, cl, wh, wl, bq, bk, bv, pos, q, k, v);

    // P = pos @ pos^T
    dim3 gpos(SKL / 128, SQL / 128);
    sgemm_nt<<<gpos, 256>>>(pos, pos, P, SQL, SKL, DHD);

    // flash attention
    const int smem_flash = (4 * 64 * 68 + 64) * (int)sizeof(float);
    cudaFuncSetAttribute(flash_attn, cudaFuncAttributeMaxDynamicSharedMemorySize, smem_flash);
    dim3 gattn(SQL / 64, NHD, BB);
    flash_attn<<<gattn, 128, smem_flash>>>(q, k, v, P, mask, out);
}

// round 4
// speedup vs baseline: 3.1170x; 1.8218x over previous
#include <cuda_runtime.h>
#include <cuda_bf16.h>
#include <cstdint>

#define BB  8
#define SQL 512
#define SKL 512
#define HH  768
#define NHD 12
#define DHD 64
#define MROWS (BB * SQL)   // 4096

// scale folded with log2(e) so we can use ex2.approx
#define C2 0.1803368801111244f   // 0.125 * log2(e)

// ---------------- scratch (device globals; allocation-free) ----------------
__device__ float g_P2[SQL * SKL];                  // (pos_q @ pos_k^T) * C2
__device__ __nv_bfloat16 g_qh[MROWS * HH];
__device__ __nv_bfloat16 g_ql[MROWS * HH];
__device__ __nv_bfloat16 g_kh[MROWS * HH];
__device__ __nv_bfloat16 g_kl[MROWS * HH];
__device__ __nv_bfloat16 g_vh[MROWS * HH];
__device__ __nv_bfloat16 g_vl[MROWS * HH];
__device__ __nv_bfloat16 g_hid_hi[MROWS * HH];
__device__ __nv_bfloat16 g_hid_lo[MROWS * HH];
__device__ __nv_bfloat16 g_ctx_hi[MROWS * HH];
__device__ __nv_bfloat16 g_ctx_lo[MROWS * HH];
__device__ __nv_bfloat16 g_w_hi[3 * HH * HH];
__device__ __nv_bfloat16 g_w_lo[3 * HH * HH];

// ---------------- helpers ----------------
__device__ __forceinline__ float ex2f(float x) {
    float y;
    asm("ex2.approx.ftz.f32 %0, %1;" : "=f"(y) : "f"(x));
    return y;
}
__device__ __forceinline__ uint32_t smem_u32(const void* p) {
    uint32_t a;
    asm("{ .reg .u64 t; cvta.to.shared.u64 t, %1; cvt.u32.u64 %0, t; }" : "=r"(a) : "l"(p));
    return a;
}
__device__ __forceinline__ void mma16816(float* d, const uint32_t* a, const uint32_t* b)
{
    asm volatile(
        "mma.sync.aligned.m16n8k16.row.col.f32.bf16.bf16.f32 "
        "{%0,%1,%2,%3}, {%4,%5,%6,%7}, {%8,%9}, {%0,%1,%2,%3};"
        : "+f"(d[0]), "+f"(d[1]), "+f"(d[2]), "+f"(d[3])
        : "r"(a[0]), "r"(a[1]), "r"(a[2]), "r"(a[3]), "r"(b[0]), "r"(b[1]));
}
__device__ __forceinline__ void ldmx2t(uint32_t& r0, uint32_t& r1, uint32_t addr)
{
    asm volatile("ldmatrix.sync.aligned.m8n8.x2.trans.shared.b16 {%0,%1}, [%2];"
                 : "=r"(r0), "=r"(r1) : "r"(addr));
}
__device__ __forceinline__ uint32_t pack_bf2(float a, float b) {
    __nv_bfloat162 h = __floats2bfloat162_rn(a, b);
    return *(uint32_t*)&h;
}

// ---------------------------------------------------------------------------
// fp32 -> bf16 hi/lo split (vectorized x4)
// ---------------------------------------------------------------------------
__global__ void cvt_split(const float* __restrict__ x, __nv_bfloat16* __restrict__ hi,
                          __nv_bfloat16* __restrict__ lo, int n4)
{
    int i = blockIdx.x * blockDim.x + threadIdx.x;
    if (i >= n4) return;
    float4 v = ((const float4*)x)[i];
    __nv_bfloat16 h0 = __float2bfloat16_rn(v.x);
    __nv_bfloat16 h1 = __float2bfloat16_rn(v.y);
    __nv_bfloat16 h2 = __float2bfloat16_rn(v.z);
    __nv_bfloat16 h3 = __float2bfloat16_rn(v.w);
    __nv_bfloat16 l0 = __float2bfloat16_rn(v.x - __bfloat162float(h0));
    __nv_bfloat16 l1 = __float2bfloat16_rn(v.y - __bfloat162float(h1));
    __nv_bfloat16 l2 = __float2bfloat16_rn(v.z - __bfloat162float(h2));
    __nv_bfloat16 l3 = __float2bfloat16_rn(v.w - __bfloat162float(h3));
    __nv_bfloat162 a, b;
    a.x = h0; a.y = h1; b.x = h2; b.y = h3;
    ((__nv_bfloat162*)hi)[2 * i] = a; ((__nv_bfloat162*)hi)[2 * i + 1] = b;
    a.x = l0; a.y = l1; b.x = l2; b.y = l3;
    ((__nv_bfloat162*)lo)[2 * i] = a; ((__nv_bfloat162*)lo)[2 * i + 1] = b;
}

// ---------------------------------------------------------------------------
// QKV projection via HMMA, 3-term bf16 split; outputs bf16 hi/lo pairs.
// CTA tile 128x128, BK=32, 256 threads. z: 0=Q 1=K(+pos) 2=V.
// ---------------------------------------------------------------------------
#define TPAD 40

__global__ __launch_bounds__(256, 2) void qkv_hmma(
    const __nv_bfloat16* __restrict__ hid_hi, const __nv_bfloat16* __restrict__ hid_lo,
    const __nv_bfloat16* __restrict__ ctx_hi, const __nv_bfloat16* __restrict__ ctx_lo,
    const __nv_bfloat16* __restrict__ w_hi,   const __nv_bfloat16* __restrict__ w_lo,
    const float* __restrict__ bq, const float* __restrict__ bk, const float* __restrict__ bv,
    const float* __restrict__ pos,
    __nv_bfloat16* __restrict__ qh, __nv_bfloat16* __restrict__ ql,
    __nv_bfloat16* __restrict__ kh, __nv_bfloat16* __restrict__ kl,
    __nv_bfloat16* __restrict__ vh, __nv_bfloat16* __restrict__ vl)
{
    __shared__ __nv_bfloat16 sAhi[128 * TPAD];
    __shared__ __nv_bfloat16 sAlo[128 * TPAD];
    __shared__ __nv_bfloat16 sBhi[128 * TPAD];
    __shared__ __nv_bfloat16 sBlo[128 * TPAD];

    const int z = blockIdx.z;
    const __nv_bfloat16* Ahi = (z == 0) ? hid_hi : ctx_hi;
    const __nv_bfloat16* Alo = (z == 0) ? hid_lo : ctx_lo;
    const __nv_bfloat16* Bhi = w_hi + (size_t)z * HH * HH;
    const __nv_bfloat16* Blo = w_lo + (size_t)z * HH * HH;
    const float* bias = (z == 0) ? bq : ((z == 1) ? bk : bv);
    __nv_bfloat16* oh = (z == 0) ? qh : ((z == 1) ? kh : vh);
    __nv_bfloat16* ol = (z == 0) ? ql : ((z == 1) ? kl : vl);

    const int t    = threadIdx.x;
    const int lane = t & 31;
    const int wid  = t >> 5;
    const int wm   = wid & 3;
    const int wn   = wid >> 2;
    const int g    = lane >> 2;
    const int tig  = lane & 3;

    const int m0 = blockIdx.y << 7;
    const int n0 = blockIdx.x << 7;

    float acc[2][8][4];
#pragma unroll
    for (int i = 0; i < 2; i++)
#pragma unroll
        for (int j = 0; j < 8; j++)
#pragma unroll
            for (int c = 0; c < 4; c++) acc[i][j][c] = 0.0f;

    for (int k0 = 0; k0 < HH; k0 += 32) {
#pragma unroll
        for (int it = 0; it < 2; it++) {
            int c   = t + it * 256;
            int row = c >> 2;
            int cc  = (c & 3) << 3;
            size_t ga = (size_t)(m0 + row) * HH + k0 + cc;
            size_t gb = (size_t)(n0 + row) * HH + k0 + cc;
            int so = row * TPAD + cc;
            *(uint4*)(sAhi + so) = *(const uint4*)(Ahi + ga);
            *(uint4*)(sAlo + so) = *(const uint4*)(Alo + ga);
            *(uint4*)(sBhi + so) = *(const uint4*)(Bhi + gb);
            *(uint4*)(sBlo + so) = *(const uint4*)(Blo + gb);
        }
        __syncthreads();

#pragma unroll
        for (int kk = 0; kk < 32; kk += 16) {
            const int acol = kk + 2 * tig;
            uint32_t af[2][4], bf[8][2];
#pragma unroll
            for (int nt = 0; nt < 8; nt++) {
                int r = (wn * 64 + nt * 8 + g) * TPAD + acol;
                bf[nt][0] = *(const uint32_t*)(sBhi + r);
                bf[nt][1] = *(const uint32_t*)(sBhi + r + 8);
            }
#pragma unroll
            for (int mt = 0; mt < 2; mt++) {
                int r = (wm * 32 + mt * 16 + g) * TPAD + acol;
                af[mt][0] = *(const uint32_t*)(sAhi + r);
                af[mt][1] = *(const uint32_t*)(sAhi + r + 8 * TPAD);
                af[mt][2] = *(const uint32_t*)(sAhi + r + 8);
                af[mt][3] = *(const uint32_t*)(sAhi + r + 8 * TPAD + 8);
            }
#pragma unroll
            for (int mt = 0; mt < 2; mt++)
#pragma unroll
                for (int nt = 0; nt < 8; nt++)
                    mma16816(acc[mt][nt], af[mt], bf[nt]);
#pragma unroll
            for (int mt = 0; mt < 2; mt++) {
                int r = (wm * 32 + mt * 16 + g) * TPAD + acol;
                af[mt][0] = *(const uint32_t*)(sAlo + r);
                af[mt][1] = *(const uint32_t*)(sAlo + r + 8 * TPAD);
                af[mt][2] = *(const uint32_t*)(sAlo + r + 8);
                af[mt][3] = *(const uint32_t*)(sAlo + r + 8 * TPAD + 8);
            }
#pragma unroll
            for (int mt = 0; mt < 2; mt++)
#pragma unroll
                for (int nt = 0; nt < 8; nt++)
                    mma16816(acc[mt][nt], af[mt], bf[nt]);
#pragma unroll
            for (int nt = 0; nt < 8; nt++) {
                int r = (wn * 64 + nt * 8 + g) * TPAD + acol;
                bf[nt][0] = *(const uint32_t*)(sBlo + r);
                bf[nt][1] = *(const uint32_t*)(sBlo + r + 8);
            }
#pragma unroll
            for (int mt = 0; mt < 2; mt++) {
                int r = (wm * 32 + mt * 16 + g) * TPAD + acol;
                af[mt][0] = *(const uint32_t*)(sAhi + r);
                af[mt][1] = *(const uint32_t*)(sAhi + r + 8 * TPAD);
                af[mt][2] = *(const uint32_t*)(sAhi + r + 8);
                af[mt][3] = *(const uint32_t*)(sAhi + r + 8 * TPAD + 8);
            }
#pragma unroll
            for (int mt = 0; mt < 2; mt++)
#pragma unroll
                for (int nt = 0; nt < 8; nt++)
                    mma16816(acc[mt][nt], af[mt], bf[nt]);
        }
        __syncthreads();
    }

    // epilogue: +bias (+pos for K), split hi/lo, store packed u32
#pragma unroll
    for (int mt = 0; mt < 2; mt++) {
#pragma unroll
        for (int nt = 0; nt < 8; nt++) {
            int m = m0 + wm * 32 + mt * 16 + g;
            int n = n0 + wn * 64 + nt * 8 + 2 * tig;
            float b0 = bias[n], b1 = bias[n + 1];
#pragma unroll
            for (int half = 0; half < 2; half++) {
                int mm = m + half * 8;
                float f0 = acc[mt][nt][2 * half]     + b0;
                float f1 = acc[mt][nt][2 * half + 1] + b1;
                if (z == 1) {
                    f0 += pos[(mm & (SKL - 1)) * DHD + (n & (DHD - 1))];
                    f1 += pos[(mm & (SKL - 1)) * DHD + ((n + 1) & (DHD - 1))];
                }
                __nv_bfloat162 hh2 = __floats2bfloat162_rn(f0, f1);
                float2 hf = __bfloat1622float2(hh2);
                __nv_bfloat162 ll2 = __floats2bfloat162_rn(f0 - hf.x, f1 - hf.y);
                *(uint32_t*)(oh + (size_t)mm * HH + n) = *(uint32_t*)&hh2;
                *(uint32_t*)(ol + (size_t)mm * HH + n) = *(uint32_t*)&ll2;
            }
        }
    }
}

// ---------------------------------------------------------------------------
// P2 = (pos @ pos^T) * C2   (512x512x64, fp32)
// ---------------------------------------------------------------------------
__global__ __launch_bounds__(256) void sgemm_nt(
    const float* __restrict__ A, const float* __restrict__ W,
    float* __restrict__ out, int M, int N, int K, float scale)
{
    const int BM = 128, BN = 128, BK = 16;
    __shared__ float As[BK][BM + 4];
    __shared__ float Bs[BK][BN + 4];

    const int t  = threadIdx.x;
    const int m0 = blockIdx.y * BM;
    const int n0 = blockIdx.x * BN;
    const int tm = (t >> 4) << 3;
    const int tn = (t & 15) << 3;

    float acc[8][8];
#pragma unroll
    for (int i = 0; i < 8; i++)
#pragma unroll
        for (int j = 0; j < 8; j++) acc[i][j] = 0.0f;

    for (int k0 = 0; k0 < K; k0 += BK) {
        for (int i = t; i < 512; i += 256) {
            int row = i >> 2;
            int c4  = (i & 3) << 2;
            float4 va = *(const float4*)(A + (size_t)(m0 + row) * K + k0 + c4);
            As[c4 + 0][row] = va.x; As[c4 + 1][row] = va.y;
            As[c4 + 2][row] = va.z; As[c4 + 3][row] = va.w;
            float4 vb = *(const float4*)(W + (size_t)(n0 + row) * K + k0 + c4);
            Bs[c4 + 0][row] = vb.x; Bs[c4 + 1][row] = vb.y;
            Bs[c4 + 2][row] = vb.z; Bs[c4 + 3][row] = vb.w;
        }
        __syncthreads();
#pragma unroll
        for (int kk = 0; kk < BK; kk++) {
            float a[8], b[8];
            *(float4*)(a + 0) = *(const float4*)&As[kk][tm];
            *(float4*)(a + 4) = *(const float4*)&As[kk][tm + 4];
            *(float4*)(b + 0) = *(const float4*)&Bs[kk][tn];
            *(float4*)(b + 4) = *(const float4*)&Bs[kk][tn + 4];
#pragma unroll
            for (int i = 0; i < 8; i++)
#pragma unroll
                for (int j = 0; j < 8; j++)
                    acc[i][j] += a[i] * b[j];
        }
        __syncthreads();
    }
#pragma unroll
    for (int i = 0; i < 8; i++)
#pragma unroll
        for (int j = 0; j < 8; j++)
            out[(size_t)(m0 + tm + i) * N + n0 + tn + j] = acc[i][j] * scale;
}

// ---------------------------------------------------------------------------
// Flash attention on HMMA. CTA = (128 q rows, head h, batch b). 8 warps x 16 rows.
// smem layout (bytes):
//   QH 0       QL 18432   KH 36864   KL 46080   VH 55296   VL 64512   MB 73728
// ---------------------------------------------------------------------------
#define FP 72            // padded row length (bf16 elems)
#define OQH 0
#define OQL 18432
#define OKH 36864
#define OKL 46080
#define OVH 55296
#define OVL 64512
#define OMB 73728
#define FSM (73728 + 256)

__global__ __launch_bounds__(256, 2) void flash_hmma(
    const __nv_bfloat16* __restrict__ qh, const __nv_bfloat16* __restrict__ ql,
    const __nv_bfloat16* __restrict__ kh, const __nv_bfloat16* __restrict__ kl,
    const __nv_bfloat16* __restrict__ vh, const __nv_bfloat16* __restrict__ vl,
    const float* __restrict__ P2, const int* __restrict__ mask,
    float* __restrict__ out)
{
    extern __shared__ char smc[];
    __nv_bfloat16* sQh = (__nv_bfloat16*)(smc + OQH);
    __nv_bfloat16* sQl = (__nv_bfloat16*)(smc + OQL);
    __nv_bfloat16* sKh = (__nv_bfloat16*)(smc + OKH);
    __nv_bfloat16* sKl = (__nv_bfloat16*)(smc + OKL);
    __nv_bfloat16* sVh = (__nv_bfloat16*)(smc + OVH);
    float*         smb = (float*)(smc + OMB);

    const int t    = threadIdx.x;
    const int lane = t & 31;
    const int w    = t >> 5;
    const int g    = lane >> 2;
    const int tig  = lane & 3;
    const int wr   = w << 4;                 // warp's 16-row strip
    const int b    = blockIdx.z;
    const int h    = blockIdx.y;
    const int q0   = blockIdx.x << 7;

    const uint32_t svh_u32 = smem_u32(smc + OVH);
    const uint32_t vl_off  = OVL - OVH;      // 9216

    // load Q tile (128 x 64) hi/lo
#pragma unroll
    for (int i = 0; i < 4; i++) {
        int idx = t + (i << 8);              // 0..1023
        int row = idx >> 3;
        int c   = (idx & 7) << 3;
        size_t gsrc = (size_t)(b * SQL + q0 + row) * HH + h * DHD + c;
        *(uint4*)(sQh + row * FP + c) = *(const uint4*)(qh + gsrc);
        *(uint4*)(sQl + row * FP + c) = *(const uint4*)(ql + gsrc);
    }

    float o[8][4];
#pragma unroll
    for (int i = 0; i < 8; i++)
#pragma unroll
        for (int c = 0; c < 4; c++) o[i][c] = 0.0f;
    float m0r = -1e30f, m1r = -1e30f, l0r = 0.0f, l1r = 0.0f;

    for (int kt = 0; kt < SKL / 64; kt++) {
        __syncthreads();
#pragma unroll
        for (int i = 0; i < 2; i++) {
            int idx = t + (i << 8);          // 0..511
            int row = idx >> 3;
            int c   = (idx & 7) << 3;
            size_t gsrc = (size_t)(b * SKL + kt * 64 + row) * HH + h * DHD + c;
            *(uint4*)(sKh + row * FP + c) = *(const uint4*)(kh + gsrc);
            *(uint4*)(sKl + row * FP + c) = *(const uint4*)(kl + gsrc);
            *(uint4*)((__nv_bfloat16*)(smc + OVH) + row * FP + c) = *(const uint4*)(vh + gsrc);
            *(uint4*)((__nv_bfloat16*)(smc + OVL) + row * FP + c) = *(const uint4*)(vl + gsrc);
        }
        if (t < 64) smb[t] = (mask[b * SKL + kt * 64 + t] == 0) ? -1e30f : 0.0f;
        __syncthreads();

        // ---- S = Q K'^T  (3-term split) ----
        float s[8][4];
#pragma unroll
        for (int nt = 0; nt < 8; nt++)
#pragma unroll
            for (int c = 0; c < 4; c++) s[nt][c] = 0.0f;

#pragma unroll
        for (int kk = 0; kk < 4; kk++) {
            const int abase = (wr + g) * FP + kk * 16 + 2 * tig;
            uint32_t ah[4], al[4];
            ah[0] = *(const uint32_t*)(sQh + abase);
            ah[1] = *(const uint32_t*)(sQh + abase + 8 * FP);
            ah[2] = *(const uint32_t*)(sQh + abase + 8);
            ah[3] = *(const uint32_t*)(sQh + abase + 8 * FP + 8);
            al[0] = *(const uint32_t*)(sQl + abase);
            al[1] = *(const uint32_t*)(sQl + abase + 8 * FP);
            al[2] = *(const uint32_t*)(sQl + abase + 8);
            al[3] = *(const uint32_t*)(sQl + abase + 8 * FP + 8);
#pragma unroll
            for (int nt = 0; nt < 8; nt++) {
                const int kb = (nt * 8 + g) * FP + kk * 16 + 2 * tig;
                uint32_t bh[2], bl[2];
                bh[0] = *(const uint32_t*)(sKh + kb);
                bh[1] = *(const uint32_t*)(sKh + kb + 8);
                bl[0] = *(const uint32_t*)(sKl + kb);
                bl[1] = *(const uint32_t*)(sKl + kb + 8);
                mma16816(s[nt], ah, bh);
                mma16816(s[nt], al, bh);
                mma16816(s[nt], ah, bl);
            }
        }

        // ---- bias + mask + online softmax (log2 domain) ----
        const float* pg0 = P2 + (size_t)(q0 + wr + g) * SKL + kt * 64;
        const float* pg1 = pg0 + 8 * SKL;
        float vm0 = -1e30f, vm1 = -1e30f;
#pragma unroll
        for (int nt = 0; nt < 8; nt++) {
            int cc = nt * 8 + 2 * tig;
            float2 p0 = *(const float2*)(pg0 + cc);
            float2 p1 = *(const float2*)(pg1 + cc);
            float mb0 = smb[cc], mb1 = smb[cc + 1];
            s[nt][0] = fmaf(s[nt][0], C2, p0.x) + mb0;
            s[nt][1] = fmaf(s[nt][1], C2, p0.y) + mb1;
            s[nt][2] = fmaf(s[nt][2], C2, p1.x) + mb0;
            s[nt][3] = fmaf(s[nt][3], C2, p1.y) + mb1;
            vm0 = fmaxf(vm0, fmaxf(s[nt][0], s[nt][1]));
            vm1 = fmaxf(vm1, fmaxf(s[nt][2], s[nt][3]));
        }
        vm0 = fmaxf(vm0, __shfl_xor_sync(0xffffffffu, vm0, 1));
        vm0 = fmaxf(vm0, __shfl_xor_sync(0xffffffffu, vm0, 2));
        vm1 = fmaxf(vm1, __shfl_xor_sync(0xffffffffu, vm1, 1));
        vm1 = fmaxf(vm1, __shfl_xor_sync(0xffffffffu, vm1, 2));
        float mn0 = fmaxf(m0r, vm0), mn1 = fmaxf(m1r, vm1);
        float cr0 = ex2f(m0r - mn0), cr1 = ex2f(m1r - mn1);
        m0r = mn0; m1r = mn1;

        float rs0 = 0.0f, rs1 = 0.0f;
#pragma unroll
        for (int nt = 0; nt < 8; nt++) {
            s[nt][0] = ex2f(s[nt][0] - mn0); rs0 += s[nt][0];
            s[nt][1] = ex2f(s[nt][1] - mn0); rs0 += s[nt][1];
            s[nt][2] = ex2f(s[nt][2] - mn1); rs1 += s[nt][2];
            s[nt][3] = ex2f(s[nt][3] - mn1); rs1 += s[nt][3];
        }
        rs0 += __shfl_xor_sync(0xffffffffu, rs0, 1);
        rs0 += __shfl_xor_sync(0xffffffffu, rs0, 2);
        rs1 += __shfl_xor_sync(0xffffffffu, rs1, 1);
        rs1 += __shfl_xor_sync(0xffffffffu, rs1, 2);
        l0r = l0r * cr0 + rs0;
        l1r = l1r * cr1 + rs1;
#pragma unroll
        for (int nt = 0; nt < 8; nt++) {
            o[nt][0] *= cr0; o[nt][1] *= cr0;
            o[nt][2] *= cr1; o[nt][3] *= cr1;
        }

        // ---- O += P @ V  (3-term split; P hi/lo from registers) ----
        const uint32_t vrow = (uint32_t)(lane & 15) * (FP * 2);
#pragma unroll
        for (int j = 0; j < 4; j++) {
            const int na = 2 * j, nb = 2 * j + 1;
            uint32_t aph[4], apl[4];
            aph[0] = pack_bf2(s[na][0], s[na][1]);
            aph[1] = pack_bf2(s[na][2], s[na][3]);
            aph[2] = pack_bf2(s[nb][0], s[nb][1]);
            aph[3] = pack_bf2(s[nb][2], s[nb][3]);
            {
                float2 f;
                f = __bfloat1622float2(*(__nv_bfloat162*)&aph[0]);
                apl[0] = pack_bf2(s[na][0] - f.x, s[na][1] - f.y);
                f = __bfloat1622float2(*(__nv_bfloat162*)&aph[1]);
                apl[1] = pack_bf2(s[na][2] - f.x, s[na][3] - f.y);
                f = __bfloat1622float2(*(__nv_bfloat162*)&aph[2]);
                apl[2] = pack_bf2(s[nb][0] - f.x, s[nb][1] - f.y);
                f = __bfloat1622float2(*(__nv_bfloat162*)&aph[3]);
                apl[3] = pack_bf2(s[nb][2] - f.x, s[nb][3] - f.y);
            }
            const uint32_t jadr = svh_u32 + j * 16 * (FP * 2) + vrow;
#pragma unroll
            for (int ntv = 0; ntv < 8; ntv++) {
                uint32_t bh[2], bl[2];
                ldmx2t(bh[0], bh[1], jadr + ntv * 16);
                ldmx2t(bl[0], bl[1], jadr + ntv * 16 + vl_off);
                mma16816(o[ntv], aph, bh);
                mma16816(o[ntv], apl, bh);
                mma16816(o[ntv], aph, bl);
            }
        }
    }

    // ---- epilogue ----
    float inv0 = 1.0f / l0r, inv1 = 1.0f / l1r;
    float* or0 = out + (size_t)(b * SQL + q0 + wr + g) * HH + h * DHD;
    float* or1 = or0 + 8 * HH;
#pragma unroll
    for (int ntv = 0; ntv < 8; ntv++) {
        int cc = ntv * 8 + 2 * tig;
        float2 w0 = make_float2(o[ntv][0] * inv0, o[ntv][1] * inv0);
        float2 w1 = make_float2(o[ntv][2] * inv1, o[ntv][3] * inv1);
        *(float2*)(or0 + cc) = w0;
        *(float2*)(or1 + cc) = w1;
    }
}

// ---------------------------------------------------------------------------
extern "C" void kernel_launch(void* const* d_in, const int* in_sizes, int n_in,
                              void* d_out, int out_size)
{
    const float* hidden  = (const float*)d_in[0];
    const float* context = (const float*)d_in[1];
    const int*   mask    = (const int*)d_in[2];
    const float* Wq      = (const float*)d_in[3];
    const float* bq      = (const float*)d_in[4];
    const float* Wk      = (const float*)d_in[5];
    const float* bk      = (const float*)d_in[6];
    const float* Wv      = (const float*)d_in[7];
    const float* bv      = (const float*)d_in[8];
    const float* pos     = (const float*)d_in[9];
    float* out = (float*)d_out;

    float* P2;
    cudaGetSymbolAddress((void**)&P2, g_P2);
    __nv_bfloat16 *qh, *ql, *kh, *kl, *vh, *vl;
    cudaGetSymbolAddress((void**)&qh, g_qh);
    cudaGetSymbolAddress((void**)&ql, g_ql);
    cudaGetSymbolAddress((void**)&kh, g_kh);
    cudaGetSymbolAddress((void**)&kl, g_kl);
    cudaGetSymbolAddress((void**)&vh, g_vh);
    cudaGetSymbolAddress((void**)&vl, g_vl);
    __nv_bfloat16 *hh, *hl, *ch, *cl, *wh, *wl;
    cudaGetSymbolAddress((void**)&hh, g_hid_hi);
    cudaGetSymbolAddress((void**)&hl, g_hid_lo);
    cudaGetSymbolAddress((void**)&ch, g_ctx_hi);
    cudaGetSymbolAddress((void**)&cl, g_ctx_lo);
    cudaGetSymbolAddress((void**)&wh, g_w_hi);
    cudaGetSymbolAddress((void**)&wl, g_w_lo);

    const int nA4 = MROWS * HH / 4, nW4 = HH * HH / 4;
    cvt_split<<<(nA4 + 255) / 256, 256>>>(hidden,  hh, hl, nA4);
    cvt_split<<<(nA4 + 255) / 256, 256>>>(context, ch, cl, nA4);
    cvt_split<<<(nW4 + 255) / 256, 256>>>(Wq, wh,               wl,               nW4);
    cvt_split<<<(nW4 + 255) / 256, 256>>>(Wk, wh + HH * HH,     wl + HH * HH,     nW4);
    cvt_split<<<(nW4 + 255) / 256, 256>>>(Wv, wh + 2 * HH * HH, wl + 2 * HH * HH, nW4);

    dim3 gproj(HH / 128, MROWS / 128, 3);
    qkv_hmma<<<gproj, 256>>>(hh, hl, ch, cl, wh, wl, bq, bk, bv, pos,
                             qh, ql, kh, kl, vh, vl);

    dim3 gpos(SKL / 128, SQL / 128);
    sgemm_nt<<<gpos, 256>>>(pos, pos, P2, SQL, SKL, DHD, C2);

    cudaFuncSetAttribute(flash_hmma, cudaFuncAttributeMaxDynamicSharedMemorySize, FSM);
    dim3 gattn(SQL / 128, NHD, BB);
    flash_hmma<<<gattn, 256, FSM>>>(qh, ql, kh, kl, vh, vl, P2, mask, out);
}

// round 5
// speedup vs baseline: 3.6866x; 1.1827x over previous
#include <cuda_runtime.h>
#include <cuda_bf16.h>
#include <cstdint>

#define BB  8
#define SQL 512
#define SKL 512
#define HH  768
#define NHD 12
#define DHD 64
#define MROWS (BB * SQL)   // 4096

#define C2 0.1803368801111244f   // 0.125 * log2(e)

// ---------------- scratch ----------------
__device__ float g_P2[SQL * SKL];
__device__ __nv_bfloat16 g_qh[MROWS * HH];
__device__ __nv_bfloat16 g_ql[MROWS * HH];
__device__ __nv_bfloat16 g_kh[MROWS * HH];
__device__ __nv_bfloat16 g_kl[MROWS * HH];
__device__ __nv_bfloat16 g_vh[MROWS * HH];
__device__ __nv_bfloat16 g_vl[MROWS * HH];
__device__ __nv_bfloat16 g_hid_hi[MROWS * HH];
__device__ __nv_bfloat16 g_hid_lo[MROWS * HH];
__device__ __nv_bfloat16 g_ctx_hi[MROWS * HH];
__device__ __nv_bfloat16 g_ctx_lo[MROWS * HH];
__device__ __nv_bfloat16 g_w_hi[3 * HH * HH];
__device__ __nv_bfloat16 g_w_lo[3 * HH * HH];

// ---------------- helpers ----------------
__device__ __forceinline__ float ex2f(float x) {
    float y;
    asm("ex2.approx.ftz.f32 %0, %1;" : "=f"(y) : "f"(x));
    return y;
}
__device__ __forceinline__ uint32_t smem_u32(const void* p) {
    uint32_t a;
    asm("{ .reg .u64 t; cvta.to.shared.u64 t, %1; cvt.u32.u64 %0, t; }" : "=r"(a) : "l"(p));
    return a;
}
__device__ __forceinline__ void cpa16(uint32_t dst, const void* src) {
    asm volatile("cp.async.cg.shared.global [%0], [%1], 16;" :: "r"(dst), "l"(src));
}
#define CPA_COMMIT() asm volatile("cp.async.commit_group;" ::: "memory")
#define CPA_WAIT(n)  asm volatile("cp.async.wait_group %0;" :: "n"(n) : "memory")

__device__ __forceinline__ void mma16816(float* d, const uint32_t* a, const uint32_t* b)
{
    asm volatile(
        "mma.sync.aligned.m16n8k16.row.col.f32.bf16.bf16.f32 "
        "{%0,%1,%2,%3}, {%4,%5,%6,%7}, {%8,%9}, {%0,%1,%2,%3};"
        : "+f"(d[0]), "+f"(d[1]), "+f"(d[2]), "+f"(d[3])
        : "r"(a[0]), "r"(a[1]), "r"(a[2]), "r"(a[3]), "r"(b[0]), "r"(b[1]));
}
__device__ __forceinline__ void ldmx2t(uint32_t& r0, uint32_t& r1, uint32_t addr)
{
    asm volatile("ldmatrix.sync.aligned.m8n8.x2.trans.shared.b16 {%0,%1}, [%2];"
                 : "=r"(r0), "=r"(r1) : "r"(addr));
}
__device__ __forceinline__ uint32_t pack_bf2(float a, float b) {
    __nv_bfloat162 h = __floats2bfloat162_rn(a, b);
    return *(uint32_t*)&h;
}

// ---------------------------------------------------------------------------
// Fused fp32 -> bf16 hi/lo split for all 5 arrays (blockIdx.y selects)
// ---------------------------------------------------------------------------
__global__ void cvt_all(
    const float* __restrict__ hidden, const float* __restrict__ context,
    const float* __restrict__ Wq, const float* __restrict__ Wk, const float* __restrict__ Wv,
    __nv_bfloat16* __restrict__ hh, __nv_bfloat16* __restrict__ hl,
    __nv_bfloat16* __restrict__ ch, __nv_bfloat16* __restrict__ cl,
    __nv_bfloat16* __restrict__ wh, __nv_bfloat16* __restrict__ wl)
{
    const int y = blockIdx.y;
    const float* x;
    __nv_bfloat16 *hi, *lo;
    int n4;
    const int nA4 = MROWS * HH / 4, nW4 = HH * HH / 4;
    switch (y) {
        case 0: x = hidden;  hi = hh;              lo = hl;              n4 = nA4; break;
        case 1: x = context; hi = ch;              lo = cl;              n4 = nA4; break;
        case 2: x = Wq;      hi = wh;              lo = wl;              n4 = nW4; break;
        case 3: x = Wk;      hi = wh + HH * HH;    lo = wl + HH * HH;    n4 = nW4; break;
        default:x = Wv;      hi = wh + 2 * HH * HH; lo = wl + 2 * HH * HH; n4 = nW4; break;
    }
    int i = blockIdx.x * blockDim.x + threadIdx.x;
    if (i >= n4) return;
    float4 v = ((const float4*)x)[i];
    __nv_bfloat16 h0 = __float2bfloat16_rn(v.x);
    __nv_bfloat16 h1 = __float2bfloat16_rn(v.y);
    __nv_bfloat16 h2 = __float2bfloat16_rn(v.z);
    __nv_bfloat16 h3 = __float2bfloat16_rn(v.w);
    __nv_bfloat16 l0 = __float2bfloat16_rn(v.x - __bfloat162float(h0));
    __nv_bfloat16 l1 = __float2bfloat16_rn(v.y - __bfloat162float(h1));
    __nv_bfloat16 l2 = __float2bfloat16_rn(v.z - __bfloat162float(h2));
    __nv_bfloat16 l3 = __float2bfloat16_rn(v.w - __bfloat162float(h3));
    __nv_bfloat162 a, b;
    a.x = h0; a.y = h1; b.x = h2; b.y = h3;
    ((__nv_bfloat162*)hi)[2 * i] = a; ((__nv_bfloat162*)hi)[2 * i + 1] = b;
    a.x = l0; a.y = l1; b.x = l2; b.y = l3;
    ((__nv_bfloat162*)lo)[2 * i] = a; ((__nv_bfloat162*)lo)[2 * i + 1] = b;
}

// ---------------------------------------------------------------------------
// QKV projection via HMMA, 3-term split, cp.async double-buffered.
// CTA 128x128, BK=32, 256 threads, smem 2 stages x 4 tiles x (128x40 bf16).
// ---------------------------------------------------------------------------
#define TPAD 40
#define QSTG 40960          // bytes per stage (4 tiles x 10240)
#define QTIL 10240

__global__ __launch_bounds__(256, 2) void qkv_hmma(
    const __nv_bfloat16* __restrict__ hid_hi, const __nv_bfloat16* __restrict__ hid_lo,
    const __nv_bfloat16* __restrict__ ctx_hi, const __nv_bfloat16* __restrict__ ctx_lo,
    const __nv_bfloat16* __restrict__ w_hi,   const __nv_bfloat16* __restrict__ w_lo,
    const float* __restrict__ bq, const float* __restrict__ bk, const float* __restrict__ bv,
    const float* __restrict__ pos,
    __nv_bfloat16* __restrict__ qh, __nv_bfloat16* __restrict__ ql,
    __nv_bfloat16* __restrict__ kh, __nv_bfloat16* __restrict__ kl,
    __nv_bfloat16* __restrict__ vh, __nv_bfloat16* __restrict__ vl)
{
    extern __shared__ char smc[];
    const uint32_t sb = smem_u32(smc);

    const int z = blockIdx.z;
    const __nv_bfloat16* Ahi = (z == 0) ? hid_hi : ctx_hi;
    const __nv_bfloat16* Alo = (z == 0) ? hid_lo : ctx_lo;
    const __nv_bfloat16* Bhi = w_hi + (size_t)z * HH * HH;
    const __nv_bfloat16* Blo = w_lo + (size_t)z * HH * HH;
    const float* bias = (z == 0) ? bq : ((z == 1) ? bk : bv);
    __nv_bfloat16* oh = (z == 0) ? qh : ((z == 1) ? kh : vh);
    __nv_bfloat16* ol = (z == 0) ? ql : ((z == 1) ? kl : vl);

    const int t    = threadIdx.x;
    const int lane = t & 31;
    const int wid  = t >> 5;
    const int wm   = wid & 3;
    const int wn   = wid >> 2;
    const int g    = lane >> 2;
    const int tig  = lane & 3;
    const int m0   = blockIdx.y << 7;
    const int n0   = blockIdx.x << 7;

    // precomputed per-thread load addressing (2 chunks/thread/tile)
    const int row0 = t >> 2,            cc0 = (t & 3) << 3;
    const int row1 = (t + 256) >> 2,    cc1 = ((t + 256) & 3) << 3;
    const uint32_t so0 = row0 * 80 + cc0 * 2;
    const uint32_t so1 = row1 * 80 + cc1 * 2;

    float acc[2][8][4];
#pragma unroll
    for (int i = 0; i < 2; i++)
#pragma unroll
        for (int j = 0; j < 8; j++)
#pragma unroll
            for (int c = 0; c < 4; c++) acc[i][j][c] = 0.0f;

    auto issue = [&](int kt, int stg) {
        const int k0 = kt << 5;
        const uint32_t base = sb + stg * QSTG;
        size_t ga0 = (size_t)(m0 + row0) * HH + k0 + cc0;
        size_t ga1 = (size_t)(m0 + row1) * HH + k0 + cc1;
        size_t gb0 = (size_t)(n0 + row0) * HH + k0 + cc0;
        size_t gb1 = (size_t)(n0 + row1) * HH + k0 + cc1;
        cpa16(base + so0,             Ahi + ga0);
        cpa16(base + so1,             Ahi + ga1);
        cpa16(base + QTIL + so0,      Alo + ga0);
        cpa16(base + QTIL + so1,      Alo + ga1);
        cpa16(base + 2 * QTIL + so0,  Bhi + gb0);
        cpa16(base + 2 * QTIL + so1,  Bhi + gb1);
        cpa16(base + 3 * QTIL + so0,  Blo + gb0);
        cpa16(base + 3 * QTIL + so1,  Blo + gb1);
    };

    issue(0, 0);
    CPA_COMMIT();

    const int NT = HH / 32;   // 24
    for (int kt = 0; kt < NT; kt++) {
        if (kt + 1 < NT) {
            issue(kt + 1, (kt + 1) & 1);
            CPA_COMMIT();
            CPA_WAIT(1);
        } else {
            CPA_WAIT(0);
        }
        __syncthreads();

        const __nv_bfloat16* sAhi = (const __nv_bfloat16*)(smc + (kt & 1) * QSTG);
        const __nv_bfloat16* sAlo = (const __nv_bfloat16*)(smc + (kt & 1) * QSTG + QTIL);
        const __nv_bfloat16* sBhi = (const __nv_bfloat16*)(smc + (kt & 1) * QSTG + 2 * QTIL);
        const __nv_bfloat16* sBlo = (const __nv_bfloat16*)(smc + (kt & 1) * QSTG + 3 * QTIL);

#pragma unroll
        for (int kk = 0; kk < 32; kk += 16) {
            const int acol = kk + 2 * tig;
            uint32_t af[2][4], bf[8][2];
#pragma unroll
            for (int nt = 0; nt < 8; nt++) {
                int r = (wn * 64 + nt * 8 + g) * TPAD + acol;
                bf[nt][0] = *(const uint32_t*)(sBhi + r);
                bf[nt][1] = *(const uint32_t*)(sBhi + r + 8);
            }
#pragma unroll
            for (int mt = 0; mt < 2; mt++) {
                int r = (wm * 32 + mt * 16 + g) * TPAD + acol;
                af[mt][0] = *(const uint32_t*)(sAhi + r);
                af[mt][1] = *(const uint32_t*)(sAhi + r + 8 * TPAD);
                af[mt][2] = *(const uint32_t*)(sAhi + r + 8);
                af[mt][3] = *(const uint32_t*)(sAhi + r + 8 * TPAD + 8);
            }
#pragma unroll
            for (int mt = 0; mt < 2; mt++)
#pragma unroll
                for (int nt = 0; nt < 8; nt++)
                    mma16816(acc[mt][nt], af[mt], bf[nt]);
#pragma unroll
            for (int mt = 0; mt < 2; mt++) {
                int r = (wm * 32 + mt * 16 + g) * TPAD + acol;
                af[mt][0] = *(const uint32_t*)(sAlo + r);
                af[mt][1] = *(const uint32_t*)(sAlo + r + 8 * TPAD);
                af[mt][2] = *(const uint32_t*)(sAlo + r + 8);
                af[mt][3] = *(const uint32_t*)(sAlo + r + 8 * TPAD + 8);
            }
#pragma unroll
            for (int mt = 0; mt < 2; mt++)
#pragma unroll
                for (int nt = 0; nt < 8; nt++)
                    mma16816(acc[mt][nt], af[mt], bf[nt]);
#pragma unroll
            for (int nt = 0; nt < 8; nt++) {
                int r = (wn * 64 + nt * 8 + g) * TPAD + acol;
                bf[nt][0] = *(const uint32_t*)(sBlo + r);
                bf[nt][1] = *(const uint32_t*)(sBlo + r + 8);
            }
#pragma unroll
            for (int mt = 0; mt < 2; mt++) {
                int r = (wm * 32 + mt * 16 + g) * TPAD + acol;
                af[mt][0] = *(const uint32_t*)(sAhi + r);
                af[mt][1] = *(const uint32_t*)(sAhi + r + 8 * TPAD);
                af[mt][2] = *(const uint32_t*)(sAhi + r + 8);
                af[mt][3] = *(const uint32_t*)(sAhi + r + 8 * TPAD + 8);
            }
#pragma unroll
            for (int mt = 0; mt < 2; mt++)
#pragma unroll
                for (int nt = 0; nt < 8; nt++)
                    mma16816(acc[mt][nt], af[mt], bf[nt]);
        }
        __syncthreads();
    }

    // epilogue: +bias (+pos for K), split hi/lo, store packed u32
#pragma unroll
    for (int mt = 0; mt < 2; mt++) {
#pragma unroll
        for (int nt = 0; nt < 8; nt++) {
            int m = m0 + wm * 32 + mt * 16 + g;
            int n = n0 + wn * 64 + nt * 8 + 2 * tig;
            float b0 = bias[n], b1 = bias[n + 1];
#pragma unroll
            for (int half = 0; half < 2; half++) {
                int mm = m + half * 8;
                float f0 = acc[mt][nt][2 * half]     + b0;
                float f1 = acc[mt][nt][2 * half + 1] + b1;
                if (z == 1) {
                    f0 += pos[(mm & (SKL - 1)) * DHD + (n & (DHD - 1))];
                    f1 += pos[(mm & (SKL - 1)) * DHD + ((n + 1) & (DHD - 1))];
                }
                __nv_bfloat162 hh2 = __floats2bfloat162_rn(f0, f1);
                float2 hf = __bfloat1622float2(hh2);
                __nv_bfloat162 ll2 = __floats2bfloat162_rn(f0 - hf.x, f1 - hf.y);
                *(uint32_t*)(oh + (size_t)mm * HH + n) = *(uint32_t*)&hh2;
                *(uint32_t*)(ol + (size_t)mm * HH + n) = *(uint32_t*)&ll2;
            }
        }
    }
}

// ---------------------------------------------------------------------------
// P2 = (pos @ pos^T) * C2  — 64x64 tiles, 64 CTAs, K=64 single shot.
// ---------------------------------------------------------------------------
__global__ __launch_bounds__(128) void pos_gemm(
    const float* __restrict__ A, float* __restrict__ out)
{
    __shared__ float As[64][68];
    __shared__ float Bs[64][68];

    const int t  = threadIdx.x;
    const int m0 = blockIdx.y << 6;
    const int n0 = blockIdx.x << 6;
    const int tm = (t >> 3) << 2;   // 16 groups x 4 rows
    const int tn = (t & 7) << 3;    // 8 groups x 8 cols

    // load 64x64 fp32 tiles, stored transposed [k][row]
#pragma unroll
    for (int i = 0; i < 8; i++) {
        int idx = t + (i << 7);      // 0..1023
        int row = idx >> 4;
        int c4  = (idx & 15) << 2;
        float4 va = *(const float4*)(A + (size_t)(m0 + row) * DHD + c4);
        As[c4 + 0][row] = va.x; As[c4 + 1][row] = va.y;
        As[c4 + 2][row] = va.z; As[c4 + 3][row] = va.w;
        float4 vb = *(const float4*)(A + (size_t)(n0 + row) * DHD + c4);
        Bs[c4 + 0][row] = vb.x; Bs[c4 + 1][row] = vb.y;
        Bs[c4 + 2][row] = vb.z; Bs[c4 + 3][row] = vb.w;
    }
    __syncthreads();

    float acc[4][8];
#pragma unroll
    for (int i = 0; i < 4; i++)
#pragma unroll
        for (int j = 0; j < 8; j++) acc[i][j] = 0.0f;

#pragma unroll 8
    for (int kk = 0; kk < 64; kk++) {
        float a[4], b[8];
        *(float4*)a = *(const float4*)&As[kk][tm];
        *(float4*)(b + 0) = *(const float4*)&Bs[kk][tn];
        *(float4*)(b + 4) = *(const float4*)&Bs[kk][tn + 4];
#pragma unroll
        for (int i = 0; i < 4; i++)
#pragma unroll
            for (int j = 0; j < 8; j++)
                acc[i][j] += a[i] * b[j];
    }

#pragma unroll
    for (int i = 0; i < 4; i++)
#pragma unroll
        for (int j = 0; j < 8; j++)
            out[(size_t)(m0 + tm + i) * SKL + n0 + tn + j] = acc[i][j] * C2;
}

// ---------------------------------------------------------------------------
// Flash attention on HMMA, cp.async double-buffered K/V.
// smem: Q hi/lo 36864 | KV 2 stages x 36864 | mask 2048  = 112640 B
// ---------------------------------------------------------------------------
#define FP   72
#define OKV  36864
#define KSTG 36864          // per stage: KH 0, KL 9216, VH 18432, VL 27648
#define KTIL 9216
#define OMB  (36864 + 2 * 36864)
#define FSM  (OMB + 2048)

__global__ __launch_bounds__(256, 2) void flash_hmma(
    const __nv_bfloat16* __restrict__ qh, const __nv_bfloat16* __restrict__ ql,
    const __nv_bfloat16* __restrict__ kh, const __nv_bfloat16* __restrict__ kl,
    const __nv_bfloat16* __restrict__ vh, const __nv_bfloat16* __restrict__ vl,
    const float* __restrict__ P2, const int* __restrict__ mask,
    float* __restrict__ out)
{
    extern __shared__ char smc[];
    __nv_bfloat16* sQh = (__nv_bfloat16*)(smc);
    __nv_bfloat16* sQl = (__nv_bfloat16*)(smc + 18432);
    float*         smb = (float*)(smc + OMB);
    const uint32_t sb  = smem_u32(smc);

    const int t    = threadIdx.x;
    const int lane = t & 31;
    const int w    = t >> 5;
    const int g    = lane >> 2;
    const int tig  = lane & 3;
    const int wr   = w << 4;
    const int b    = blockIdx.z;
    const int h    = blockIdx.y;
    const int q0   = blockIdx.x << 7;

    // per-thread K/V chunk addressing (2 chunks/thread/tile)
    const int krow0 = t >> 3,          kc0 = (t & 7) << 3;
    const int krow1 = (t + 256) >> 3,  kc1 = ((t + 256) & 7) << 3;
    const uint32_t ko0 = krow0 * 144 + kc0 * 2;
    const uint32_t ko1 = krow1 * 144 + kc1 * 2;

    auto issue_kv = [&](int kt, int stg) {
        const uint32_t base = sb + OKV + stg * KSTG;
        size_t g0 = (size_t)(b * SKL + kt * 64 + krow0) * HH + h * DHD + kc0;
        size_t g1 = (size_t)(b * SKL + kt * 64 + krow1) * HH + h * DHD + kc1;
        cpa16(base + ko0,            kh + g0);
        cpa16(base + ko1,            kh + g1);
        cpa16(base + KTIL + ko0,     kl + g0);
        cpa16(base + KTIL + ko1,     kl + g1);
        cpa16(base + 2 * KTIL + ko0, vh + g0);
        cpa16(base + 2 * KTIL + ko1, vh + g1);
        cpa16(base + 3 * KTIL + ko0, vl + g0);
        cpa16(base + 3 * KTIL + ko1, vl + g1);
    };

    issue_kv(0, 0);
    CPA_COMMIT();

    // Q tile + full mask row (regular loads)
#pragma unroll
    for (int i = 0; i < 4; i++) {
        int idx = t + (i << 8);
        int row = idx >> 3;
        int c   = (idx & 7) << 3;
        size_t gsrc = (size_t)(b * SQL + q0 + row) * HH + h * DHD + c;
        *(uint4*)(sQh + row * FP + c) = *(const uint4*)(qh + gsrc);
        *(uint4*)(sQl + row * FP + c) = *(const uint4*)(ql + gsrc);
    }
    {
        int i0 = t, i1 = t + 256;
        smb[i0] = (mask[b * SKL + i0] == 0) ? -1e30f : 0.0f;
        smb[i1] = (mask[b * SKL + i1] == 0) ? -1e30f : 0.0f;
    }

    float o[8][4];
#pragma unroll
    for (int i = 0; i < 8; i++)
#pragma unroll
        for (int c = 0; c < 4; c++) o[i][c] = 0.0f;
    float m0r = -1e30f, m1r = -1e30f, l0r = 0.0f, l1r = 0.0f;

    const int NT = SKL / 64;   // 8
    for (int kt = 0; kt < NT; kt++) {
        if (kt + 1 < NT) {
            issue_kv(kt + 1, (kt + 1) & 1);
            CPA_COMMIT();
            CPA_WAIT(1);
        } else {
            CPA_WAIT(0);
        }
        __syncthreads();

        const int stg = kt & 1;
        const __nv_bfloat16* sKh = (const __nv_bfloat16*)(smc + OKV + stg * KSTG);
        const __nv_bfloat16* sKl = (const __nv_bfloat16*)(smc + OKV + stg * KSTG + KTIL);
        const uint32_t svh = sb + OKV + stg * KSTG + 2 * KTIL;

        // ---- S = Q K'^T ----
        float s[8][4];
#pragma unroll
        for (int nt = 0; nt < 8; nt++)
#pragma unroll
            for (int c = 0; c < 4; c++) s[nt][c] = 0.0f;

#pragma unroll
        for (int kk = 0; kk < 4; kk++) {
            const int abase = (wr + g) * FP + kk * 16 + 2 * tig;
            uint32_t ah[4], al[4];
            ah[0] = *(const uint32_t*)(sQh + abase);
            ah[1] = *(const uint32_t*)(sQh + abase + 8 * FP);
            ah[2] = *(const uint32_t*)(sQh + abase + 8);
            ah[3] = *(const uint32_t*)(sQh + abase + 8 * FP + 8);
            al[0] = *(const uint32_t*)(sQl + abase);
            al[1] = *(const uint32_t*)(sQl + abase + 8 * FP);
            al[2] = *(const uint32_t*)(sQl + abase + 8);
            al[3] = *(const uint32_t*)(sQl + abase + 8 * FP + 8);
#pragma unroll
            for (int nt = 0; nt < 8; nt++) {
                const int kb = (nt * 8 + g) * FP + kk * 16 + 2 * tig;
                uint32_t bh[2], bl[2];
                bh[0] = *(const uint32_t*)(sKh + kb);
                bh[1] = *(const uint32_t*)(sKh + kb + 8);
                bl[0] = *(const uint32_t*)(sKl + kb);
                bl[1] = *(const uint32_t*)(sKl + kb + 8);
                mma16816(s[nt], ah, bh);
                mma16816(s[nt], al, bh);
                mma16816(s[nt], ah, bl);
            }
        }

        // ---- bias + mask + online softmax ----
        const float* pg0 = P2 + (size_t)(q0 + wr + g) * SKL + kt * 64;
        const float* pg1 = pg0 + 8 * SKL;
        const float* mrow = smb + kt * 64;
        float vm0 = -1e30f, vm1 = -1e30f;
#pragma unroll
        for (int nt = 0; nt < 8; nt++) {
            int cc = nt * 8 + 2 * tig;
            float2 p0 = *(const float2*)(pg0 + cc);
            float2 p1 = *(const float2*)(pg1 + cc);
            float mb0 = mrow[cc], mb1 = mrow[cc + 1];
            s[nt][0] = fmaf(s[nt][0], C2, p0.x) + mb0;
            s[nt][1] = fmaf(s[nt][1], C2, p0.y) + mb1;
            s[nt][2] = fmaf(s[nt][2], C2, p1.x) + mb0;
            s[nt][3] = fmaf(s[nt][3], C2, p1.y) + mb1;
            vm0 = fmaxf(vm0, fmaxf(s[nt][0], s[nt][1]));
            vm1 = fmaxf(vm1, fmaxf(s[nt][2], s[nt][3]));
        }
        vm0 = fmaxf(vm0, __shfl_xor_sync(0xffffffffu, vm0, 1));
        vm0 = fmaxf(vm0, __shfl_xor_sync(0xffffffffu, vm0, 2));
        vm1 = fmaxf(vm1, __shfl_xor_sync(0xffffffffu, vm1, 1));
        vm1 = fmaxf(vm1, __shfl_xor_sync(0xffffffffu, vm1, 2));
        float mn0 = fmaxf(m0r, vm0), mn1 = fmaxf(m1r, vm1);
        float cr0 = ex2f(m0r - mn0), cr1 = ex2f(m1r - mn1);
        m0r = mn0; m1r = mn1;

        float rs0 = 0.0f, rs1 = 0.0f;
#pragma unroll
        for (int nt = 0; nt < 8; nt++) {
            s[nt][0] = ex2f(s[nt][0] - mn0); rs0 += s[nt][0];
            s[nt][1] = ex2f(s[nt][1] - mn0); rs0 += s[nt][1];
            s[nt][2] = ex2f(s[nt][2] - mn1); rs1 += s[nt][2];
            s[nt][3] = ex2f(s[nt][3] - mn1); rs1 += s[nt][3];
        }
        rs0 += __shfl_xor_sync(0xffffffffu, rs0, 1);
        rs0 += __shfl_xor_sync(0xffffffffu, rs0, 2);
        rs1 += __shfl_xor_sync(0xffffffffu, rs1, 1);
        rs1 += __shfl_xor_sync(0xffffffffu, rs1, 2);
        l0r = l0r * cr0 + rs0;
        l1r = l1r * cr1 + rs1;
#pragma unroll
        for (int nt = 0; nt < 8; nt++) {
            o[nt][0] *= cr0; o[nt][1] *= cr0;
            o[nt][2] *= cr1; o[nt][3] *= cr1;
        }

        // ---- O += P @ V ----
        const uint32_t vrow = (uint32_t)(lane & 15) * (FP * 2);
#pragma unroll
        for (int j = 0; j < 4; j++) {
            const int na = 2 * j, nb = 2 * j + 1;
            uint32_t aph[4], apl[4];
            aph[0] = pack_bf2(s[na][0], s[na][1]);
            aph[1] = pack_bf2(s[na][2], s[na][3]);
            aph[2] = pack_bf2(s[nb][0], s[nb][1]);
            aph[3] = pack_bf2(s[nb][2], s[nb][3]);
            {
                float2 f;
                f = __bfloat1622float2(*(__nv_bfloat162*)&aph[0]);
                apl[0] = pack_bf2(s[na][0] - f.x, s[na][1] - f.y);
                f = __bfloat1622float2(*(__nv_bfloat162*)&aph[1]);
                apl[1] = pack_bf2(s[na][2] - f.x, s[na][3] - f.y);
                f = __bfloat1622float2(*(__nv_bfloat162*)&aph[2]);
                apl[2] = pack_bf2(s[nb][0] - f.x, s[nb][1] - f.y);
                f = __bfloat1622float2(*(__nv_bfloat162*)&aph[3]);
                apl[3] = pack_bf2(s[nb][2] - f.x, s[nb][3] - f.y);
            }
            const uint32_t jadr = svh + j * 16 * (FP * 2) + vrow;
#pragma unroll
            for (int ntv = 0; ntv < 8; ntv++) {
                uint32_t bh[2], bl[2];
                ldmx2t(bh[0], bh[1], jadr + ntv * 16);
                ldmx2t(bl[0], bl[1], jadr + ntv * 16 + KTIL);
                mma16816(o[ntv], aph, bh);
                mma16816(o[ntv], apl, bh);
                mma16816(o[ntv], aph, bl);
            }
        }
        __syncthreads();
    }

    float inv0 = 1.0f / l0r, inv1 = 1.0f / l1r;
    float* or0 = out + (size_t)(b * SQL + q0 + wr + g) * HH + h * DHD;
    float* or1 = or0 + 8 * HH;
#pragma unroll
    for (int ntv = 0; ntv < 8; ntv++) {
        int cc = ntv * 8 + 2 * tig;
        float2 w0 = make_float2(o[ntv][0] * inv0, o[ntv][1] * inv0);
        float2 w1 = make_float2(o[ntv][2] * inv1, o[ntv][3] * inv1);
        *(float2*)(or0 + cc) = w0;
        *(float2*)(or1 + cc) = w1;
    }
}

// ---------------------------------------------------------------------------
extern "C" void kernel_launch(void* const* d_in, const int* in_sizes, int n_in,
                              void* d_out, int out_size)
{
    const float* hidden  = (const float*)d_in[0];
    const float* context = (const float*)d_in[1];
    const int*   mask    = (const int*)d_in[2];
    const float* Wq      = (const float*)d_in[3];
    const float* bq      = (const float*)d_in[4];
    const float* Wk      = (const float*)d_in[5];
    const float* bk      = (const float*)d_in[6];
    const float* Wv      = (const float*)d_in[7];
    const float* bv      = (const float*)d_in[8];
    const float* pos     = (const float*)d_in[9];
    float* out = (float*)d_out;

    float* P2;
    cudaGetSymbolAddress((void**)&P2, g_P2);
    __nv_bfloat16 *qh, *ql, *kh, *kl, *vh, *vl;
    cudaGetSymbolAddress((void**)&qh, g_qh);
    cudaGetSymbolAddress((void**)&ql, g_ql);
    cudaGetSymbolAddress((void**)&kh, g_kh);
    cudaGetSymbolAddress((void**)&kl, g_kl);
    cudaGetSymbolAddress((void**)&vh, g_vh);
    cudaGetSymbolAddress((void**)&vl, g_vl);
    __nv_bfloat16 *hh, *hl, *ch, *cl, *wh, *wl;
    cudaGetSymbolAddress((void**)&hh, g_hid_hi);
    cudaGetSymbolAddress((void**)&hl, g_hid_lo);
    cudaGetSymbolAddress((void**)&ch, g_ctx_hi);
    cudaGetSymbolAddress((void**)&cl, g_ctx_lo);
    cudaGetSymbolAddress((void**)&wh, g_w_hi);
    cudaGetSymbolAddress((void**)&wl, g_w_lo);

    // fused conversion: 1 launch for all 5 arrays
    const int nA4 = MROWS * HH / 4;
    dim3 gcvt((nA4 + 255) / 256, 5);
    cvt_all<<<gcvt, 256>>>(hidden, context, Wq, Wk, Wv, hh, hl, ch, cl, wh, wl);

    // QKV projections (double-buffered)
    cudaFuncSetAttribute(qkv_hmma, cudaFuncAttributeMaxDynamicSharedMemorySize, 2 * QSTG);
    dim3 gproj(HH / 128, MROWS / 128, 3);
    qkv_hmma<<<gproj, 256, 2 * QSTG>>>(hh, hl, ch, cl, wh, wl, bq, bk, bv, pos,
                                       qh, ql, kh, kl, vh, vl);

    // P2 = (pos @ pos^T) * C2
    dim3 gpos(SKL / 64, SQL / 64);
    pos_gemm<<<gpos, 128>>>(pos, P2);

    // flash attention (double-buffered K/V)
    cudaFuncSetAttribute(flash_hmma, cudaFuncAttributeMaxDynamicSharedMemorySize, FSM);
    dim3 gattn(SQL / 128, NHD, BB);
    flash_hmma<<<gattn, 256, FSM>>>(qh, ql, kh, kl, vh, vl, P2, mask, out);
}

// round 6
// speedup vs baseline: 3.8302x; 1.0390x over previous
#include <cuda_runtime.h>
#include <cuda_bf16.h>
#include <cstdint>

#define BB  8
#define SQL 512
#define SKL 512
#define HH  768
#define NHD 12
#define DHD 64
#define MROWS (BB * SQL)   // 4096

#define C2 0.1803368801111244f   // 0.125 * log2(e)

// ---------------- scratch ----------------
__device__ float g_P2[SQL * SKL];
__device__ __nv_bfloat16 g_qh[MROWS * HH];
__device__ __nv_bfloat16 g_ql[MROWS * HH];
__device__ __nv_bfloat16 g_kh[MROWS * HH];
__device__ __nv_bfloat16 g_kl[MROWS * HH];
__device__ __nv_bfloat16 g_vh[MROWS * HH];
__device__ __nv_bfloat16 g_vl[MROWS * HH];
__device__ __nv_bfloat16 g_hid_hi[MROWS * HH];
__device__ __nv_bfloat16 g_hid_lo[MROWS * HH];
__device__ __nv_bfloat16 g_ctx_hi[MROWS * HH];
__device__ __nv_bfloat16 g_ctx_lo[MROWS * HH];
__device__ __nv_bfloat16 g_w_hi[3 * HH * HH];
__device__ __nv_bfloat16 g_w_lo[3 * HH * HH];

// ---------------- helpers ----------------
__device__ __forceinline__ float ex2f(float x) {
    float y;
    asm("ex2.approx.ftz.f32 %0, %1;" : "=f"(y) : "f"(x));
    return y;
}
__device__ __forceinline__ uint32_t smem_u32(const void* p) {
    uint32_t a;
    asm("{ .reg .u64 t; cvta.to.shared.u64 t, %1; cvt.u32.u64 %0, t; }" : "=r"(a) : "l"(p));
    return a;
}
__device__ __forceinline__ void cpa16(uint32_t dst, const void* src) {
    asm volatile("cp.async.cg.shared.global [%0], [%1], 16;" :: "r"(dst), "l"(src));
}
#define CPA_COMMIT() asm volatile("cp.async.commit_group;" ::: "memory")
#define CPA_WAIT(n)  asm volatile("cp.async.wait_group %0;" :: "n"(n) : "memory")

__device__ __forceinline__ void mma16816(float* d, const uint32_t* a, const uint32_t* b)
{
    asm volatile(
        "mma.sync.aligned.m16n8k16.row.col.f32.bf16.bf16.f32 "
        "{%0,%1,%2,%3}, {%4,%5,%6,%7}, {%8,%9}, {%0,%1,%2,%3};"
        : "+f"(d[0]), "+f"(d[1]), "+f"(d[2]), "+f"(d[3])
        : "r"(a[0]), "r"(a[1]), "r"(a[2]), "r"(a[3]), "r"(b[0]), "r"(b[1]));
}
__device__ __forceinline__ void ldmx4(uint32_t* r, uint32_t addr)
{
    asm volatile("ldmatrix.sync.aligned.m8n8.x4.shared.b16 {%0,%1,%2,%3}, [%4];"
                 : "=r"(r[0]), "=r"(r[1]), "=r"(r[2]), "=r"(r[3]) : "r"(addr));
}
__device__ __forceinline__ void ldmx4t(uint32_t* r, uint32_t addr)
{
    asm volatile("ldmatrix.sync.aligned.m8n8.x4.trans.shared.b16 {%0,%1,%2,%3}, [%4];"
                 : "=r"(r[0]), "=r"(r[1]), "=r"(r[2]), "=r"(r[3]) : "r"(addr));
}
__device__ __forceinline__ uint32_t pack_bf2(float a, float b) {
    __nv_bfloat162 h = __floats2bfloat162_rn(a, b);
    return *(uint32_t*)&h;
}

// ---------------------------------------------------------------------------
// Fused fp32 -> bf16 hi/lo split for all 5 arrays
// ---------------------------------------------------------------------------
__global__ void cvt_all(
    const float* __restrict__ hidden, const float* __restrict__ context,
    const float* __restrict__ Wq, const float* __restrict__ Wk, const float* __restrict__ Wv,
    __nv_bfloat16* __restrict__ hh, __nv_bfloat16* __restrict__ hl,
    __nv_bfloat16* __restrict__ ch, __nv_bfloat16* __restrict__ cl,
    __nv_bfloat16* __restrict__ wh, __nv_bfloat16* __restrict__ wl)
{
    const int y = blockIdx.y;
    const float* x;
    __nv_bfloat16 *hi, *lo;
    int n4;
    const int nA4 = MROWS * HH / 4, nW4 = HH * HH / 4;
    switch (y) {
        case 0: x = hidden;  hi = hh;               lo = hl;               n4 = nA4; break;
        case 1: x = context; hi = ch;               lo = cl;               n4 = nA4; break;
        case 2: x = Wq;      hi = wh;               lo = wl;               n4 = nW4; break;
        case 3: x = Wk;      hi = wh + HH * HH;     lo = wl + HH * HH;     n4 = nW4; break;
        default:x = Wv;      hi = wh + 2 * HH * HH; lo = wl + 2 * HH * HH; n4 = nW4; break;
    }
    int i = blockIdx.x * blockDim.x + threadIdx.x;
    if (i >= n4) return;
    float4 v = ((const float4*)x)[i];
    __nv_bfloat16 h0 = __float2bfloat16_rn(v.x);
    __nv_bfloat16 h1 = __float2bfloat16_rn(v.y);
    __nv_bfloat16 h2 = __float2bfloat16_rn(v.z);
    __nv_bfloat16 h3 = __float2bfloat16_rn(v.w);
    __nv_bfloat16 l0 = __float2bfloat16_rn(v.x - __bfloat162float(h0));
    __nv_bfloat16 l1 = __float2bfloat16_rn(v.y - __bfloat162float(h1));
    __nv_bfloat16 l2 = __float2bfloat16_rn(v.z - __bfloat162float(h2));
    __nv_bfloat16 l3 = __float2bfloat16_rn(v.w - __bfloat162float(h3));
    __nv_bfloat162 a, b;
    a.x = h0; a.y = h1; b.x = h2; b.y = h3;
    ((__nv_bfloat162*)hi)[2 * i] = a; ((__nv_bfloat162*)hi)[2 * i + 1] = b;
    a.x = l0; a.y = l1; b.x = l2; b.y = l3;
    ((__nv_bfloat162*)lo)[2 * i] = a; ((__nv_bfloat162*)lo)[2 * i + 1] = b;
}

// ---------------------------------------------------------------------------
// QKV projection via HMMA + ldmatrix, 3-term split, cp.async double-buffered.
// ---------------------------------------------------------------------------
#define TPAD 40
#define QSTG 40960
#define QTIL 10240

__global__ __launch_bounds__(256, 2) void qkv_hmma(
    const __nv_bfloat16* __restrict__ hid_hi, const __nv_bfloat16* __restrict__ hid_lo,
    const __nv_bfloat16* __restrict__ ctx_hi, const __nv_bfloat16* __restrict__ ctx_lo,
    const __nv_bfloat16* __restrict__ w_hi,   const __nv_bfloat16* __restrict__ w_lo,
    const float* __restrict__ bq, const float* __restrict__ bk, const float* __restrict__ bv,
    const float* __restrict__ pos,
    __nv_bfloat16* __restrict__ qh, __nv_bfloat16* __restrict__ ql,
    __nv_bfloat16* __restrict__ kh, __nv_bfloat16* __restrict__ kl,
    __nv_bfloat16* __restrict__ vh, __nv_bfloat16* __restrict__ vl)
{
    extern __shared__ char smc[];
    const uint32_t sb = smem_u32(smc);

    const int z = blockIdx.z;
    const __nv_bfloat16* Ahi = (z == 0) ? hid_hi : ctx_hi;
    const __nv_bfloat16* Alo = (z == 0) ? hid_lo : ctx_lo;
    const __nv_bfloat16* Bhi = w_hi + (size_t)z * HH * HH;
    const __nv_bfloat16* Blo = w_lo + (size_t)z * HH * HH;
    const float* bias = (z == 0) ? bq : ((z == 1) ? bk : bv);
    __nv_bfloat16* oh = (z == 0) ? qh : ((z == 1) ? kh : vh);
    __nv_bfloat16* ol = (z == 0) ? ql : ((z == 1) ? kl : vl);

    const int t    = threadIdx.x;
    const int lane = t & 31;
    const int wid  = t >> 5;
    const int wm   = wid & 3;
    const int wn   = wid >> 2;
    const int g    = lane >> 2;
    const int tig  = lane & 3;
    const int m0   = blockIdx.y << 7;
    const int n0   = blockIdx.x << 7;

    // ldmatrix per-thread byte offsets (within tile)
    const uint32_t a_off = ((wm * 32 + (lane & 15)) * TPAD + ((lane >> 4) << 3)) * 2;
    const uint32_t b_off = ((wn * 64 + (lane & 7) + ((lane & 16) ? 8 : 0)) * TPAD
                            + (((lane >> 3) & 1) << 3)) * 2;

    // cp.async load addressing (2 chunks/thread/tile)
    const int row0 = t >> 2,         cc0 = (t & 3) << 3;
    const int row1 = (t + 256) >> 2, cc1 = ((t + 256) & 3) << 3;
    const uint32_t so0 = row0 * 80 + cc0 * 2;
    const uint32_t so1 = row1 * 80 + cc1 * 2;

    float acc[2][8][4];
#pragma unroll
    for (int i = 0; i < 2; i++)
#pragma unroll
        for (int j = 0; j < 8; j++)
#pragma unroll
            for (int c = 0; c < 4; c++) acc[i][j][c] = 0.0f;

    auto issue = [&](int kt, int stg) {
        const int k0 = kt << 5;
        const uint32_t base = sb + stg * QSTG;
        size_t ga0 = (size_t)(m0 + row0) * HH + k0 + cc0;
        size_t ga1 = (size_t)(m0 + row1) * HH + k0 + cc1;
        size_t gb0 = (size_t)(n0 + row0) * HH + k0 + cc0;
        size_t gb1 = (size_t)(n0 + row1) * HH + k0 + cc1;
        cpa16(base + so0,            Ahi + ga0);
        cpa16(base + so1,            Ahi + ga1);
        cpa16(base + QTIL + so0,     Alo + ga0);
        cpa16(base + QTIL + so1,     Alo + ga1);
        cpa16(base + 2 * QTIL + so0, Bhi + gb0);
        cpa16(base + 2 * QTIL + so1, Bhi + gb1);
        cpa16(base + 3 * QTIL + so0, Blo + gb0);
        cpa16(base + 3 * QTIL + so1, Blo + gb1);
    };

    issue(0, 0);
    CPA_COMMIT();

    const int NT = HH / 32;   // 24
    for (int kt = 0; kt < NT; kt++) {
        if (kt + 1 < NT) {
            issue(kt + 1, (kt + 1) & 1);
            CPA_COMMIT();
            CPA_WAIT(1);
        } else {
            CPA_WAIT(0);
        }
        __syncthreads();

        const uint32_t stga = sb + (kt & 1) * QSTG;
        const uint32_t pAhi = stga + a_off;
        const uint32_t pAlo = stga + QTIL + a_off;
        const uint32_t pBhi = stga + 2 * QTIL + b_off;
        const uint32_t pBlo = stga + 3 * QTIL + b_off;

#pragma unroll
        for (int kk = 0; kk < 2; kk++) {
            const uint32_t kb = kk * 32;   // 16 bf16 cols = 32 bytes
            uint32_t bh[8][2];
#pragma unroll
            for (int np = 0; np < 4; np++) {
                uint32_t r[4];
                ldmx4(r, pBhi + np * (16 * TPAD * 2) + kb);
                bh[2 * np][0] = r[0]; bh[2 * np][1] = r[1];
                bh[2 * np + 1][0] = r[2]; bh[2 * np + 1][1] = r[3];
            }
            uint32_t af[2][4];
            ldmx4(af[0], pAhi + kb);
            ldmx4(af[1], pAhi + 16 * TPAD * 2 + kb);
#pragma unroll
            for (int mt = 0; mt < 2; mt++)
#pragma unroll
                for (int nt = 0; nt < 8; nt++)
                    mma16816(acc[mt][nt], af[mt], bh[nt]);

            uint32_t al[2][4];
            ldmx4(al[0], pAlo + kb);
            ldmx4(al[1], pAlo + 16 * TPAD * 2 + kb);
#pragma unroll
            for (int mt = 0; mt < 2; mt++)
#pragma unroll
                for (int nt = 0; nt < 8; nt++)
                    mma16816(acc[mt][nt], al[mt], bh[nt]);

#pragma unroll
            for (int np = 0; np < 4; np++) {
                uint32_t r[4];
                ldmx4(r, pBlo + np * (16 * TPAD * 2) + kb);
                bh[2 * np][0] = r[0]; bh[2 * np][1] = r[1];
                bh[2 * np + 1][0] = r[2]; bh[2 * np + 1][1] = r[3];
            }
#pragma unroll
            for (int mt = 0; mt < 2; mt++)
#pragma unroll
                for (int nt = 0; nt < 8; nt++)
                    mma16816(acc[mt][nt], af[mt], bh[nt]);
        }
        __syncthreads();
    }

    // epilogue
#pragma unroll
    for (int mt = 0; mt < 2; mt++) {
#pragma unroll
        for (int nt = 0; nt < 8; nt++) {
            int m = m0 + wm * 32 + mt * 16 + g;
            int n = n0 + wn * 64 + nt * 8 + 2 * tig;
            float b0 = bias[n], b1 = bias[n + 1];
#pragma unroll
            for (int half = 0; half < 2; half++) {
                int mm = m + half * 8;
                float f0 = acc[mt][nt][2 * half]     + b0;
                float f1 = acc[mt][nt][2 * half + 1] + b1;
                if (z == 1) {
                    f0 += pos[(mm & (SKL - 1)) * DHD + (n & (DHD - 1))];
                    f1 += pos[(mm & (SKL - 1)) * DHD + ((n + 1) & (DHD - 1))];
                }
                __nv_bfloat162 hh2 = __floats2bfloat162_rn(f0, f1);
                float2 hf = __bfloat1622float2(hh2);
                __nv_bfloat162 ll2 = __floats2bfloat162_rn(f0 - hf.x, f1 - hf.y);
                *(uint32_t*)(oh + (size_t)mm * HH + n) = *(uint32_t*)&hh2;
                *(uint32_t*)(ol + (size_t)mm * HH + n) = *(uint32_t*)&ll2;
            }
        }
    }
}

// ---------------------------------------------------------------------------
// P2 = (pos @ pos^T) * C2  — 64x64 tiles, 64 CTAs
// ---------------------------------------------------------------------------
__global__ __launch_bounds__(128) void pos_gemm(
    const float* __restrict__ A, float* __restrict__ out)
{
    __shared__ float As[64][68];
    __shared__ float Bs[64][68];

    const int t  = threadIdx.x;
    const int m0 = blockIdx.y << 6;
    const int n0 = blockIdx.x << 6;
    const int tm = (t >> 3) << 2;
    const int tn = (t & 7) << 3;

#pragma unroll
    for (int i = 0; i < 8; i++) {
        int idx = t + (i << 7);
        int row = idx >> 4;
        int c4  = (idx & 15) << 2;
        float4 va = *(const float4*)(A + (size_t)(m0 + row) * DHD + c4);
        As[c4 + 0][row] = va.x; As[c4 + 1][row] = va.y;
        As[c4 + 2][row] = va.z; As[c4 + 3][row] = va.w;
        float4 vb = *(const float4*)(A + (size_t)(n0 + row) * DHD + c4);
        Bs[c4 + 0][row] = vb.x; Bs[c4 + 1][row] = vb.y;
        Bs[c4 + 2][row] = vb.z; Bs[c4 + 3][row] = vb.w;
    }
    __syncthreads();

    float acc[4][8];
#pragma unroll
    for (int i = 0; i < 4; i++)
#pragma unroll
        for (int j = 0; j < 8; j++) acc[i][j] = 0.0f;

#pragma unroll 8
    for (int kk = 0; kk < 64; kk++) {
        float a[4], b[8];
        *(float4*)a = *(const float4*)&As[kk][tm];
        *(float4*)(b + 0) = *(const float4*)&Bs[kk][tn];
        *(float4*)(b + 4) = *(const float4*)&Bs[kk][tn + 4];
#pragma unroll
        for (int i = 0; i < 4; i++)
#pragma unroll
            for (int j = 0; j < 8; j++)
                acc[i][j] += a[i] * b[j];
    }

#pragma unroll
    for (int i = 0; i < 4; i++)
#pragma unroll
        for (int j = 0; j < 8; j++)
            out[(size_t)(m0 + tm + i) * SKL + n0 + tn + j] = acc[i][j] * C2;
}

// ---------------------------------------------------------------------------
// Flash attention on HMMA + ldmatrix, cp.async double-buffered K/V.
// ---------------------------------------------------------------------------
#define FP   72
#define OKV  36864
#define KSTG 36864
#define KTIL 9216
#define OMB  (36864 + 2 * 36864)
#define FSM  (OMB + 2048)

__global__ __launch_bounds__(256, 2) void flash_hmma(
    const __nv_bfloat16* __restrict__ qh, const __nv_bfloat16* __restrict__ ql,
    const __nv_bfloat16* __restrict__ kh, const __nv_bfloat16* __restrict__ kl,
    const __nv_bfloat16* __restrict__ vh, const __nv_bfloat16* __restrict__ vl,
    const float* __restrict__ P2, const int* __restrict__ mask,
    float* __restrict__ out)
{
    extern __shared__ char smc[];
    __nv_bfloat16* sQh = (__nv_bfloat16*)(smc);
    __nv_bfloat16* sQl = (__nv_bfloat16*)(smc + 18432);
    float*         smb = (float*)(smc + OMB);
    const uint32_t sb  = smem_u32(smc);

    const int t    = threadIdx.x;
    const int lane = t & 31;
    const int w    = t >> 5;
    const int g    = lane >> 2;
    const int tig  = lane & 3;
    const int wr   = w << 4;
    const int b    = blockIdx.z;
    const int h    = blockIdx.y;
    const int q0   = blockIdx.x << 7;

    // ldmatrix per-thread byte offsets
    const uint32_t q_off = ((wr + (lane & 15)) * FP + ((lane >> 4) << 3)) * 2;
    const uint32_t k_off = (((lane & 7) + ((lane & 16) ? 8 : 0)) * FP
                            + (((lane >> 3) & 1) << 3)) * 2;
    const uint32_t v_off = ((lane & 15) * FP + ((lane >> 4) << 3)) * 2;

    // cp.async K/V addressing
    const int krow0 = t >> 3,         kc0 = (t & 7) << 3;
    const int krow1 = (t + 256) >> 3, kc1 = ((t + 256) & 7) << 3;
    const uint32_t ko0 = krow0 * 144 + kc0 * 2;
    const uint32_t ko1 = krow1 * 144 + kc1 * 2;

    auto issue_kv = [&](int kt, int stg) {
        const uint32_t base = sb + OKV + stg * KSTG;
        size_t g0 = (size_t)(b * SKL + kt * 64 + krow0) * HH + h * DHD + kc0;
        size_t g1 = (size_t)(b * SKL + kt * 64 + krow1) * HH + h * DHD + kc1;
        cpa16(base + ko0,            kh + g0);
        cpa16(base + ko1,            kh + g1);
        cpa16(base + KTIL + ko0,     kl + g0);
        cpa16(base + KTIL + ko1,     kl + g1);
        cpa16(base + 2 * KTIL + ko0, vh + g0);
        cpa16(base + 2 * KTIL + ko1, vh + g1);
        cpa16(base + 3 * KTIL + ko0, vl + g0);
        cpa16(base + 3 * KTIL + ko1, vl + g1);
    };

    issue_kv(0, 0);
    CPA_COMMIT();

#pragma unroll
    for (int i = 0; i < 4; i++) {
        int idx = t + (i << 8);
        int row = idx >> 3;
        int c   = (idx & 7) << 3;
        size_t gsrc = (size_t)(b * SQL + q0 + row) * HH + h * DHD + c;
        *(uint4*)(sQh + row * FP + c) = *(const uint4*)(qh + gsrc);
        *(uint4*)(sQl + row * FP + c) = *(const uint4*)(ql + gsrc);
    }
    {
        int i0 = t, i1 = t + 256;
        smb[i0] = (mask[b * SKL + i0] == 0) ? -1e30f : 0.0f;
        smb[i1] = (mask[b * SKL + i1] == 0) ? -1e30f : 0.0f;
    }

    float o[8][4];
#pragma unroll
    for (int i = 0; i < 8; i++)
#pragma unroll
        for (int c = 0; c < 4; c++) o[i][c] = 0.0f;
    float m0r = -1e30f, m1r = -1e30f, l0r = 0.0f, l1r = 0.0f;

    const int NT = SKL / 64;   // 8
    for (int kt = 0; kt < NT; kt++) {
        if (kt + 1 < NT) {
            issue_kv(kt + 1, (kt + 1) & 1);
            CPA_COMMIT();
            CPA_WAIT(1);
        } else {
            CPA_WAIT(0);
        }
        __syncthreads();

        const int stg = kt & 1;
        const uint32_t kvb = sb + OKV + stg * KSTG;
        const uint32_t pKh = kvb + k_off;
        const uint32_t pKl = kvb + KTIL + k_off;
        const uint32_t pVh = kvb + 2 * KTIL + v_off;
        const uint32_t pVl = kvb + 3 * KTIL + v_off;

        // ---- S = Q K'^T ----
        float s[8][4];
#pragma unroll
        for (int nt = 0; nt < 8; nt++)
#pragma unroll
            for (int c = 0; c < 4; c++) s[nt][c] = 0.0f;

#pragma unroll
        for (int kk = 0; kk < 4; kk++) {
            const uint32_t kb = kk * 32;
            uint32_t ah[4], al[4];
            ldmx4(ah, sb + q_off + kb);
            ldmx4(al, sb + 18432 + q_off + kb);
#pragma unroll
            for (int np = 0; np < 4; np++) {
                uint32_t bh4[4], bl4[4];
                ldmx4(bh4, pKh + np * (16 * FP * 2) + kb);
                ldmx4(bl4, pKl + np * (16 * FP * 2) + kb);
                mma16816(s[2 * np],     ah, bh4 + 0);
                mma16816(s[2 * np],     al, bh4 + 0);
                mma16816(s[2 * np],     ah, bl4 + 0);
                mma16816(s[2 * np + 1], ah, bh4 + 2);
                mma16816(s[2 * np + 1], al, bh4 + 2);
                mma16816(s[2 * np + 1], ah, bl4 + 2);
            }
        }

        // ---- bias + mask + online softmax ----
        const float* pg0 = P2 + (size_t)(q0 + wr + g) * SKL + kt * 64;
        const float* pg1 = pg0 + 8 * SKL;
        const float* mrow = smb + kt * 64;
        float vm0 = -1e30f, vm1 = -1e30f;
#pragma unroll
        for (int nt = 0; nt < 8; nt++) {
            int cc = nt * 8 + 2 * tig;
            float2 p0 = *(const float2*)(pg0 + cc);
            float2 p1 = *(const float2*)(pg1 + cc);
            float mb0 = mrow[cc], mb1 = mrow[cc + 1];
            s[nt][0] = fmaf(s[nt][0], C2, p0.x) + mb0;
            s[nt][1] = fmaf(s[nt][1], C2, p0.y) + mb1;
            s[nt][2] = fmaf(s[nt][2], C2, p1.x) + mb0;
            s[nt][3] = fmaf(s[nt][3], C2, p1.y) + mb1;
            vm0 = fmaxf(vm0, fmaxf(s[nt][0], s[nt][1]));
            vm1 = fmaxf(vm1, fmaxf(s[nt][2], s[nt][3]));
        }
        vm0 = fmaxf(vm0, __shfl_xor_sync(0xffffffffu, vm0, 1));
        vm0 = fmaxf(vm0, __shfl_xor_sync(0xffffffffu, vm0, 2));
        vm1 = fmaxf(vm1, __shfl_xor_sync(0xffffffffu, vm1, 1));
        vm1 = fmaxf(vm1, __shfl_xor_sync(0xffffffffu, vm1, 2));
        float mn0 = fmaxf(m0r, vm0), mn1 = fmaxf(m1r, vm1);
        float cr0 = ex2f(m0r - mn0), cr1 = ex2f(m1r - mn1);
        m0r = mn0; m1r = mn1;

        float rs0 = 0.0f, rs1 = 0.0f;
#pragma unroll
        for (int nt = 0; nt < 8; nt++) {
            s[nt][0] = ex2f(s[nt][0] - mn0); rs0 += s[nt][0];
            s[nt][1] = ex2f(s[nt][1] - mn0); rs0 += s[nt][1];
            s[nt][2] = ex2f(s[nt][2] - mn1); rs1 += s[nt][2];
            s[nt][3] = ex2f(s[nt][3] - mn1); rs1 += s[nt][3];
        }
        rs0 += __shfl_xor_sync(0xffffffffu, rs0, 1);
        rs0 += __shfl_xor_sync(0xffffffffu, rs0, 2);
        rs1 += __shfl_xor_sync(0xffffffffu, rs1, 1);
        rs1 += __shfl_xor_sync(0xffffffffu, rs1, 2);
        l0r = l0r * cr0 + rs0;
        l1r = l1r * cr1 + rs1;
#pragma unroll
        for (int nt = 0; nt < 8; nt++) {
            o[nt][0] *= cr0; o[nt][1] *= cr0;
            o[nt][2] *= cr1; o[nt][3] *= cr1;
        }

        // ---- O += P @ V ----
#pragma unroll
        for (int j = 0; j < 4; j++) {
            const int na = 2 * j, nb = 2 * j + 1;
            uint32_t aph[4], apl[4];
            aph[0] = pack_bf2(s[na][0], s[na][1]);
            aph[1] = pack_bf2(s[na][2], s[na][3]);
            aph[2] = pack_bf2(s[nb][0], s[nb][1]);
            aph[3] = pack_bf2(s[nb][2], s[nb][3]);
            {
                float2 f;
                f = __bfloat1622float2(*(__nv_bfloat162*)&aph[0]);
                apl[0] = pack_bf2(s[na][0] - f.x, s[na][1] - f.y);
                f = __bfloat1622float2(*(__nv_bfloat162*)&aph[1]);
                apl[1] = pack_bf2(s[na][2] - f.x, s[na][3] - f.y);
                f = __bfloat1622float2(*(__nv_bfloat162*)&aph[2]);
                apl[2] = pack_bf2(s[nb][0] - f.x, s[nb][1] - f.y);
                f = __bfloat1622float2(*(__nv_bfloat162*)&aph[3]);
                apl[3] = pack_bf2(s[nb][2] - f.x, s[nb][3] - f.y);
            }
            const uint32_t jh = pVh + j * (16 * FP * 2);
            const uint32_t jl = pVl + j * (16 * FP * 2);
#pragma unroll
            for (int vp = 0; vp < 4; vp++) {
                uint32_t bh4[4], bl4[4];
                ldmx4t(bh4, jh + vp * 32);
                ldmx4t(bl4, jl + vp * 32);
                mma16816(o[2 * vp],     aph, bh4 + 0);
                mma16816(o[2 * vp],     apl, bh4 + 0);
                mma16816(o[2 * vp],     aph, bl4 + 0);
                mma16816(o[2 * vp + 1], aph, bh4 + 2);
                mma16816(o[2 * vp + 1], apl, bh4 + 2);
                mma16816(o[2 * vp + 1], aph, bl4 + 2);
            }
        }
        __syncthreads();
    }

    float inv0 = 1.0f / l0r, inv1 = 1.0f / l1r;
    float* or0 = out + (size_t)(b * SQL + q0 + wr + g) * HH + h * DHD;
    float* or1 = or0 + 8 * HH;
#pragma unroll
    for (int ntv = 0; ntv < 8; ntv++) {
        int cc = ntv * 8 + 2 * tig;
        float2 w0 = make_float2(o[ntv][0] * inv0, o[ntv][1] * inv0);
        float2 w1 = make_float2(o[ntv][2] * inv1, o[ntv][3] * inv1);
        *(float2*)(or0 + cc) = w0;
        *(float2*)(or1 + cc) = w1;
    }
}

// ---------------------------------------------------------------------------
extern "C" void kernel_launch(void* const* d_in, const int* in_sizes, int n_in,
                              void* d_out, int out_size)
{
    const float* hidden  = (const float*)d_in[0];
    const float* context = (const float*)d_in[1];
    const int*   mask    = (const int*)d_in[2];
    const float* Wq      = (const float*)d_in[3];
    const float* bq      = (const float*)d_in[4];
    const float* Wk      = (const float*)d_in[5];
    const float* bk      = (const float*)d_in[6];
    const float* Wv      = (const float*)d_in[7];
    const float* bv      = (const float*)d_in[8];
    const float* pos     = (const float*)d_in[9];
    float* out = (float*)d_out;

    float* P2;
    cudaGetSymbolAddress((void**)&P2, g_P2);
    __nv_bfloat16 *qh, *ql, *kh, *kl, *vh, *vl;
    cudaGetSymbolAddress((void**)&qh, g_qh);
    cudaGetSymbolAddress((void**)&ql, g_ql);
    cudaGetSymbolAddress((void**)&kh, g_kh);
    cudaGetSymbolAddress((void**)&kl, g_kl);
    cudaGetSymbolAddress((void**)&vh, g_vh);
    cudaGetSymbolAddress((void**)&vl, g_vl);
    __nv_bfloat16 *hh, *hl, *ch, *cl, *wh, *wl;
    cudaGetSymbolAddress((void**)&hh, g_hid_hi);
    cudaGetSymbolAddress((void**)&hl, g_hid_lo);
    cudaGetSymbolAddress((void**)&ch, g_ctx_hi);
    cudaGetSymbolAddress((void**)&cl, g_ctx_lo);
    cudaGetSymbolAddress((void**)&wh, g_w_hi);
    cudaGetSymbolAddress((void**)&wl, g_w_lo);

    const int nA4 = MROWS * HH / 4;
    dim3 gcvt((nA4 + 255) / 256, 5);
    cvt_all<<<gcvt, 256>>>(hidden, context, Wq, Wk, Wv, hh, hl, ch, cl, wh, wl);

    cudaFuncSetAttribute(qkv_hmma, cudaFuncAttributeMaxDynamicSharedMemorySize, 2 * QSTG);
    dim3 gproj(HH / 128, MROWS / 128, 3);
    qkv_hmma<<<gproj, 256, 2 * QSTG>>>(hh, hl, ch, cl, wh, wl, bq, bk, bv, pos,
                                       qh, ql, kh, kl, vh, vl);

    dim3 gpos(SKL / 64, SQL / 64);
    pos_gemm<<<gpos, 128>>>(pos, P2);

    cudaFuncSetAttribute(flash_hmma, cudaFuncAttributeMaxDynamicSharedMemorySize, FSM);
    dim3 gattn(SQL / 128, NHD, BB);
    flash_hmma<<<gattn, 256, FSM>>>(qh, ql, kh, kl, vh, vl, P2, mask, out);
}

// round 7
// speedup vs baseline: 5.0933x; 1.3298x over previous
#include <cuda_runtime.h>
#include <cuda_fp16.h>
#include <cstdint>

#define BB  8
#define SQL 512
#define SKL 512
#define HH  768
#define NHD 12
#define DHD 64
#define MROWS (BB * SQL)   // 4096

#define C2 0.1803368801111244f   // 0.125 * log2(e)

// ---------------- scratch ----------------
__device__ float g_P2[SQL * SKL];
__device__ __half g_qh[MROWS * HH];
__device__ __half g_ql[MROWS * HH];
__device__ __half g_kh[MROWS * HH];   // k' = k + pos, single fp16
__device__ __half g_vh[MROWS * HH];   // v, single fp16
__device__ __half g_hid_hi[MROWS * HH];
__device__ __half g_hid_lo[MROWS * HH];
__device__ __half g_ctx_hi[MROWS * HH];
__device__ __half g_ctx_lo[MROWS * HH];
__device__ __half g_w[3 * HH * HH];   // weights, single fp16

// ---------------- helpers ----------------
__device__ __forceinline__ float ex2f(float x) {
    float y;
    asm("ex2.approx.ftz.f32 %0, %1;" : "=f"(y) : "f"(x));
    return y;
}
__device__ __forceinline__ uint32_t smem_u32(const void* p) {
    uint32_t a;
    asm("{ .reg .u64 t; cvta.to.shared.u64 t, %1; cvt.u32.u64 %0, t; }" : "=r"(a) : "l"(p));
    return a;
}
__device__ __forceinline__ void cpa16(uint32_t dst, const void* src) {
    asm volatile("cp.async.cg.shared.global [%0], [%1], 16;" :: "r"(dst), "l"(src));
}
#define CPA_COMMIT() asm volatile("cp.async.commit_group;" ::: "memory")
#define CPA_WAIT(n)  asm volatile("cp.async.wait_group %0;" :: "n"(n) : "memory")

__device__ __forceinline__ void mma16816(float* d, const uint32_t* a, const uint32_t* b)
{
    asm volatile(
        "mma.sync.aligned.m16n8k16.row.col.f32.f16.f16.f32 "
        "{%0,%1,%2,%3}, {%4,%5,%6,%7}, {%8,%9}, {%0,%1,%2,%3};"
        : "+f"(d[0]), "+f"(d[1]), "+f"(d[2]), "+f"(d[3])
        : "r"(a[0]), "r"(a[1]), "r"(a[2]), "r"(a[3]), "r"(b[0]), "r"(b[1]));
}
__device__ __forceinline__ void ldmx4(uint32_t* r, uint32_t addr)
{
    asm volatile("ldmatrix.sync.aligned.m8n8.x4.shared.b16 {%0,%1,%2,%3}, [%4];"
                 : "=r"(r[0]), "=r"(r[1]), "=r"(r[2]), "=r"(r[3]) : "r"(addr));
}
__device__ __forceinline__ void ldmx4t(uint32_t* r, uint32_t addr)
{
    asm volatile("ldmatrix.sync.aligned.m8n8.x4.trans.shared.b16 {%0,%1,%2,%3}, [%4];"
                 : "=r"(r[0]), "=r"(r[1]), "=r"(r[2]), "=r"(r[3]) : "r"(addr));
}
__device__ __forceinline__ uint32_t pack_hf2(float a, float b) {
    __half2 h = __floats2half2_rn(a, b);
    return *(uint32_t*)&h;
}

// ---------------------------------------------------------------------------
// fp32 -> fp16 conversions: activations hi/lo split, weights single.
// ---------------------------------------------------------------------------
__global__ void cvt_all(
    const float* __restrict__ hidden, const float* __restrict__ context,
    const float* __restrict__ Wq, const float* __restrict__ Wk, const float* __restrict__ Wv,
    __half* __restrict__ hh, __half* __restrict__ hl,
    __half* __restrict__ ch, __half* __restrict__ cl,
    __half* __restrict__ w)
{
    const int y = blockIdx.y;
    const float* x;
    __half *hi, *lo;
    int n4;
    const int nA4 = MROWS * HH / 4, nW4 = HH * HH / 4;
    switch (y) {
        case 0: x = hidden;  hi = hh;              lo = hl;      n4 = nA4; break;
        case 1: x = context; hi = ch;              lo = cl;      n4 = nA4; break;
        case 2: x = Wq;      hi = w;               lo = nullptr; n4 = nW4; break;
        case 3: x = Wk;      hi = w + HH * HH;     lo = nullptr; n4 = nW4; break;
        default:x = Wv;      hi = w + 2 * HH * HH; lo = nullptr; n4 = nW4; break;
    }
    int i = blockIdx.x * blockDim.x + threadIdx.x;
    if (i >= n4) return;
    float4 v = ((const float4*)x)[i];
    __half h0 = __float2half_rn(v.x);
    __half h1 = __float2half_rn(v.y);
    __half h2 = __float2half_rn(v.z);
    __half h3 = __float2half_rn(v.w);
    __half2 a, b;
    a.x = h0; a.y = h1; b.x = h2; b.y = h3;
    ((__half2*)hi)[2 * i] = a; ((__half2*)hi)[2 * i + 1] = b;
    if (lo) {
        __half l0 = __float2half_rn(v.x - __half2float(h0));
        __half l1 = __float2half_rn(v.y - __half2float(h1));
        __half l2 = __float2half_rn(v.z - __half2float(h2));
        __half l3 = __float2half_rn(v.w - __half2float(h3));
        a.x = l0; a.y = l1; b.x = l2; b.y = l3;
        ((__half2*)lo)[2 * i] = a; ((__half2*)lo)[2 * i + 1] = b;
    }
}

// ---------------------------------------------------------------------------
// QKV projection: A split (hi/lo fp16) x W single fp16, 2-term HMMA.
// CTA 128x128, BK=32, 256 threads, double-buffered cp.async.
// ---------------------------------------------------------------------------
#define TPAD 40
#define QTIL 10240
#define QSTG 30720          // Ahi, Alo, B

__global__ __launch_bounds__(256, 2) void qkv_hmma(
    const __half* __restrict__ hid_hi, const __half* __restrict__ hid_lo,
    const __half* __restrict__ ctx_hi, const __half* __restrict__ ctx_lo,
    const __half* __restrict__ w,
    const float* __restrict__ bq, const float* __restrict__ bk, const float* __restrict__ bv,
    const float* __restrict__ pos,
    __half* __restrict__ qh, __half* __restrict__ ql,
    __half* __restrict__ kh, __half* __restrict__ vh)
{
    extern __shared__ char smc[];
    const uint32_t sb = smem_u32(smc);

    const int z = blockIdx.z;
    const __half* Ahi = (z == 0) ? hid_hi : ctx_hi;
    const __half* Alo = (z == 0) ? hid_lo : ctx_lo;
    const __half* B   = w + (size_t)z * HH * HH;
    const float* bias = (z == 0) ? bq : ((z == 1) ? bk : bv);

    const int t    = threadIdx.x;
    const int lane = t & 31;
    const int wid  = t >> 5;
    const int wm   = wid & 3;
    const int wn   = wid >> 2;
    const int g    = lane >> 2;
    const int tig  = lane & 3;
    const int m0   = blockIdx.y << 7;
    const int n0   = blockIdx.x << 7;

    const uint32_t a_off = ((wm * 32 + (lane & 15)) * TPAD + ((lane >> 4) << 3)) * 2;
    const uint32_t b_off = ((wn * 64 + (lane & 7) + ((lane & 16) ? 8 : 0)) * TPAD
                            + (((lane >> 3) & 1) << 3)) * 2;

    const int row0 = t >> 2,         cc0 = (t & 3) << 3;
    const int row1 = (t + 256) >> 2, cc1 = ((t + 256) & 3) << 3;
    const uint32_t so0 = row0 * 80 + cc0 * 2;
    const uint32_t so1 = row1 * 80 + cc1 * 2;

    float acc[2][8][4];
#pragma unroll
    for (int i = 0; i < 2; i++)
#pragma unroll
        for (int j = 0; j < 8; j++)
#pragma unroll
            for (int c = 0; c < 4; c++) acc[i][j][c] = 0.0f;

    auto issue = [&](int kt, int stg) {
        const int k0 = kt << 5;
        const uint32_t base = sb + stg * QSTG;
        size_t ga0 = (size_t)(m0 + row0) * HH + k0 + cc0;
        size_t ga1 = (size_t)(m0 + row1) * HH + k0 + cc1;
        size_t gb0 = (size_t)(n0 + row0) * HH + k0 + cc0;
        size_t gb1 = (size_t)(n0 + row1) * HH + k0 + cc1;
        cpa16(base + so0,            Ahi + ga0);
        cpa16(base + so1,            Ahi + ga1);
        cpa16(base + QTIL + so0,     Alo + ga0);
        cpa16(base + QTIL + so1,     Alo + ga1);
        cpa16(base + 2 * QTIL + so0, B + gb0);
        cpa16(base + 2 * QTIL + so1, B + gb1);
    };

    issue(0, 0);
    CPA_COMMIT();

    const int NT = HH / 32;   // 24
    for (int kt = 0; kt < NT; kt++) {
        if (kt + 1 < NT) {
            issue(kt + 1, (kt + 1) & 1);
            CPA_COMMIT();
            CPA_WAIT(1);
        } else {
            CPA_WAIT(0);
        }
        __syncthreads();

        const uint32_t stga = sb + (kt & 1) * QSTG;
        const uint32_t pAhi = stga + a_off;
        const uint32_t pAlo = stga + QTIL + a_off;
        const uint32_t pB   = stga + 2 * QTIL + b_off;

#pragma unroll
        for (int kk = 0; kk < 2; kk++) {
            const uint32_t kb = kk * 32;
            uint32_t bfr[8][2];
#pragma unroll
            for (int np = 0; np < 4; np++) {
                uint32_t r[4];
                ldmx4(r, pB + np * (16 * TPAD * 2) + kb);
                bfr[2 * np][0] = r[0];     bfr[2 * np][1] = r[1];
                bfr[2 * np + 1][0] = r[2]; bfr[2 * np + 1][1] = r[3];
            }
            uint32_t af[2][4];
            ldmx4(af[0], pAhi + kb);
            ldmx4(af[1], pAhi + 16 * TPAD * 2 + kb);
#pragma unroll
            for (int mt = 0; mt < 2; mt++)
#pragma unroll
                for (int nt = 0; nt < 8; nt++)
                    mma16816(acc[mt][nt], af[mt], bfr[nt]);

            uint32_t al[2][4];
            ldmx4(al[0], pAlo + kb);
            ldmx4(al[1], pAlo + 16 * TPAD * 2 + kb);
#pragma unroll
            for (int mt = 0; mt < 2; mt++)
#pragma unroll
                for (int nt = 0; nt < 8; nt++)
                    mma16816(acc[mt][nt], al[mt], bfr[nt]);
        }
        __syncthreads();
    }

    // epilogue
#pragma unroll
    for (int mt = 0; mt < 2; mt++) {
#pragma unroll
        for (int nt = 0; nt < 8; nt++) {
            int m = m0 + wm * 32 + mt * 16 + g;
            int n = n0 + wn * 64 + nt * 8 + 2 * tig;
            float b0 = bias[n], b1 = bias[n + 1];
#pragma unroll
            for (int half = 0; half < 2; half++) {
                int mm = m + half * 8;
                float f0 = acc[mt][nt][2 * half]     + b0;
                float f1 = acc[mt][nt][2 * half + 1] + b1;
                if (z == 0) {
                    // Q: split hi/lo fp16
                    uint32_t hi = pack_hf2(f0, f1);
                    float2 hf = __half22float2(*(__half2*)&hi);
                    uint32_t lo = pack_hf2(f0 - hf.x, f1 - hf.y);
                    *(uint32_t*)(qh + (size_t)mm * HH + n) = hi;
                    *(uint32_t*)(ql + (size_t)mm * HH + n) = lo;
                } else if (z == 1) {
                    // K' = k + pos, single fp16
                    f0 += pos[(mm & (SKL - 1)) * DHD + (n & (DHD - 1))];
                    f1 += pos[(mm & (SKL - 1)) * DHD + ((n + 1) & (DHD - 1))];
                    *(uint32_t*)(kh + (size_t)mm * HH + n) = pack_hf2(f0, f1);
                } else {
                    *(uint32_t*)(vh + (size_t)mm * HH + n) = pack_hf2(f0, f1);
                }
            }
        }
    }
}

// ---------------------------------------------------------------------------
// P2 = (pos @ pos^T) * C2  — 64x64 tiles, 64 CTAs
// ---------------------------------------------------------------------------
__global__ __launch_bounds__(128) void pos_gemm(
    const float* __restrict__ A, float* __restrict__ out)
{
    __shared__ float As[64][68];
    __shared__ float Bs[64][68];

    const int t  = threadIdx.x;
    const int m0 = blockIdx.y << 6;
    const int n0 = blockIdx.x << 6;
    const int tm = (t >> 3) << 2;
    const int tn = (t & 7) << 3;

#pragma unroll
    for (int i = 0; i < 8; i++) {
        int idx = t + (i << 7);
        int row = idx >> 4;
        int c4  = (idx & 15) << 2;
        float4 va = *(const float4*)(A + (size_t)(m0 + row) * DHD + c4);
        As[c4 + 0][row] = va.x; As[c4 + 1][row] = va.y;
        As[c4 + 2][row] = va.z; As[c4 + 3][row] = va.w;
        float4 vb = *(const float4*)(A + (size_t)(n0 + row) * DHD + c4);
        Bs[c4 + 0][row] = vb.x; Bs[c4 + 1][row] = vb.y;
        Bs[c4 + 2][row] = vb.z; Bs[c4 + 3][row] = vb.w;
    }
    __syncthreads();

    float acc[4][8];
#pragma unroll
    for (int i = 0; i < 4; i++)
#pragma unroll
        for (int j = 0; j < 8; j++) acc[i][j] = 0.0f;

#pragma unroll 8
    for (int kk = 0; kk < 64; kk++) {
        float a[4], b[8];
        *(float4*)a = *(const float4*)&As[kk][tm];
        *(float4*)(b + 0) = *(const float4*)&Bs[kk][tn];
        *(float4*)(b + 4) = *(const float4*)&Bs[kk][tn + 4];
#pragma unroll
        for (int i = 0; i < 4; i++)
#pragma unroll
            for (int j = 0; j < 8; j++)
                acc[i][j] += a[i] * b[j];
    }

#pragma unroll
    for (int i = 0; i < 4; i++)
#pragma unroll
        for (int j = 0; j < 8; j++)
            out[(size_t)(m0 + tm + i) * SKL + n0 + tn + j] = acc[i][j] * C2;
}

// ---------------------------------------------------------------------------
// Flash attention: Q split fp16 x K' single; P split fp16 x V single.
// smem: Qhi 18432 | Qlo 18432 | KV 2 stages x 18432 (K 9216 + V 9216) | mask
// ---------------------------------------------------------------------------
#define FP   72
#define OKV  36864
#define KSTG 18432
#define KTIL 9216
#define OMB  (OKV + 2 * KSTG)   // 73728
#define FSM  (OMB + 2048)

__global__ __launch_bounds__(256, 2) void flash_hmma(
    const __half* __restrict__ qh, const __half* __restrict__ ql,
    const __half* __restrict__ kh, const __half* __restrict__ vh,
    const float* __restrict__ P2, const int* __restrict__ mask,
    float* __restrict__ out)
{
    extern __shared__ char smc[];
    __half* sQh = (__half*)(smc);
    __half* sQl = (__half*)(smc + 18432);
    float*  smb = (float*)(smc + OMB);
    const uint32_t sb = smem_u32(smc);

    const int t    = threadIdx.x;
    const int lane = t & 31;
    const int w    = t >> 5;
    const int g    = lane >> 2;
    const int tig  = lane & 3;
    const int wr   = w << 4;
    const int b    = blockIdx.z;
    const int h    = blockIdx.y;
    const int q0   = blockIdx.x << 7;

    const uint32_t q_off = ((wr + (lane & 15)) * FP + ((lane >> 4) << 3)) * 2;
    const uint32_t k_off = (((lane & 7) + ((lane & 16) ? 8 : 0)) * FP
                            + (((lane >> 3) & 1) << 3)) * 2;
    const uint32_t v_off = ((lane & 15) * FP + ((lane >> 4) << 3)) * 2;

    const int krow0 = t >> 3,         kc0 = (t & 7) << 3;
    const int krow1 = (t + 256) >> 3, kc1 = ((t + 256) & 7) << 3;
    const uint32_t ko0 = krow0 * 144 + kc0 * 2;
    const uint32_t ko1 = krow1 * 144 + kc1 * 2;

    auto issue_kv = [&](int kt, int stg) {
        const uint32_t base = sb + OKV + stg * KSTG;
        size_t g0 = (size_t)(b * SKL + kt * 64 + krow0) * HH + h * DHD + kc0;
        size_t g1 = (size_t)(b * SKL + kt * 64 + krow1) * HH + h * DHD + kc1;
        cpa16(base + ko0,        kh + g0);
        cpa16(base + ko1,        kh + g1);
        cpa16(base + KTIL + ko0, vh + g0);
        cpa16(base + KTIL + ko1, vh + g1);
    };

    issue_kv(0, 0);
    CPA_COMMIT();

#pragma unroll
    for (int i = 0; i < 4; i++) {
        int idx = t + (i << 8);
        int row = idx >> 3;
        int c   = (idx & 7) << 3;
        size_t gsrc = (size_t)(b * SQL + q0 + row) * HH + h * DHD + c;
        *(uint4*)(sQh + row * FP + c) = *(const uint4*)(qh + gsrc);
        *(uint4*)(sQl + row * FP + c) = *(const uint4*)(ql + gsrc);
    }
    {
        int i0 = t, i1 = t + 256;
        smb[i0] = (mask[b * SKL + i0] == 0) ? -1e30f : 0.0f;
        smb[i1] = (mask[b * SKL + i1] == 0) ? -1e30f : 0.0f;
    }

    float o[8][4];
#pragma unroll
    for (int i = 0; i < 8; i++)
#pragma unroll
        for (int c = 0; c < 4; c++) o[i][c] = 0.0f;
    float m0r = -1e30f, m1r = -1e30f, l0r = 0.0f, l1r = 0.0f;

    const int NT = SKL / 64;   // 8
    for (int kt = 0; kt < NT; kt++) {
        if (kt + 1 < NT) {
            issue_kv(kt + 1, (kt + 1) & 1);
            CPA_COMMIT();
            CPA_WAIT(1);
        } else {
            CPA_WAIT(0);
        }
        __syncthreads();

        const int stg = kt & 1;
        const uint32_t kvb = sb + OKV + stg * KSTG;
        const uint32_t pK = kvb + k_off;
        const uint32_t pV = kvb + KTIL + v_off;

        // ---- S = Q K'^T (2-term) ----
        float s[8][4];
#pragma unroll
        for (int nt = 0; nt < 8; nt++)
#pragma unroll
            for (int c = 0; c < 4; c++) s[nt][c] = 0.0f;

#pragma unroll
        for (int kk = 0; kk < 4; kk++) {
            const uint32_t kb = kk * 32;
            uint32_t ah[4], al[4];
            ldmx4(ah, sb + q_off + kb);
            ldmx4(al, sb + 18432 + q_off + kb);
#pragma unroll
            for (int np = 0; np < 4; np++) {
                uint32_t bh4[4];
                ldmx4(bh4, pK + np * (16 * FP * 2) + kb);
                mma16816(s[2 * np],     ah, bh4 + 0);
                mma16816(s[2 * np],     al, bh4 + 0);
                mma16816(s[2 * np + 1], ah, bh4 + 2);
                mma16816(s[2 * np + 1], al, bh4 + 2);
            }
        }

        // ---- bias + mask + online softmax ----
        const float* pg0 = P2 + (size_t)(q0 + wr + g) * SKL + kt * 64;
        const float* pg1 = pg0 + 8 * SKL;
        const float* mrow = smb + kt * 64;
        float vm0 = -1e30f, vm1 = -1e30f;
#pragma unroll
        for (int nt = 0; nt < 8; nt++) {
            int cc = nt * 8 + 2 * tig;
            float2 p0 = *(const float2*)(pg0 + cc);
            float2 p1 = *(const float2*)(pg1 + cc);
            float mb0 = mrow[cc], mb1 = mrow[cc + 1];
            s[nt][0] = fmaf(s[nt][0], C2, p0.x) + mb0;
            s[nt][1] = fmaf(s[nt][1], C2, p0.y) + mb1;
            s[nt][2] = fmaf(s[nt][2], C2, p1.x) + mb0;
            s[nt][3] = fmaf(s[nt][3], C2, p1.y) + mb1;
            vm0 = fmaxf(vm0, fmaxf(s[nt][0], s[nt][1]));
            vm1 = fmaxf(vm1, fmaxf(s[nt][2], s[nt][3]));
        }
        vm0 = fmaxf(vm0, __shfl_xor_sync(0xffffffffu, vm0, 1));
        vm0 = fmaxf(vm0, __shfl_xor_sync(0xffffffffu, vm0, 2));
        vm1 = fmaxf(vm1, __shfl_xor_sync(0xffffffffu, vm1, 1));
        vm1 = fmaxf(vm1, __shfl_xor_sync(0xffffffffu, vm1, 2));
        float mn0 = fmaxf(m0r, vm0), mn1 = fmaxf(m1r, vm1);
        float cr0 = ex2f(m0r - mn0), cr1 = ex2f(m1r - mn1);
        m0r = mn0; m1r = mn1;

        float rs0 = 0.0f, rs1 = 0.0f;
#pragma unroll
        for (int nt = 0; nt < 8; nt++) {
            s[nt][0] = ex2f(s[nt][0] - mn0); rs0 += s[nt][0];
            s[nt][1] = ex2f(s[nt][1] - mn0); rs0 += s[nt][1];
            s[nt][2] = ex2f(s[nt][2] - mn1); rs1 += s[nt][2];
            s[nt][3] = ex2f(s[nt][3] - mn1); rs1 += s[nt][3];
        }
        rs0 += __shfl_xor_sync(0xffffffffu, rs0, 1);
        rs0 += __shfl_xor_sync(0xffffffffu, rs0, 2);
        rs1 += __shfl_xor_sync(0xffffffffu, rs1, 1);
        rs1 += __shfl_xor_sync(0xffffffffu, rs1, 2);
        l0r = l0r * cr0 + rs0;
        l1r = l1r * cr1 + rs1;
#pragma unroll
        for (int nt = 0; nt < 8; nt++) {
            o[nt][0] *= cr0; o[nt][1] *= cr0;
            o[nt][2] *= cr1; o[nt][3] *= cr1;
        }

        // ---- O += P @ V (2-term: P split, V single) ----
#pragma unroll
        for (int j = 0; j < 4; j++) {
            const int na = 2 * j, nb = 2 * j + 1;
            uint32_t aph[4], apl[4];
            aph[0] = pack_hf2(s[na][0], s[na][1]);
            aph[1] = pack_hf2(s[na][2], s[na][3]);
            aph[2] = pack_hf2(s[nb][0], s[nb][1]);
            aph[3] = pack_hf2(s[nb][2], s[nb][3]);
            {
                float2 f;
                f = __half22float2(*(__half2*)&aph[0]);
                apl[0] = pack_hf2(s[na][0] - f.x, s[na][1] - f.y);
                f = __half22float2(*(__half2*)&aph[1]);
                apl[1] = pack_hf2(s[na][2] - f.x, s[na][3] - f.y);
                f = __half22float2(*(__half2*)&aph[2]);
                apl[2] = pack_hf2(s[nb][0] - f.x, s[nb][1] - f.y);
                f = __half22float2(*(__half2*)&aph[3]);
                apl[3] = pack_hf2(s[nb][2] - f.x, s[nb][3] - f.y);
            }
            const uint32_t jv = pV + j * (16 * FP * 2);
#pragma unroll
            for (int vp = 0; vp < 4; vp++) {
                uint32_t bv4[4];
                ldmx4t(bv4, jv + vp * 32);
                mma16816(o[2 * vp],     aph, bv4 + 0);
                mma16816(o[2 * vp],     apl, bv4 + 0);
                mma16816(o[2 * vp + 1], aph, bv4 + 2);
                mma16816(o[2 * vp + 1], apl, bv4 + 2);
            }
        }
        __syncthreads();
    }

    float inv0 = 1.0f / l0r, inv1 = 1.0f / l1r;
    float* or0 = out + (size_t)(b * SQL + q0 + wr + g) * HH + h * DHD;
    float* or1 = or0 + 8 * HH;
#pragma unroll
    for (int ntv = 0; ntv < 8; ntv++) {
        int cc = ntv * 8 + 2 * tig;
        float2 w0 = make_float2(o[ntv][0] * inv0, o[ntv][1] * inv0);
        float2 w1 = make_float2(o[ntv][2] * inv1, o[ntv][3] * inv1);
        *(float2*)(or0 + cc) = w0;
        *(float2*)(or1 + cc) = w1;
    }
}

// ---------------------------------------------------------------------------
extern "C" void kernel_launch(void* const* d_in, const int* in_sizes, int n_in,
                              void* d_out, int out_size)
{
    const float* hidden  = (const float*)d_in[0];
    const float* context = (const float*)d_in[1];
    const int*   mask    = (const int*)d_in[2];
    const float* Wq      = (const float*)d_in[3];
    const float* bq      = (const float*)d_in[4];
    const float* Wk      = (const float*)d_in[5];
    const float* bk      = (const float*)d_in[6];
    const float* Wv      = (const float*)d_in[7];
    const float* bv      = (const float*)d_in[8];
    const float* pos     = (const float*)d_in[9];
    float* out = (float*)d_out;

    float* P2;
    cudaGetSymbolAddress((void**)&P2, g_P2);
    __half *qh, *ql, *kh, *vh;
    cudaGetSymbolAddress((void**)&qh, g_qh);
    cudaGetSymbolAddress((void**)&ql, g_ql);
    cudaGetSymbolAddress((void**)&kh, g_kh);
    cudaGetSymbolAddress((void**)&vh, g_vh);
    __half *hh, *hl, *ch, *cl, *w;
    cudaGetSymbolAddress((void**)&hh, g_hid_hi);
    cudaGetSymbolAddress((void**)&hl, g_hid_lo);
    cudaGetSymbolAddress((void**)&ch, g_ctx_hi);
    cudaGetSymbolAddress((void**)&cl, g_ctx_lo);
    cudaGetSymbolAddress((void**)&w,  g_w);

    const int nA4 = MROWS * HH / 4;
    dim3 gcvt((nA4 + 255) / 256, 5);
    cvt_all<<<gcvt, 256>>>(hidden, context, Wq, Wk, Wv, hh, hl, ch, cl, w);

    cudaFuncSetAttribute(qkv_hmma, cudaFuncAttributeMaxDynamicSharedMemorySize, 2 * QSTG);
    dim3 gproj(HH / 128, MROWS / 128, 3);
    qkv_hmma<<<gproj, 256, 2 * QSTG>>>(hh, hl, ch, cl, w, bq, bk, bv, pos,
                                       qh, ql, kh, vh);

    dim3 gpos(SKL / 64, SQL / 64);
    pos_gemm<<<gpos, 128>>>(pos, P2);

    cudaFuncSetAttribute(flash_hmma, cudaFuncAttributeMaxDynamicSharedMemorySize, FSM);
    dim3 gattn(SQL / 128, NHD, BB);
    flash_hmma<<<gattn, 256, FSM>>>(qh, ql, kh, vh, P2, mask, out);
}

// round 8
// speedup vs baseline: 5.5045x; 1.0807x over previous
#include <cuda_runtime.h>
#include <cuda_fp16.h>
#include <cstdint>

#define BB  8
#define SQL 512
#define SKL 512
#define HH  768
#define NHD 12
#define DHD 64
#define MROWS (BB * SQL)   // 4096

#define C2 0.1803368801111244f   // 0.125 * log2(e)

// ---------------- scratch ----------------
__device__ float g_P2[SQL * SKL];
__device__ __half g_qh[MROWS * HH];   // q, single fp16
__device__ __half g_kh[MROWS * HH];   // k' = k + pos, single fp16
__device__ __half g_vh[MROWS * HH];   // v, single fp16
__device__ __half g_hid_hi[MROWS * HH];
__device__ __half g_hid_lo[MROWS * HH];
__device__ __half g_ctx_hi[MROWS * HH];
__device__ __half g_ctx_lo[MROWS * HH];
__device__ __half g_w[3 * HH * HH];   // weights, single fp16

// ---------------- helpers ----------------
__device__ __forceinline__ float ex2f(float x) {
    float y;
    asm("ex2.approx.ftz.f32 %0, %1;" : "=f"(y) : "f"(x));
    return y;
}
__device__ __forceinline__ uint32_t smem_u32(const void* p) {
    uint32_t a;
    asm("{ .reg .u64 t; cvta.to.shared.u64 t, %1; cvt.u32.u64 %0, t; }" : "=r"(a) : "l"(p));
    return a;
}
__device__ __forceinline__ void cpa16(uint32_t dst, const void* src) {
    asm volatile("cp.async.cg.shared.global [%0], [%1], 16;" :: "r"(dst), "l"(src));
}
#define CPA_COMMIT() asm volatile("cp.async.commit_group;" ::: "memory")
#define CPA_WAIT(n)  asm volatile("cp.async.wait_group %0;" :: "n"(n) : "memory")

__device__ __forceinline__ void mma16816(float* d, const uint32_t* a, const uint32_t* b)
{
    asm volatile(
        "mma.sync.aligned.m16n8k16.row.col.f32.f16.f16.f32 "
        "{%0,%1,%2,%3}, {%4,%5,%6,%7}, {%8,%9}, {%0,%1,%2,%3};"
        : "+f"(d[0]), "+f"(d[1]), "+f"(d[2]), "+f"(d[3])
        : "r"(a[0]), "r"(a[1]), "r"(a[2]), "r"(a[3]), "r"(b[0]), "r"(b[1]));
}
__device__ __forceinline__ void ldmx4(uint32_t* r, uint32_t addr)
{
    asm volatile("ldmatrix.sync.aligned.m8n8.x4.shared.b16 {%0,%1,%2,%3}, [%4];"
                 : "=r"(r[0]), "=r"(r[1]), "=r"(r[2]), "=r"(r[3]) : "r"(addr));
}
__device__ __forceinline__ void ldmx4t(uint32_t* r, uint32_t addr)
{
    asm volatile("ldmatrix.sync.aligned.m8n8.x4.trans.shared.b16 {%0,%1,%2,%3}, [%4];"
                 : "=r"(r[0]), "=r"(r[1]), "=r"(r[2]), "=r"(r[3]) : "r"(addr));
}
__device__ __forceinline__ uint32_t pack_hf2(float a, float b) {
    __half2 h = __floats2half2_rn(a, b);
    return *(uint32_t*)&h;
}

// ---------------------------------------------------------------------------
// fp32 -> fp16 conversions: activations hi/lo split, weights single.
// ---------------------------------------------------------------------------
__global__ void cvt_all(
    const float* __restrict__ hidden, const float* __restrict__ context,
    const float* __restrict__ Wq, const float* __restrict__ Wk, const float* __restrict__ Wv,
    __half* __restrict__ hh, __half* __restrict__ hl,
    __half* __restrict__ ch, __half* __restrict__ cl,
    __half* __restrict__ w)
{
    const int y = blockIdx.y;
    const float* x;
    __half *hi, *lo;
    int n4;
    const int nA4 = MROWS * HH / 4, nW4 = HH * HH / 4;
    switch (y) {
        case 0: x = hidden;  hi = hh;              lo = hl;      n4 = nA4; break;
        case 1: x = context; hi = ch;              lo = cl;      n4 = nA4; break;
        case 2: x = Wq;      hi = w;               lo = nullptr; n4 = nW4; break;
        case 3: x = Wk;      hi = w + HH * HH;     lo = nullptr; n4 = nW4; break;
        default:x = Wv;      hi = w + 2 * HH * HH; lo = nullptr; n4 = nW4; break;
    }
    int i = blockIdx.x * blockDim.x + threadIdx.x;
    if (i >= n4) return;
    float4 v = ((const float4*)x)[i];
    __half h0 = __float2half_rn(v.x);
    __half h1 = __float2half_rn(v.y);
    __half h2 = __float2half_rn(v.z);
    __half h3 = __float2half_rn(v.w);
    __half2 a, b;
    a.x = h0; a.y = h1; b.x = h2; b.y = h3;
    ((__half2*)hi)[2 * i] = a; ((__half2*)hi)[2 * i + 1] = b;
    if (lo) {
        __half l0 = __float2half_rn(v.x - __half2float(h0));
        __half l1 = __float2half_rn(v.y - __half2float(h1));
        __half l2 = __float2half_rn(v.z - __half2float(h2));
        __half l3 = __float2half_rn(v.w - __half2float(h3));
        a.x = l0; a.y = l1; b.x = l2; b.y = l3;
        ((__half2*)lo)[2 * i] = a; ((__half2*)lo)[2 * i + 1] = b;
    }
}

// ---------------------------------------------------------------------------
// QKV projection: A split (hi/lo fp16) x W single fp16, 2-term HMMA.
// Outputs single fp16 (q, k'=k+pos, v).
// ---------------------------------------------------------------------------
#define TPAD 40
#define QTIL 10240
#define QSTG 30720          // Ahi, Alo, B

__global__ __launch_bounds__(256, 2) void qkv_hmma(
    const __half* __restrict__ hid_hi, const __half* __restrict__ hid_lo,
    const __half* __restrict__ ctx_hi, const __half* __restrict__ ctx_lo,
    const __half* __restrict__ w,
    const float* __restrict__ bq, const float* __restrict__ bk, const float* __restrict__ bv,
    const float* __restrict__ pos,
    __half* __restrict__ qh, __half* __restrict__ kh, __half* __restrict__ vh)
{
    extern __shared__ char smc[];
    const uint32_t sb = smem_u32(smc);

    const int z = blockIdx.z;
    const __half* Ahi = (z == 0) ? hid_hi : ctx_hi;
    const __half* Alo = (z == 0) ? hid_lo : ctx_lo;
    const __half* B   = w + (size_t)z * HH * HH;
    const float* bias = (z == 0) ? bq : ((z == 1) ? bk : bv);
    __half* outp = (z == 0) ? qh : ((z == 1) ? kh : vh);

    const int t    = threadIdx.x;
    const int lane = t & 31;
    const int wid  = t >> 5;
    const int wm   = wid & 3;
    const int wn   = wid >> 2;
    const int g    = lane >> 2;
    const int tig  = lane & 3;
    const int m0   = blockIdx.y << 7;
    const int n0   = blockIdx.x << 7;

    const uint32_t a_off = ((wm * 32 + (lane & 15)) * TPAD + ((lane >> 4) << 3)) * 2;
    const uint32_t b_off = ((wn * 64 + (lane & 7) + ((lane & 16) ? 8 : 0)) * TPAD
                            + (((lane >> 3) & 1) << 3)) * 2;

    const int row0 = t >> 2,         cc0 = (t & 3) << 3;
    const int row1 = (t + 256) >> 2, cc1 = ((t + 256) & 3) << 3;
    const uint32_t so0 = row0 * 80 + cc0 * 2;
    const uint32_t so1 = row1 * 80 + cc1 * 2;

    float acc[2][8][4];
#pragma unroll
    for (int i = 0; i < 2; i++)
#pragma unroll
        for (int j = 0; j < 8; j++)
#pragma unroll
            for (int c = 0; c < 4; c++) acc[i][j][c] = 0.0f;

    auto issue = [&](int kt, int stg) {
        const int k0 = kt << 5;
        const uint32_t base = sb + stg * QSTG;
        size_t ga0 = (size_t)(m0 + row0) * HH + k0 + cc0;
        size_t ga1 = (size_t)(m0 + row1) * HH + k0 + cc1;
        size_t gb0 = (size_t)(n0 + row0) * HH + k0 + cc0;
        size_t gb1 = (size_t)(n0 + row1) * HH + k0 + cc1;
        cpa16(base + so0,            Ahi + ga0);
        cpa16(base + so1,            Ahi + ga1);
        cpa16(base + QTIL + so0,     Alo + ga0);
        cpa16(base + QTIL + so1,     Alo + ga1);
        cpa16(base + 2 * QTIL + so0, B + gb0);
        cpa16(base + 2 * QTIL + so1, B + gb1);
    };

    issue(0, 0);
    CPA_COMMIT();

    const int NT = HH / 32;   // 24
    for (int kt = 0; kt < NT; kt++) {
        if (kt + 1 < NT) {
            issue(kt + 1, (kt + 1) & 1);
            CPA_COMMIT();
            CPA_WAIT(1);
        } else {
            CPA_WAIT(0);
        }
        __syncthreads();

        const uint32_t stga = sb + (kt & 1) * QSTG;
        const uint32_t pAhi = stga + a_off;
        const uint32_t pAlo = stga + QTIL + a_off;
        const uint32_t pB   = stga + 2 * QTIL + b_off;

#pragma unroll
        for (int kk = 0; kk < 2; kk++) {
            const uint32_t kb = kk * 32;
            uint32_t bfr[8][2];
#pragma unroll
            for (int np = 0; np < 4; np++) {
                uint32_t r[4];
                ldmx4(r, pB + np * (16 * TPAD * 2) + kb);
                bfr[2 * np][0] = r[0];     bfr[2 * np][1] = r[1];
                bfr[2 * np + 1][0] = r[2]; bfr[2 * np + 1][1] = r[3];
            }
            uint32_t af[2][4];
            ldmx4(af[0], pAhi + kb);
            ldmx4(af[1], pAhi + 16 * TPAD * 2 + kb);
#pragma unroll
            for (int mt = 0; mt < 2; mt++)
#pragma unroll
                for (int nt = 0; nt < 8; nt++)
                    mma16816(acc[mt][nt], af[mt], bfr[nt]);

            uint32_t al[2][4];
            ldmx4(al[0], pAlo + kb);
            ldmx4(al[1], pAlo + 16 * TPAD * 2 + kb);
#pragma unroll
            for (int mt = 0; mt < 2; mt++)
#pragma unroll
                for (int nt = 0; nt < 8; nt++)
                    mma16816(acc[mt][nt], al[mt], bfr[nt]);
        }
        __syncthreads();
    }

    // epilogue: +bias (+pos for K), single fp16 store
#pragma unroll
    for (int mt = 0; mt < 2; mt++) {
#pragma unroll
        for (int nt = 0; nt < 8; nt++) {
            int m = m0 + wm * 32 + mt * 16 + g;
            int n = n0 + wn * 64 + nt * 8 + 2 * tig;
            float b0 = bias[n], b1 = bias[n + 1];
#pragma unroll
            for (int half = 0; half < 2; half++) {
                int mm = m + half * 8;
                float f0 = acc[mt][nt][2 * half]     + b0;
                float f1 = acc[mt][nt][2 * half + 1] + b1;
                if (z == 1) {
                    f0 += pos[(mm & (SKL - 1)) * DHD + (n & (DHD - 1))];
                    f1 += pos[(mm & (SKL - 1)) * DHD + ((n + 1) & (DHD - 1))];
                }
                *(uint32_t*)(outp + (size_t)mm * HH + n) = pack_hf2(f0, f1);
            }
        }
    }
}

// ---------------------------------------------------------------------------
// P2 = (pos @ pos^T) * C2  — 64x64 tiles, 64 CTAs
// ---------------------------------------------------------------------------
__global__ __launch_bounds__(128) void pos_gemm(
    const float* __restrict__ A, float* __restrict__ out)
{
    __shared__ float As[64][68];
    __shared__ float Bs[64][68];

    const int t  = threadIdx.x;
    const int m0 = blockIdx.y << 6;
    const int n0 = blockIdx.x << 6;
    const int tm = (t >> 3) << 2;
    const int tn = (t & 7) << 3;

#pragma unroll
    for (int i = 0; i < 8; i++) {
        int idx = t + (i << 7);
        int row = idx >> 4;
        int c4  = (idx & 15) << 2;
        float4 va = *(const float4*)(A + (size_t)(m0 + row) * DHD + c4);
        As[c4 + 0][row] = va.x; As[c4 + 1][row] = va.y;
        As[c4 + 2][row] = va.z; As[c4 + 3][row] = va.w;
        float4 vb = *(const float4*)(A + (size_t)(n0 + row) * DHD + c4);
        Bs[c4 + 0][row] = vb.x; Bs[c4 + 1][row] = vb.y;
        Bs[c4 + 2][row] = vb.z; Bs[c4 + 3][row] = vb.w;
    }
    __syncthreads();

    float acc[4][8];
#pragma unroll
    for (int i = 0; i < 4; i++)
#pragma unroll
        for (int j = 0; j < 8; j++) acc[i][j] = 0.0f;

#pragma unroll 8
    for (int kk = 0; kk < 64; kk++) {
        float a[4], b[8];
        *(float4*)a = *(const float4*)&As[kk][tm];
        *(float4*)(b + 0) = *(const float4*)&Bs[kk][tn];
        *(float4*)(b + 4) = *(const float4*)&Bs[kk][tn + 4];
#pragma unroll
        for (int i = 0; i < 4; i++)
#pragma unroll
            for (int j = 0; j < 8; j++)
                acc[i][j] += a[i] * b[j];
    }

#pragma unroll
    for (int i = 0; i < 4; i++)
#pragma unroll
        for (int j = 0; j < 8; j++)
            out[(size_t)(m0 + tm + i) * SKL + n0 + tn + j] = acc[i][j] * C2;
}

// ---------------------------------------------------------------------------
// Flash attention: pure 1-term fp16 (Q single x K' single; P single x V single).
// smem: Q 18432 | KV 2 stages x 18432 (K 9216 + V 9216) | mask 2048
// ---------------------------------------------------------------------------
#define FP   72
#define OKV  18432
#define KSTG 18432
#define KTIL 9216
#define OMB  (OKV + 2 * KSTG)   // 55296
#define FSM  (OMB + 2048)       // 57344

__global__ __launch_bounds__(256, 2) void flash_hmma(
    const __half* __restrict__ qh,
    const __half* __restrict__ kh, const __half* __restrict__ vh,
    const float* __restrict__ P2, const int* __restrict__ mask,
    float* __restrict__ out)
{
    extern __shared__ char smc[];
    __half* sQh = (__half*)(smc);
    float*  smb = (float*)(smc + OMB);
    const uint32_t sb = smem_u32(smc);

    const int t    = threadIdx.x;
    const int lane = t & 31;
    const int w    = t >> 5;
    const int g    = lane >> 2;
    const int tig  = lane & 3;
    const int wr   = w << 4;
    const int b    = blockIdx.z;
    const int h    = blockIdx.y;
    const int q0   = blockIdx.x << 7;

    const uint32_t q_off = ((wr + (lane & 15)) * FP + ((lane >> 4) << 3)) * 2;
    const uint32_t k_off = (((lane & 7) + ((lane & 16) ? 8 : 0)) * FP
                            + (((lane >> 3) & 1) << 3)) * 2;
    const uint32_t v_off = ((lane & 15) * FP + ((lane >> 4) << 3)) * 2;

    const int krow0 = t >> 3,         kc0 = (t & 7) << 3;
    const int krow1 = (t + 256) >> 3, kc1 = ((t + 256) & 7) << 3;
    const uint32_t ko0 = krow0 * 144 + kc0 * 2;
    const uint32_t ko1 = krow1 * 144 + kc1 * 2;

    auto issue_kv = [&](int kt, int stg) {
        const uint32_t base = sb + OKV + stg * KSTG;
        size_t g0 = (size_t)(b * SKL + kt * 64 + krow0) * HH + h * DHD + kc0;
        size_t g1 = (size_t)(b * SKL + kt * 64 + krow1) * HH + h * DHD + kc1;
        cpa16(base + ko0,        kh + g0);
        cpa16(base + ko1,        kh + g1);
        cpa16(base + KTIL + ko0, vh + g0);
        cpa16(base + KTIL + ko1, vh + g1);
    };

    issue_kv(0, 0);
    CPA_COMMIT();

#pragma unroll
    for (int i = 0; i < 2; i++) {
        int idx = t + (i << 8);           // 0..511: 128 rows x 64 cols / 8 per uint4
        int row = idx >> 2;
        int c   = (idx & 3) << 4;
        size_t gsrc = (size_t)(b * SQL + q0 + row) * HH + h * DHD + c;
        *(uint4*)(sQh + row * FP + c)     = *(const uint4*)(qh + gsrc);
        *(uint4*)(sQh + row * FP + c + 8) = *(const uint4*)(qh + gsrc + 8);
    }
    {
        int i0 = t, i1 = t + 256;
        smb[i0] = (mask[b * SKL + i0] == 0) ? -1e30f : 0.0f;
        smb[i1] = (mask[b * SKL + i1] == 0) ? -1e30f : 0.0f;
    }

    float o[8][4];
#pragma unroll
    for (int i = 0; i < 8; i++)
#pragma unroll
        for (int c = 0; c < 4; c++) o[i][c] = 0.0f;
    float m0r = -1e30f, m1r = -1e30f, l0r = 0.0f, l1r = 0.0f;

    const int NT = SKL / 64;   // 8
    for (int kt = 0; kt < NT; kt++) {
        if (kt + 1 < NT) {
            issue_kv(kt + 1, (kt + 1) & 1);
            CPA_COMMIT();
            CPA_WAIT(1);
        } else {
            CPA_WAIT(0);
        }
        __syncthreads();

        const int stg = kt & 1;
        const uint32_t kvb = sb + OKV + stg * KSTG;
        const uint32_t pK = kvb + k_off;
        const uint32_t pV = kvb + KTIL + v_off;

        // ---- S = Q K'^T (1-term) ----
        float s[8][4];
#pragma unroll
        for (int nt = 0; nt < 8; nt++)
#pragma unroll
            for (int c = 0; c < 4; c++) s[nt][c] = 0.0f;

#pragma unroll
        for (int kk = 0; kk < 4; kk++) {
            const uint32_t kb = kk * 32;
            uint32_t ah[4];
            ldmx4(ah, sb + q_off + kb);
#pragma unroll
            for (int np = 0; np < 4; np++) {
                uint32_t bh4[4];
                ldmx4(bh4, pK + np * (16 * FP * 2) + kb);
                mma16816(s[2 * np],     ah, bh4 + 0);
                mma16816(s[2 * np + 1], ah, bh4 + 2);
            }
        }

        // ---- bias + mask + online softmax ----
        const float* pg0 = P2 + (size_t)(q0 + wr + g) * SKL + kt * 64;
        const float* pg1 = pg0 + 8 * SKL;
        const float* mrow = smb + kt * 64;
        float vm0 = -1e30f, vm1 = -1e30f;
#pragma unroll
        for (int nt = 0; nt < 8; nt++) {
            int cc = nt * 8 + 2 * tig;
            float2 p0 = *(const float2*)(pg0 + cc);
            float2 p1 = *(const float2*)(pg1 + cc);
            float mb0 = mrow[cc], mb1 = mrow[cc + 1];
            s[nt][0] = fmaf(s[nt][0], C2, p0.x) + mb0;
            s[nt][1] = fmaf(s[nt][1], C2, p0.y) + mb1;
            s[nt][2] = fmaf(s[nt][2], C2, p1.x) + mb0;
            s[nt][3] = fmaf(s[nt][3], C2, p1.y) + mb1;
            vm0 = fmaxf(vm0, fmaxf(s[nt][0], s[nt][1]));
            vm1 = fmaxf(vm1, fmaxf(s[nt][2], s[nt][3]));
        }
        vm0 = fmaxf(vm0, __shfl_xor_sync(0xffffffffu, vm0, 1));
        vm0 = fmaxf(vm0, __shfl_xor_sync(0xffffffffu, vm0, 2));
        vm1 = fmaxf(vm1, __shfl_xor_sync(0xffffffffu, vm1, 1));
        vm1 = fmaxf(vm1, __shfl_xor_sync(0xffffffffu, vm1, 2));
        float mn0 = fmaxf(m0r, vm0), mn1 = fmaxf(m1r, vm1);
        float cr0 = ex2f(m0r - mn0), cr1 = ex2f(m1r - mn1);
        m0r = mn0; m1r = mn1;

        float rs0 = 0.0f, rs1 = 0.0f;
#pragma unroll
        for (int nt = 0; nt < 8; nt++) {
            s[nt][0] = ex2f(s[nt][0] - mn0); rs0 += s[nt][0];
            s[nt][1] = ex2f(s[nt][1] - mn0); rs0 += s[nt][1];
            s[nt][2] = ex2f(s[nt][2] - mn1); rs1 += s[nt][2];
            s[nt][3] = ex2f(s[nt][3] - mn1); rs1 += s[nt][3];
        }
        rs0 += __shfl_xor_sync(0xffffffffu, rs0, 1);
        rs0 += __shfl_xor_sync(0xffffffffu, rs0, 2);
        rs1 += __shfl_xor_sync(0xffffffffu, rs1, 1);
        rs1 += __shfl_xor_sync(0xffffffffu, rs1, 2);
        l0r = l0r * cr0 + rs0;
        l1r = l1r * cr1 + rs1;
#pragma unroll
        for (int nt = 0; nt < 8; nt++) {
            o[nt][0] *= cr0; o[nt][1] *= cr0;
            o[nt][2] *= cr1; o[nt][3] *= cr1;
        }

        // ---- O += P @ V (1-term: P single fp16) ----
#pragma unroll
        for (int j = 0; j < 4; j++) {
            const int na = 2 * j, nb = 2 * j + 1;
            uint32_t aph[4];
            aph[0] = pack_hf2(s[na][0], s[na][1]);
            aph[1] = pack_hf2(s[na][2], s[na][3]);
            aph[2] = pack_hf2(s[nb][0], s[nb][1]);
            aph[3] = pack_hf2(s[nb][2], s[nb][3]);
            const uint32_t jv = pV + j * (16 * FP * 2);
#pragma unroll
            for (int vp = 0; vp < 4; vp++) {
                uint32_t bv4[4];
                ldmx4t(bv4, jv + vp * 32);
                mma16816(o[2 * vp],     aph, bv4 + 0);
                mma16816(o[2 * vp + 1], aph, bv4 + 2);
            }
        }
        __syncthreads();
    }

    float inv0 = 1.0f / l0r, inv1 = 1.0f / l1r;
    float* or0 = out + (size_t)(b * SQL + q0 + wr + g) * HH + h * DHD;
    float* or1 = or0 + 8 * HH;
#pragma unroll
    for (int ntv = 0; ntv < 8; ntv++) {
        int cc = ntv * 8 + 2 * tig;
        float2 w0 = make_float2(o[ntv][0] * inv0, o[ntv][1] * inv0);
        float2 w1 = make_float2(o[ntv][2] * inv1, o[ntv][3] * inv1);
        *(float2*)(or0 + cc) = w0;
        *(float2*)(or1 + cc) = w1;
    }
}

// ---------------------------------------------------------------------------
extern "C" void kernel_launch(void* const* d_in, const int* in_sizes, int n_in,
                              void* d_out, int out_size)
{
    const float* hidden  = (const float*)d_in[0];
    const float* context = (const float*)d_in[1];
    const int*   mask    = (const int*)d_in[2];
    const float* Wq      = (const float*)d_in[3];
    const float* bq      = (const float*)d_in[4];
    const float* Wk      = (const float*)d_in[5];
    const float* bk      = (const float*)d_in[6];
    const float* Wv      = (const float*)d_in[7];
    const float* bv      = (const float*)d_in[8];
    const float* pos     = (const float*)d_in[9];
    float* out = (float*)d_out;

    float* P2;
    cudaGetSymbolAddress((void**)&P2, g_P2);
    __half *qh, *kh, *vh;
    cudaGetSymbolAddress((void**)&qh, g_qh);
    cudaGetSymbolAddress((void**)&kh, g_kh);
    cudaGetSymbolAddress((void**)&vh, g_vh);
    __half *hh, *hl, *ch, *cl, *w;
    cudaGetSymbolAddress((void**)&hh, g_hid_hi);
    cudaGetSymbolAddress((void**)&hl, g_hid_lo);
    cudaGetSymbolAddress((void**)&ch, g_ctx_hi);
    cudaGetSymbolAddress((void**)&cl, g_ctx_lo);
    cudaGetSymbolAddress((void**)&w,  g_w);

    const int nA4 = MROWS * HH / 4;
    dim3 gcvt((nA4 + 255) / 256, 5);
    cvt_all<<<gcvt, 256>>>(hidden, context, Wq, Wk, Wv, hh, hl, ch, cl, w);

    cudaFuncSetAttribute(qkv_hmma, cudaFuncAttributeMaxDynamicSharedMemorySize, 2 * QSTG);
    dim3 gproj(HH / 128, MROWS / 128, 3);
    qkv_hmma<<<gproj, 256, 2 * QSTG>>>(hh, hl, ch, cl, w, bq, bk, bv, pos,
                                       qh, kh, vh);

    dim3 gpos(SKL / 64, SQL / 64);
    pos_gemm<<<gpos, 128>>>(pos, P2);

    cudaFuncSetAttribute(flash_hmma, cudaFuncAttributeMaxDynamicSharedMemorySize, FSM);
    dim3 gattn(SQL / 128, NHD, BB);
    flash_hmma<<<gattn, 256, FSM>>>(qh, kh, vh, P2, mask, out);
}

// round 9
// speedup vs baseline: 7.2695x; 1.3207x over previous
#include <cuda_runtime.h>
#include <cuda_fp16.h>
#include <cstdint>

#define BB  8
#define SQL 512
#define SKL 512
#define HH  768
#define NHD 12
#define DHD 64
#define MROWS (BB * SQL)   // 4096

#define C2 0.1803368801111244f   // 0.125 * log2(e)

// ---------------- scratch ----------------
__device__ float g_P2[SQL * SKL];
__device__ __half g_qh[MROWS * HH];   // q
__device__ __half g_kh[MROWS * HH];   // k' = k + pos
__device__ __half g_vh[MROWS * HH];   // v
__device__ __half g_hid[MROWS * HH];
__device__ __half g_ctx[MROWS * HH];
__device__ __half g_w[3 * HH * HH];

// ---------------- helpers ----------------
__device__ __forceinline__ float ex2f(float x) {
    float y;
    asm("ex2.approx.ftz.f32 %0, %1;" : "=f"(y) : "f"(x));
    return y;
}
__device__ __forceinline__ uint32_t smem_u32(const void* p) {
    uint32_t a;
    asm("{ .reg .u64 t; cvta.to.shared.u64 t, %1; cvt.u32.u64 %0, t; }" : "=r"(a) : "l"(p));
    return a;
}
__device__ __forceinline__ void cpa16(uint32_t dst, const void* src) {
    asm volatile("cp.async.cg.shared.global [%0], [%1], 16;" :: "r"(dst), "l"(src));
}
#define CPA_COMMIT() asm volatile("cp.async.commit_group;" ::: "memory")
#define CPA_WAIT(n)  asm volatile("cp.async.wait_group %0;" :: "n"(n) : "memory")

__device__ __forceinline__ void mma16816(float* d, const uint32_t* a, const uint32_t* b)
{
    asm volatile(
        "mma.sync.aligned.m16n8k16.row.col.f32.f16.f16.f32 "
        "{%0,%1,%2,%3}, {%4,%5,%6,%7}, {%8,%9}, {%0,%1,%2,%3};"
        : "+f"(d[0]), "+f"(d[1]), "+f"(d[2]), "+f"(d[3])
        : "r"(a[0]), "r"(a[1]), "r"(a[2]), "r"(a[3]), "r"(b[0]), "r"(b[1]));
}
__device__ __forceinline__ void ldmx4(uint32_t* r, uint32_t addr)
{
    asm volatile("ldmatrix.sync.aligned.m8n8.x4.shared.b16 {%0,%1,%2,%3}, [%4];"
                 : "=r"(r[0]), "=r"(r[1]), "=r"(r[2]), "=r"(r[3]) : "r"(addr));
}
__device__ __forceinline__ void ldmx4t(uint32_t* r, uint32_t addr)
{
    asm volatile("ldmatrix.sync.aligned.m8n8.x4.trans.shared.b16 {%0,%1,%2,%3}, [%4];"
                 : "=r"(r[0]), "=r"(r[1]), "=r"(r[2]), "=r"(r[3]) : "r"(addr));
}
__device__ __forceinline__ uint32_t pack_hf2(float a, float b) {
    __half2 h = __floats2half2_rn(a, b);
    return *(uint32_t*)&h;
}

// ---------------------------------------------------------------------------
// fp32 -> fp16 conversion (single precision level now), 5 arrays fused.
// ---------------------------------------------------------------------------
__global__ void cvt_all(
    const float* __restrict__ hidden, const float* __restrict__ context,
    const float* __restrict__ Wq, const float* __restrict__ Wk, const float* __restrict__ Wv,
    __half* __restrict__ hh, __half* __restrict__ ch, __half* __restrict__ w)
{
    const int y = blockIdx.y;
    const float* x;
    __half* hi;
    int n4;
    const int nA4 = MROWS * HH / 4, nW4 = HH * HH / 4;
    switch (y) {
        case 0: x = hidden;  hi = hh;              n4 = nA4; break;
        case 1: x = context; hi = ch;              n4 = nA4; break;
        case 2: x = Wq;      hi = w;               n4 = nW4; break;
        case 3: x = Wk;      hi = w + HH * HH;     n4 = nW4; break;
        default:x = Wv;      hi = w + 2 * HH * HH; n4 = nW4; break;
    }
    int i = blockIdx.x * blockDim.x + threadIdx.x;
    if (i >= n4) return;
    float4 v = ((const float4*)x)[i];
    __half2 a, b;
    a.x = __float2half_rn(v.x); a.y = __float2half_rn(v.y);
    b.x = __float2half_rn(v.z); b.y = __float2half_rn(v.w);
    ((__half2*)hi)[2 * i] = a; ((__half2*)hi)[2 * i + 1] = b;
}

// ---------------------------------------------------------------------------
// QKV projection: A single fp16 x W single fp16, 1-term HMMA.
// CTA 128x128, BK=32, 256 threads, double-buffered cp.async.
// ---------------------------------------------------------------------------
#define TPAD 40
#define QTIL 10240
#define QSTG 20480          // A, B

__global__ __launch_bounds__(256, 2) void qkv_hmma(
    const __half* __restrict__ hid, const __half* __restrict__ ctx,
    const __half* __restrict__ w,
    const float* __restrict__ bq, const float* __restrict__ bk, const float* __restrict__ bv,
    const float* __restrict__ pos,
    __half* __restrict__ qh, __half* __restrict__ kh, __half* __restrict__ vh)
{
    extern __shared__ char smc[];
    const uint32_t sb = smem_u32(smc);

    const int z = blockIdx.z;
    const __half* A = (z == 0) ? hid : ctx;
    const __half* B = w + (size_t)z * HH * HH;
    const float* bias = (z == 0) ? bq : ((z == 1) ? bk : bv);
    __half* outp = (z == 0) ? qh : ((z == 1) ? kh : vh);

    const int t    = threadIdx.x;
    const int lane = t & 31;
    const int wid  = t >> 5;
    const int wm   = wid & 3;
    const int wn   = wid >> 2;
    const int g    = lane >> 2;
    const int tig  = lane & 3;
    const int m0   = blockIdx.y << 7;
    const int n0   = blockIdx.x << 7;

    const uint32_t a_off = ((wm * 32 + (lane & 15)) * TPAD + ((lane >> 4) << 3)) * 2;
    const uint32_t b_off = ((wn * 64 + (lane & 7) + ((lane & 16) ? 8 : 0)) * TPAD
                            + (((lane >> 3) & 1) << 3)) * 2;

    const int row0 = t >> 2,         cc0 = (t & 3) << 3;
    const int row1 = (t + 256) >> 2, cc1 = ((t + 256) & 3) << 3;
    const uint32_t so0 = row0 * 80 + cc0 * 2;
    const uint32_t so1 = row1 * 80 + cc1 * 2;

    float acc[2][8][4];
#pragma unroll
    for (int i = 0; i < 2; i++)
#pragma unroll
        for (int j = 0; j < 8; j++)
#pragma unroll
            for (int c = 0; c < 4; c++) acc[i][j][c] = 0.0f;

    auto issue = [&](int kt, int stg) {
        const int k0 = kt << 5;
        const uint32_t base = sb + stg * QSTG;
        size_t ga0 = (size_t)(m0 + row0) * HH + k0 + cc0;
        size_t ga1 = (size_t)(m0 + row1) * HH + k0 + cc1;
        size_t gb0 = (size_t)(n0 + row0) * HH + k0 + cc0;
        size_t gb1 = (size_t)(n0 + row1) * HH + k0 + cc1;
        cpa16(base + so0,        A + ga0);
        cpa16(base + so1,        A + ga1);
        cpa16(base + QTIL + so0, B + gb0);
        cpa16(base + QTIL + so1, B + gb1);
    };

    issue(0, 0);
    CPA_COMMIT();

    const int NT = HH / 32;   // 24
    for (int kt = 0; kt < NT; kt++) {
        if (kt + 1 < NT) {
            issue(kt + 1, (kt + 1) & 1);
            CPA_COMMIT();
            CPA_WAIT(1);
        } else {
            CPA_WAIT(0);
        }
        __syncthreads();

        const uint32_t stga = sb + (kt & 1) * QSTG;
        const uint32_t pA = stga + a_off;
        const uint32_t pB = stga + QTIL + b_off;

#pragma unroll
        for (int kk = 0; kk < 2; kk++) {
            const uint32_t kb = kk * 32;
            uint32_t bfr[8][2];
#pragma unroll
            for (int np = 0; np < 4; np++) {
                uint32_t r[4];
                ldmx4(r, pB + np * (16 * TPAD * 2) + kb);
                bfr[2 * np][0] = r[0];     bfr[2 * np][1] = r[1];
                bfr[2 * np + 1][0] = r[2]; bfr[2 * np + 1][1] = r[3];
            }
            uint32_t af[2][4];
            ldmx4(af[0], pA + kb);
            ldmx4(af[1], pA + 16 * TPAD * 2 + kb);
#pragma unroll
            for (int mt = 0; mt < 2; mt++)
#pragma unroll
                for (int nt = 0; nt < 8; nt++)
                    mma16816(acc[mt][nt], af[mt], bfr[nt]);
        }
        __syncthreads();
    }

    // epilogue: +bias (+pos for K), single fp16 store
#pragma unroll
    for (int mt = 0; mt < 2; mt++) {
#pragma unroll
        for (int nt = 0; nt < 8; nt++) {
            int m = m0 + wm * 32 + mt * 16 + g;
            int n = n0 + wn * 64 + nt * 8 + 2 * tig;
            float b0 = bias[n], b1 = bias[n + 1];
#pragma unroll
            for (int half = 0; half < 2; half++) {
                int mm = m + half * 8;
                float f0 = acc[mt][nt][2 * half]     + b0;
                float f1 = acc[mt][nt][2 * half + 1] + b1;
                if (z == 1) {
                    f0 += pos[(mm & (SKL - 1)) * DHD + (n & (DHD - 1))];
                    f1 += pos[(mm & (SKL - 1)) * DHD + ((n + 1) & (DHD - 1))];
                }
                *(uint32_t*)(outp + (size_t)mm * HH + n) = pack_hf2(f0, f1);
            }
        }
    }
}

// ---------------------------------------------------------------------------
// P2 = (pos @ pos^T) * C2  — 64x64 tiles, 64 CTAs
// ---------------------------------------------------------------------------
__global__ __launch_bounds__(128) void pos_gemm(
    const float* __restrict__ A, float* __restrict__ out)
{
    __shared__ float As[64][68];
    __shared__ float Bs[64][68];

    const int t  = threadIdx.x;
    const int m0 = blockIdx.y << 6;
    const int n0 = blockIdx.x << 6;
    const int tm = (t >> 3) << 2;
    const int tn = (t & 7) << 3;

#pragma unroll
    for (int i = 0; i < 8; i++) {
        int idx = t + (i << 7);
        int row = idx >> 4;
        int c4  = (idx & 15) << 2;
        float4 va = *(const float4*)(A + (size_t)(m0 + row) * DHD + c4);
        As[c4 + 0][row] = va.x; As[c4 + 1][row] = va.y;
        As[c4 + 2][row] = va.z; As[c4 + 3][row] = va.w;
        float4 vb = *(const float4*)(A + (size_t)(n0 + row) * DHD + c4);
        Bs[c4 + 0][row] = vb.x; Bs[c4 + 1][row] = vb.y;
        Bs[c4 + 2][row] = vb.z; Bs[c4 + 3][row] = vb.w;
    }
    __syncthreads();

    float acc[4][8];
#pragma unroll
    for (int i = 0; i < 4; i++)
#pragma unroll
        for (int j = 0; j < 8; j++) acc[i][j] = 0.0f;

#pragma unroll 8
    for (int kk = 0; kk < 64; kk++) {
        float a[4], b[8];
        *(float4*)a = *(const float4*)&As[kk][tm];
        *(float4*)(b + 0) = *(const float4*)&Bs[kk][tn];
        *(float4*)(b + 4) = *(const float4*)&Bs[kk][tn + 4];
#pragma unroll
        for (int i = 0; i < 4; i++)
#pragma unroll
            for (int j = 0; j < 8; j++)
                acc[i][j] += a[i] * b[j];
    }

#pragma unroll
    for (int i = 0; i < 4; i++)
#pragma unroll
        for (int j = 0; j < 8; j++)
            out[(size_t)(m0 + tm + i) * SKL + n0 + tn + j] = acc[i][j] * C2;
}

// ---------------------------------------------------------------------------
// Flash attention: pure 1-term fp16 (unchanged from round 8).
// ---------------------------------------------------------------------------
#define FP   72
#define OKV  18432
#define KSTG 18432
#define KTIL 9216
#define OMB  (OKV + 2 * KSTG)   // 55296
#define FSM  (OMB + 2048)       // 57344

__global__ __launch_bounds__(256, 2) void flash_hmma(
    const __half* __restrict__ qh,
    const __half* __restrict__ kh, const __half* __restrict__ vh,
    const float* __restrict__ P2, const int* __restrict__ mask,
    float* __restrict__ out)
{
    extern __shared__ char smc[];
    __half* sQh = (__half*)(smc);
    float*  smb = (float*)(smc + OMB);
    const uint32_t sb = smem_u32(smc);

    const int t    = threadIdx.x;
    const int lane = t & 31;
    const int w    = t >> 5;
    const int g    = lane >> 2;
    const int tig  = lane & 3;
    const int wr   = w << 4;
    const int b    = blockIdx.z;
    const int h    = blockIdx.y;
    const int q0   = blockIdx.x << 7;

    const uint32_t q_off = ((wr + (lane & 15)) * FP + ((lane >> 4) << 3)) * 2;
    const uint32_t k_off = (((lane & 7) + ((lane & 16) ? 8 : 0)) * FP
                            + (((lane >> 3) & 1) << 3)) * 2;
    const uint32_t v_off = ((lane & 15) * FP + ((lane >> 4) << 3)) * 2;

    const int krow0 = t >> 3,         kc0 = (t & 7) << 3;
    const int krow1 = (t + 256) >> 3, kc1 = ((t + 256) & 7) << 3;
    const uint32_t ko0 = krow0 * 144 + kc0 * 2;
    const uint32_t ko1 = krow1 * 144 + kc1 * 2;

    auto issue_kv = [&](int kt, int stg) {
        const uint32_t base = sb + OKV + stg * KSTG;
        size_t g0 = (size_t)(b * SKL + kt * 64 + krow0) * HH + h * DHD + kc0;
        size_t g1 = (size_t)(b * SKL + kt * 64 + krow1) * HH + h * DHD + kc1;
        cpa16(base + ko0,        kh + g0);
        cpa16(base + ko1,        kh + g1);
        cpa16(base + KTIL + ko0, vh + g0);
        cpa16(base + KTIL + ko1, vh + g1);
    };

    issue_kv(0, 0);
    CPA_COMMIT();

#pragma unroll
    for (int i = 0; i < 2; i++) {
        int idx = t + (i << 8);
        int row = idx >> 2;
        int c   = (idx & 3) << 4;
        size_t gsrc = (size_t)(b * SQL + q0 + row) * HH + h * DHD + c;
        *(uint4*)(sQh + row * FP + c)     = *(const uint4*)(qh + gsrc);
        *(uint4*)(sQh + row * FP + c + 8) = *(const uint4*)(qh + gsrc + 8);
    }
    {
        int i0 = t, i1 = t + 256;
        smb[i0] = (mask[b * SKL + i0] == 0) ? -1e30f : 0.0f;
        smb[i1] = (mask[b * SKL + i1] == 0) ? -1e30f : 0.0f;
    }

    float o[8][4];
#pragma unroll
    for (int i = 0; i < 8; i++)
#pragma unroll
        for (int c = 0; c < 4; c++) o[i][c] = 0.0f;
    float m0r = -1e30f, m1r = -1e30f, l0r = 0.0f, l1r = 0.0f;

    const int NT = SKL / 64;   // 8
    for (int kt = 0; kt < NT; kt++) {
        if (kt + 1 < NT) {
            issue_kv(kt + 1, (kt + 1) & 1);
            CPA_COMMIT();
            CPA_WAIT(1);
        } else {
            CPA_WAIT(0);
        }
        __syncthreads();

        const int stg = kt & 1;
        const uint32_t kvb = sb + OKV + stg * KSTG;
        const uint32_t pK = kvb + k_off;
        const uint32_t pV = kvb + KTIL + v_off;

        // ---- S = Q K'^T ----
        float s[8][4];
#pragma unroll
        for (int nt = 0; nt < 8; nt++)
#pragma unroll
            for (int c = 0; c < 4; c++) s[nt][c] = 0.0f;

#pragma unroll
        for (int kk = 0; kk < 4; kk++) {
            const uint32_t kb = kk * 32;
            uint32_t ah[4];
            ldmx4(ah, sb + q_off + kb);
#pragma unroll
            for (int np = 0; np < 4; np++) {
                uint32_t bh4[4];
                ldmx4(bh4, pK + np * (16 * FP * 2) + kb);
                mma16816(s[2 * np],     ah, bh4 + 0);
                mma16816(s[2 * np + 1], ah, bh4 + 2);
            }
        }

        // ---- bias + mask + online softmax ----
        const float* pg0 = P2 + (size_t)(q0 + wr + g) * SKL + kt * 64;
        const float* pg1 = pg0 + 8 * SKL;
        const float* mrow = smb + kt * 64;
        float vm0 = -1e30f, vm1 = -1e30f;
#pragma unroll
        for (int nt = 0; nt < 8; nt++) {
            int cc = nt * 8 + 2 * tig;
            float2 p0 = *(const float2*)(pg0 + cc);
            float2 p1 = *(const float2*)(pg1 + cc);
            float mb0 = mrow[cc], mb1 = mrow[cc + 1];
            s[nt][0] = fmaf(s[nt][0], C2, p0.x) + mb0;
            s[nt][1] = fmaf(s[nt][1], C2, p0.y) + mb1;
            s[nt][2] = fmaf(s[nt][2], C2, p1.x) + mb0;
            s[nt][3] = fmaf(s[nt][3], C2, p1.y) + mb1;
            vm0 = fmaxf(vm0, fmaxf(s[nt][0], s[nt][1]));
            vm1 = fmaxf(vm1, fmaxf(s[nt][2], s[nt][3]));
        }
        vm0 = fmaxf(vm0, __shfl_xor_sync(0xffffffffu, vm0, 1));
        vm0 = fmaxf(vm0, __shfl_xor_sync(0xffffffffu, vm0, 2));
        vm1 = fmaxf(vm1, __shfl_xor_sync(0xffffffffu, vm1, 1));
        vm1 = fmaxf(vm1, __shfl_xor_sync(0xffffffffu, vm1, 2));
        float mn0 = fmaxf(m0r, vm0), mn1 = fmaxf(m1r, vm1);
        float cr0 = ex2f(m0r - mn0), cr1 = ex2f(m1r - mn1);
        m0r = mn0; m1r = mn1;

        float rs0 = 0.0f, rs1 = 0.0f;
#pragma unroll
        for (int nt = 0; nt < 8; nt++) {
            s[nt][0] = ex2f(s[nt][0] - mn0); rs0 += s[nt][0];
            s[nt][1] = ex2f(s[nt][1] - mn0); rs0 += s[nt][1];
            s[nt][2] = ex2f(s[nt][2] - mn1); rs1 += s[nt][2];
            s[nt][3] = ex2f(s[nt][3] - mn1); rs1 += s[nt][3];
        }
        rs0 += __shfl_xor_sync(0xffffffffu, rs0, 1);
        rs0 += __shfl_xor_sync(0xffffffffu, rs0, 2);
        rs1 += __shfl_xor_sync(0xffffffffu, rs1, 1);
        rs1 += __shfl_xor_sync(0xffffffffu, rs1, 2);
        l0r = l0r * cr0 + rs0;
        l1r = l1r * cr1 + rs1;
#pragma unroll
        for (int nt = 0; nt < 8; nt++) {
            o[nt][0] *= cr0; o[nt][1] *= cr0;
            o[nt][2] *= cr1; o[nt][3] *= cr1;
        }

        // ---- O += P @ V ----
#pragma unroll
        for (int j = 0; j < 4; j++) {
            const int na = 2 * j, nb = 2 * j + 1;
            uint32_t aph[4];
            aph[0] = pack_hf2(s[na][0], s[na][1]);
            aph[1] = pack_hf2(s[na][2], s[na][3]);
            aph[2] = pack_hf2(s[nb][0], s[nb][1]);
            aph[3] = pack_hf2(s[nb][2], s[nb][3]);
            const uint32_t jv = pV + j * (16 * FP * 2);
#pragma unroll
            for (int vp = 0; vp < 4; vp++) {
                uint32_t bv4[4];
                ldmx4t(bv4, jv + vp * 32);
                mma16816(o[2 * vp],     aph, bv4 + 0);
                mma16816(o[2 * vp + 1], aph, bv4 + 2);
            }
        }
        __syncthreads();
    }

    float inv0 = 1.0f / l0r, inv1 = 1.0f / l1r;
    float* or0 = out + (size_t)(b * SQL + q0 + wr + g) * HH + h * DHD;
    float* or1 = or0 + 8 * HH;
#pragma unroll
    for (int ntv = 0; ntv < 8; ntv++) {
        int cc = ntv * 8 + 2 * tig;
        float2 w0 = make_float2(o[ntv][0] * inv0, o[ntv][1] * inv0);
        float2 w1 = make_float2(o[ntv][2] * inv1, o[ntv][3] * inv1);
        *(float2*)(or0 + cc) = w0;
        *(float2*)(or1 + cc) = w1;
    }
}

// ---------------------------------------------------------------------------
extern "C" void kernel_launch(void* const* d_in, const int* in_sizes, int n_in,
                              void* d_out, int out_size)
{
    const float* hidden  = (const float*)d_in[0];
    const float* context = (const float*)d_in[1];
    const int*   mask    = (const int*)d_in[2];
    const float* Wq      = (const float*)d_in[3];
    const float* bq      = (const float*)d_in[4];
    const float* Wk      = (const float*)d_in[5];
    const float* bk      = (const float*)d_in[6];
    const float* Wv      = (const float*)d_in[7];
    const float* bv      = (const float*)d_in[8];
    const float* pos     = (const float*)d_in[9];
    float* out = (float*)d_out;

    float* P2;
    cudaGetSymbolAddress((void**)&P2, g_P2);
    __half *qh, *kh, *vh, *hh, *ch, *w;
    cudaGetSymbolAddress((void**)&qh, g_qh);
    cudaGetSymbolAddress((void**)&kh, g_kh);
    cudaGetSymbolAddress((void**)&vh, g_vh);
    cudaGetSymbolAddress((void**)&hh, g_hid);
    cudaGetSymbolAddress((void**)&ch, g_ctx);
    cudaGetSymbolAddress((void**)&w,  g_w);

    const int nA4 = MROWS * HH / 4;
    dim3 gcvt((nA4 + 255) / 256, 5);
    cvt_all<<<gcvt, 256>>>(hidden, context, Wq, Wk, Wv, hh, ch, w);

    cudaFuncSetAttribute(qkv_hmma, cudaFuncAttributeMaxDynamicSharedMemorySize, 2 * QSTG);
    dim3 gproj(HH / 128, MROWS / 128, 3);
    qkv_hmma<<<gproj, 256, 2 * QSTG>>>(hh, ch, w, bq, bk, bv, pos, qh, kh, vh);

    dim3 gpos(SKL / 64, SQL / 64);
    pos_gemm<<<gpos, 128>>>(pos, P2);

    cudaFuncSetAttribute(flash_hmma, cudaFuncAttributeMaxDynamicSharedMemorySize, FSM);
    dim3 gattn(SQL / 128, NHD, BB);
    flash_hmma<<<gattn, 256, FSM>>>(qh, kh, vh, P2, mask, out);
}

// round 10
// speedup vs baseline: 7.8137x; 1.0749x over previous
#include <cuda_runtime.h>
#include <cuda_fp16.h>
#include <cstdint>

#define BB  8
#define SQL 512
#define SKL 512
#define HH  768
#define NHD 12
#define DHD 64
#define MROWS (BB * SQL)   // 4096

#define C2 0.1803368801111244f   // 0.125 * log2(e)

// ---------------- scratch ----------------
__device__ float g_P2[SQL * SKL];
__device__ __half g_qh[MROWS * HH];
__device__ __half g_kh[MROWS * HH];
__device__ __half g_vh[MROWS * HH];
__device__ __half g_hid[MROWS * HH];
__device__ __half g_ctx[MROWS * HH];
__device__ __half g_w[3 * HH * HH];

// ---------------- helpers ----------------
__device__ __forceinline__ float ex2f(float x) {
    float y;
    asm("ex2.approx.ftz.f32 %0, %1;" : "=f"(y) : "f"(x));
    return y;
}
__device__ __forceinline__ uint32_t smem_u32(const void* p) {
    uint32_t a;
    asm("{ .reg .u64 t; cvta.to.shared.u64 t, %1; cvt.u32.u64 %0, t; }" : "=r"(a) : "l"(p));
    return a;
}
__device__ __forceinline__ void cpa16(uint32_t dst, const void* src) {
    asm volatile("cp.async.cg.shared.global [%0], [%1], 16;" :: "r"(dst), "l"(src));
}
#define CPA_COMMIT() asm volatile("cp.async.commit_group;" ::: "memory")
#define CPA_WAIT(n)  asm volatile("cp.async.wait_group %0;" :: "n"(n) : "memory")

__device__ __forceinline__ void mma16816(float* d, const uint32_t* a, const uint32_t* b)
{
    asm volatile(
        "mma.sync.aligned.m16n8k16.row.col.f32.f16.f16.f32 "
        "{%0,%1,%2,%3}, {%4,%5,%6,%7}, {%8,%9}, {%0,%1,%2,%3};"
        : "+f"(d[0]), "+f"(d[1]), "+f"(d[2]), "+f"(d[3])
        : "r"(a[0]), "r"(a[1]), "r"(a[2]), "r"(a[3]), "r"(b[0]), "r"(b[1]));
}
__device__ __forceinline__ void ldmx4(uint32_t* r, uint32_t addr)
{
    asm volatile("ldmatrix.sync.aligned.m8n8.x4.shared.b16 {%0,%1,%2,%3}, [%4];"
                 : "=r"(r[0]), "=r"(r[1]), "=r"(r[2]), "=r"(r[3]) : "r"(addr));
}
__device__ __forceinline__ void ldmx4t(uint32_t* r, uint32_t addr)
{
    asm volatile("ldmatrix.sync.aligned.m8n8.x4.trans.shared.b16 {%0,%1,%2,%3}, [%4];"
                 : "=r"(r[0]), "=r"(r[1]), "=r"(r[2]), "=r"(r[3]) : "r"(addr));
}
__device__ __forceinline__ uint32_t pack_hf2(float a, float b) {
    __half2 h = __floats2half2_rn(a, b);
    return *(uint32_t*)&h;
}

// ---------------------------------------------------------------------------
// fp32 -> fp16 conversion, 5 arrays fused.
// ---------------------------------------------------------------------------
__global__ void cvt_all(
    const float* __restrict__ hidden, const float* __restrict__ context,
    const float* __restrict__ Wq, const float* __restrict__ Wk, const float* __restrict__ Wv,
    __half* __restrict__ hh, __half* __restrict__ ch, __half* __restrict__ w)
{
    const int y = blockIdx.y;
    const float* x;
    __half* hi;
    int n4;
    const int nA4 = MROWS * HH / 4, nW4 = HH * HH / 4;
    switch (y) {
        case 0: x = hidden;  hi = hh;              n4 = nA4; break;
        case 1: x = context; hi = ch;              n4 = nA4; break;
        case 2: x = Wq;      hi = w;               n4 = nW4; break;
        case 3: x = Wk;      hi = w + HH * HH;     n4 = nW4; break;
        default:x = Wv;      hi = w + 2 * HH * HH; n4 = nW4; break;
    }
    int i = blockIdx.x * blockDim.x + threadIdx.x;
    if (i >= n4) return;
    float4 v = ((const float4*)x)[i];
    __half2 a, b;
    a.x = __float2half_rn(v.x); a.y = __float2half_rn(v.y);
    b.x = __float2half_rn(v.z); b.y = __float2half_rn(v.w);
    ((__half2*)hi)[2 * i] = a; ((__half2*)hi)[2 * i + 1] = b;
}

// ---------------------------------------------------------------------------
// QKV projection: 1-term fp16 HMMA, BK=64 (12 fat iterations), double-buffered.
// CTA 128x128, 256 threads.
// ---------------------------------------------------------------------------
#define QPAD 72
#define QTIL 18432          // 128 x 72 halves
#define QSTG 36864          // A + B

__global__ __launch_bounds__(256, 2) void qkv_hmma(
    const __half* __restrict__ hid, const __half* __restrict__ ctx,
    const __half* __restrict__ w,
    const float* __restrict__ bq, const float* __restrict__ bk, const float* __restrict__ bv,
    const float* __restrict__ pos,
    __half* __restrict__ qh, __half* __restrict__ kh, __half* __restrict__ vh)
{
    extern __shared__ char smc[];
    const uint32_t sb = smem_u32(smc);

    const int z = blockIdx.z;
    const __half* A = (z == 0) ? hid : ctx;
    const __half* B = w + (size_t)z * HH * HH;
    const float* bias = (z == 0) ? bq : ((z == 1) ? bk : bv);
    __half* outp = (z == 0) ? qh : ((z == 1) ? kh : vh);

    const int t    = threadIdx.x;
    const int lane = t & 31;
    const int wid  = t >> 5;
    const int wm   = wid & 3;
    const int wn   = wid >> 2;
    const int g    = lane >> 2;
    const int tig  = lane & 3;
    const int m0   = blockIdx.y << 7;
    const int n0   = blockIdx.x << 7;

    const uint32_t a_off = ((wm * 32 + (lane & 15)) * QPAD + ((lane >> 4) << 3)) * 2;
    const uint32_t b_off = ((wn * 64 + (lane & 7) + ((lane & 16) ? 8 : 0)) * QPAD
                            + (((lane >> 3) & 1) << 3)) * 2;

    float acc[2][8][4];
#pragma unroll
    for (int i = 0; i < 2; i++)
#pragma unroll
        for (int j = 0; j < 8; j++)
#pragma unroll
            for (int c = 0; c < 4; c++) acc[i][j][c] = 0.0f;

    // cp.async: per tile 128 rows x 64 halves = 1024 uint4; 4 per thread per tile
    auto issue = [&](int kt, int stg) {
        const int k0 = kt << 6;
        const uint32_t base = sb + stg * QSTG;
#pragma unroll
        for (int i = 0; i < 4; i++) {
            int idx = t + (i << 8);
            int row = idx >> 3;
            int c   = (idx & 7) << 3;
            uint32_t so = row * 144 + c * 2;
            cpa16(base + so,        A + (size_t)(m0 + row) * HH + k0 + c);
            cpa16(base + QTIL + so, B + (size_t)(n0 + row) * HH + k0 + c);
        }
    };

    issue(0, 0);
    CPA_COMMIT();

    const int NT = HH / 64;   // 12
    for (int kt = 0; kt < NT; kt++) {
        if (kt + 1 < NT) {
            issue(kt + 1, (kt + 1) & 1);
            CPA_COMMIT();
            CPA_WAIT(1);
        } else {
            CPA_WAIT(0);
        }
        __syncthreads();

        const uint32_t stga = sb + (kt & 1) * QSTG;
        const uint32_t pA = stga + a_off;
        const uint32_t pB = stga + QTIL + b_off;

#pragma unroll
        for (int kk = 0; kk < 4; kk++) {
            const uint32_t kb = kk * 32;
            uint32_t bfr[8][2];
#pragma unroll
            for (int np = 0; np < 4; np++) {
                uint32_t r[4];
                ldmx4(r, pB + np * (16 * QPAD * 2) + kb);
                bfr[2 * np][0] = r[0];     bfr[2 * np][1] = r[1];
                bfr[2 * np + 1][0] = r[2]; bfr[2 * np + 1][1] = r[3];
            }
            uint32_t af[2][4];
            ldmx4(af[0], pA + kb);
            ldmx4(af[1], pA + 16 * QPAD * 2 + kb);
#pragma unroll
            for (int mt = 0; mt < 2; mt++)
#pragma unroll
                for (int nt = 0; nt < 8; nt++)
                    mma16816(acc[mt][nt], af[mt], bfr[nt]);
        }
        __syncthreads();
    }

    // epilogue: +bias (+pos for K), single fp16 store
#pragma unroll
    for (int mt = 0; mt < 2; mt++) {
#pragma unroll
        for (int nt = 0; nt < 8; nt++) {
            int m = m0 + wm * 32 + mt * 16 + g;
            int n = n0 + wn * 64 + nt * 8 + 2 * tig;
            float b0 = bias[n], b1 = bias[n + 1];
#pragma unroll
            for (int half = 0; half < 2; half++) {
                int mm = m + half * 8;
                float f0 = acc[mt][nt][2 * half]     + b0;
                float f1 = acc[mt][nt][2 * half + 1] + b1;
                if (z == 1) {
                    f0 += pos[(mm & (SKL - 1)) * DHD + (n & (DHD - 1))];
                    f1 += pos[(mm & (SKL - 1)) * DHD + ((n + 1) & (DHD - 1))];
                }
                *(uint32_t*)(outp + (size_t)mm * HH + n) = pack_hf2(f0, f1);
            }
        }
    }
}

// ---------------------------------------------------------------------------
// P2 = (pos @ pos^T) * C2  — 64x64 tiles, 64 CTAs
// ---------------------------------------------------------------------------
__global__ __launch_bounds__(128) void pos_gemm(
    const float* __restrict__ A, float* __restrict__ out)
{
    __shared__ float As[64][68];
    __shared__ float Bs[64][68];

    const int t  = threadIdx.x;
    const int m0 = blockIdx.y << 6;
    const int n0 = blockIdx.x << 6;
    const int tm = (t >> 3) << 2;
    const int tn = (t & 7) << 3;

#pragma unroll
    for (int i = 0; i < 8; i++) {
        int idx = t + (i << 7);
        int row = idx >> 4;
        int c4  = (idx & 15) << 2;
        float4 va = *(const float4*)(A + (size_t)(m0 + row) * DHD + c4);
        As[c4 + 0][row] = va.x; As[c4 + 1][row] = va.y;
        As[c4 + 2][row] = va.z; As[c4 + 3][row] = va.w;
        float4 vb = *(const float4*)(A + (size_t)(n0 + row) * DHD + c4);
        Bs[c4 + 0][row] = vb.x; Bs[c4 + 1][row] = vb.y;
        Bs[c4 + 2][row] = vb.z; Bs[c4 + 3][row] = vb.w;
    }
    __syncthreads();

    float acc[4][8];
#pragma unroll
    for (int i = 0; i < 4; i++)
#pragma unroll
        for (int j = 0; j < 8; j++) acc[i][j] = 0.0f;

#pragma unroll 8
    for (int kk = 0; kk < 64; kk++) {
        float a[4], b[8];
        *(float4*)a = *(const float4*)&As[kk][tm];
        *(float4*)(b + 0) = *(const float4*)&Bs[kk][tn];
        *(float4*)(b + 4) = *(const float4*)&Bs[kk][tn + 4];
#pragma unroll
        for (int i = 0; i < 4; i++)
#pragma unroll
            for (int j = 0; j < 8; j++)
                acc[i][j] += a[i] * b[j];
    }

#pragma unroll
    for (int i = 0; i < 4; i++)
#pragma unroll
        for (int j = 0; j < 8; j++)
            out[(size_t)(m0 + tm + i) * SKL + n0 + tn + j] = acc[i][j] * C2;
}

// ---------------------------------------------------------------------------
// Flash attention: 64 q-rows/CTA, 128 threads (4 warps x 16 rows), occ 4.
// Q fragments hoisted to registers. smem: Q 9216 | KV 2x18432 | mask 2048.
// ---------------------------------------------------------------------------
#define FP   72
#define OKV  9216
#define KSTG 18432
#define KTIL 9216
#define OMB  (OKV + 2 * KSTG)   // 46080
#define FSM  (OMB + 2048)       // 48128

__global__ __launch_bounds__(128, 4) void flash_hmma(
    const __half* __restrict__ qh,
    const __half* __restrict__ kh, const __half* __restrict__ vh,
    const float* __restrict__ P2, const int* __restrict__ mask,
    float* __restrict__ out)
{
    extern __shared__ char smc[];
    __half* sQh = (__half*)(smc);
    float*  smb = (float*)(smc + OMB);
    const uint32_t sb = smem_u32(smc);

    const int t    = threadIdx.x;
    const int lane = t & 31;
    const int w    = t >> 5;          // 0..3
    const int g    = lane >> 2;
    const int tig  = lane & 3;
    const int wr   = w << 4;          // warp's 16-row strip within 64
    const int b    = blockIdx.z;
    const int h    = blockIdx.y;
    const int q0   = blockIdx.x << 6; // 64-row q tile

    const uint32_t q_off = ((wr + (lane & 15)) * FP + ((lane >> 4) << 3)) * 2;
    const uint32_t k_off = (((lane & 7) + ((lane & 16) ? 8 : 0)) * FP
                            + (((lane >> 3) & 1) << 3)) * 2;
    const uint32_t v_off = ((lane & 15) * FP + ((lane >> 4) << 3)) * 2;

    // cp.async KV: per tile 64 rows x 64 halves = 512 uint4; 4/thread/tile
    auto issue_kv = [&](int kt, int stg) {
        const uint32_t base = sb + OKV + stg * KSTG;
#pragma unroll
        for (int i = 0; i < 4; i++) {
            int idx = t + (i << 7);
            int row = idx >> 3;
            int c   = (idx & 7) << 3;
            uint32_t so = row * 144 + c * 2;
            size_t gg = (size_t)(b * SKL + kt * 64 + row) * HH + h * DHD + c;
            cpa16(base + so,        kh + gg);
            cpa16(base + KTIL + so, vh + gg);
        }
    };

    issue_kv(0, 0);
    CPA_COMMIT();

    // Q tile (64 x 64) + mask row (512 floats)
#pragma unroll
    for (int i = 0; i < 4; i++) {
        int idx = t + (i << 7);
        int row = idx >> 3;
        int c   = (idx & 7) << 3;
        size_t gsrc = (size_t)(b * SQL + q0 + row) * HH + h * DHD + c;
        *(uint4*)(sQh + row * FP + c) = *(const uint4*)(qh + gsrc);
    }
#pragma unroll
    for (int i = 0; i < 4; i++) {
        int idx = t + (i << 7);
        smb[idx] = (mask[b * SKL + idx] == 0) ? -1e30f : 0.0f;
    }
    __syncthreads();

    // hoist Q fragments (constant across k-tiles)
    uint32_t qfr[4][4];
#pragma unroll
    for (int kk = 0; kk < 4; kk++)
        ldmx4(qfr[kk], sb + q_off + kk * 32);

    float o[8][4];
#pragma unroll
    for (int i = 0; i < 8; i++)
#pragma unroll
        for (int c = 0; c < 4; c++) o[i][c] = 0.0f;
    float m0r = -1e30f, m1r = -1e30f, l0r = 0.0f, l1r = 0.0f;

    const int NT = SKL / 64;   // 8
    for (int kt = 0; kt < NT; kt++) {
        if (kt + 1 < NT) {
            issue_kv(kt + 1, (kt + 1) & 1);
            CPA_COMMIT();
            CPA_WAIT(1);
        } else {
            CPA_WAIT(0);
        }
        __syncthreads();

        const int stg = kt & 1;
        const uint32_t kvb = sb + OKV + stg * KSTG;
        const uint32_t pK = kvb + k_off;
        const uint32_t pV = kvb + KTIL + v_off;

        // ---- S = Q K'^T ----
        float s[8][4];
#pragma unroll
        for (int nt = 0; nt < 8; nt++)
#pragma unroll
            for (int c = 0; c < 4; c++) s[nt][c] = 0.0f;

#pragma unroll
        for (int kk = 0; kk < 4; kk++) {
            const uint32_t kb = kk * 32;
#pragma unroll
            for (int np = 0; np < 4; np++) {
                uint32_t bh4[4];
                ldmx4(bh4, pK + np * (16 * FP * 2) + kb);
                mma16816(s[2 * np],     qfr[kk], bh4 + 0);
                mma16816(s[2 * np + 1], qfr[kk], bh4 + 2);
            }
        }

        // ---- bias + mask + online softmax ----
        const float* pg0 = P2 + (size_t)(q0 + wr + g) * SKL + kt * 64;
        const float* pg1 = pg0 + 8 * SKL;
        const float* mrow = smb + kt * 64;
        float vm0 = -1e30f, vm1 = -1e30f;
#pragma unroll
        for (int nt = 0; nt < 8; nt++) {
            int cc = nt * 8 + 2 * tig;
            float2 p0 = *(const float2*)(pg0 + cc);
            float2 p1 = *(const float2*)(pg1 + cc);
            float mb0 = mrow[cc], mb1 = mrow[cc + 1];
            s[nt][0] = fmaf(s[nt][0], C2, p0.x) + mb0;
            s[nt][1] = fmaf(s[nt][1], C2, p0.y) + mb1;
            s[nt][2] = fmaf(s[nt][2], C2, p1.x) + mb0;
            s[nt][3] = fmaf(s[nt][3], C2, p1.y) + mb1;
            vm0 = fmaxf(vm0, fmaxf(s[nt][0], s[nt][1]));
            vm1 = fmaxf(vm1, fmaxf(s[nt][2], s[nt][3]));
        }
        vm0 = fmaxf(vm0, __shfl_xor_sync(0xffffffffu, vm0, 1));
        vm0 = fmaxf(vm0, __shfl_xor_sync(0xffffffffu, vm0, 2));
        vm1 = fmaxf(vm1, __shfl_xor_sync(0xffffffffu, vm1, 1));
        vm1 = fmaxf(vm1, __shfl_xor_sync(0xffffffffu, vm1, 2));
        float mn0 = fmaxf(m0r, vm0), mn1 = fmaxf(m1r, vm1);
        float cr0 = ex2f(m0r - mn0), cr1 = ex2f(m1r - mn1);
        m0r = mn0; m1r = mn1;

        float rs0 = 0.0f, rs1 = 0.0f;
#pragma unroll
        for (int nt = 0; nt < 8; nt++) {
            s[nt][0] = ex2f(s[nt][0] - mn0); rs0 += s[nt][0];
            s[nt][1] = ex2f(s[nt][1] - mn0); rs0 += s[nt][1];
            s[nt][2] = ex2f(s[nt][2] - mn1); rs1 += s[nt][2];
            s[nt][3] = ex2f(s[nt][3] - mn1); rs1 += s[nt][3];
        }
        rs0 += __shfl_xor_sync(0xffffffffu, rs0, 1);
        rs0 += __shfl_xor_sync(0xffffffffu, rs0, 2);
        rs1 += __shfl_xor_sync(0xffffffffu, rs1, 1);
        rs1 += __shfl_xor_sync(0xffffffffu, rs1, 2);
        l0r = l0r * cr0 + rs0;
        l1r = l1r * cr1 + rs1;
#pragma unroll
        for (int nt = 0; nt < 8; nt++) {
            o[nt][0] *= cr0; o[nt][1] *= cr0;
            o[nt][2] *= cr1; o[nt][3] *= cr1;
        }

        // ---- O += P @ V ----
#pragma unroll
        for (int j = 0; j < 4; j++) {
            const int na = 2 * j, nb = 2 * j + 1;
            uint32_t aph[4];
            aph[0] = pack_hf2(s[na][0], s[na][1]);
            aph[1] = pack_hf2(s[na][2], s[na][3]);
            aph[2] = pack_hf2(s[nb][0], s[nb][1]);
            aph[3] = pack_hf2(s[nb][2], s[nb][3]);
            const uint32_t jv = pV + j * (16 * FP * 2);
#pragma unroll
            for (int vp = 0; vp < 4; vp++) {
                uint32_t bv4[4];
                ldmx4t(bv4, jv + vp * 32);
                mma16816(o[2 * vp],     aph, bv4 + 0);
                mma16816(o[2 * vp + 1], aph, bv4 + 2);
            }
        }
        __syncthreads();
    }

    float inv0 = 1.0f / l0r, inv1 = 1.0f / l1r;
    float* or0 = out + (size_t)(b * SQL + q0 + wr + g) * HH + h * DHD;
    float* or1 = or0 + 8 * HH;
#pragma unroll
    for (int ntv = 0; ntv < 8; ntv++) {
        int cc = ntv * 8 + 2 * tig;
        float2 w0 = make_float2(o[ntv][0] * inv0, o[ntv][1] * inv0);
        float2 w1 = make_float2(o[ntv][2] * inv1, o[ntv][3] * inv1);
        *(float2*)(or0 + cc) = w0;
        *(float2*)(or1 + cc) = w1;
    }
}

// ---------------------------------------------------------------------------
extern "C" void kernel_launch(void* const* d_in, const int* in_sizes, int n_in,
                              void* d_out, int out_size)
{
    const float* hidden  = (const float*)d_in[0];
    const float* context = (const float*)d_in[1];
    const int*   mask    = (const int*)d_in[2];
    const float* Wq      = (const float*)d_in[3];
    const float* bq      = (const float*)d_in[4];
    const float* Wk      = (const float*)d_in[5];
    const float* bk      = (const float*)d_in[6];
    const float* Wv      = (const float*)d_in[7];
    const float* bv      = (const float*)d_in[8];
    const float* pos     = (const float*)d_in[9];
    float* out = (float*)d_out;

    float* P2;
    cudaGetSymbolAddress((void**)&P2, g_P2);
    __half *qh, *kh, *vh, *hh, *ch, *w;
    cudaGetSymbolAddress((void**)&qh, g_qh);
    cudaGetSymbolAddress((void**)&kh, g_kh);
    cudaGetSymbolAddress((void**)&vh, g_vh);
    cudaGetSymbolAddress((void**)&hh, g_hid);
    cudaGetSymbolAddress((void**)&ch, g_ctx);
    cudaGetSymbolAddress((void**)&w,  g_w);

    const int nA4 = MROWS * HH / 4;
    dim3 gcvt((nA4 + 255) / 256, 5);
    cvt_all<<<gcvt, 256>>>(hidden, context, Wq, Wk, Wv, hh, ch, w);

    cudaFuncSetAttribute(qkv_hmma, cudaFuncAttributeMaxDynamicSharedMemorySize, 2 * QSTG);
    dim3 gproj(HH / 128, MROWS / 128, 3);
    qkv_hmma<<<gproj, 256, 2 * QSTG>>>(hh, ch, w, bq, bk, bv, pos, qh, kh, vh);

    dim3 gpos(SKL / 64, SQL / 64);
    pos_gemm<<<gpos, 128>>>(pos, P2);

    cudaFuncSetAttribute(flash_hmma, cudaFuncAttributeMaxDynamicSharedMemorySize, FSM);
    dim3 gattn(SQL / 64, NHD, BB);   // (8, 12, 8) = 768 CTAs
    flash_hmma<<<gattn, 128, FSM>>>(qh, kh, vh, P2, mask, out);
}